// round 11
// baseline (speedup 1.0000x reference)
#include <cuda_runtime.h>
#include <cuda_bf16.h>
#include <cstdint>
#include <cstddef>

#define NB 64
typedef unsigned long long ull;
typedef unsigned int uint32;

__device__ __forceinline__ ull pack2(float x) {
    ull d; unsigned u = __float_as_uint(x);
    asm("mov.b64 %0, {%1, %1};" : "=l"(d) : "r"(u));
    return d;
}
__device__ __forceinline__ ull fma2(ull a, ull b, ull c) {
    ull d;
    asm("fma.rn.f32x2 %0, %1, %2, %3;" : "=l"(d) : "l"(a), "l"(b), "l"(c));
    return d;
}
__device__ __forceinline__ void unpack2(ull a, float& lo, float& hi) {
    unsigned l, h;
    asm("mov.b64 {%0, %1}, %2;" : "=r"(l), "=r"(h) : "l"(a));
    lo = __uint_as_float(l); hi = __uint_as_float(h);
}
__device__ __forceinline__ uint32 smem_u32(const void* p) {
    uint32 a;
    asm("{ .reg .u64 t; cvta.to.shared.u64 t, %1; cvt.u32.u64 %0, t; }" : "=r"(a) : "l"(p));
    return a;
}
__device__ __forceinline__ void ldm_x4(uint32& r0, uint32& r1, uint32& r2, uint32& r3, uint32 a) {
    asm volatile("ldmatrix.sync.aligned.m8n8.x4.shared.b16 {%0,%1,%2,%3}, [%4];"
                 : "=r"(r0), "=r"(r1), "=r"(r2), "=r"(r3) : "r"(a));
}
__device__ __forceinline__ void ldm_x2(uint32& r0, uint32& r1, uint32 a) {
    asm volatile("ldmatrix.sync.aligned.m8n8.x2.shared.b16 {%0,%1}, [%2];"
                 : "=r"(r0), "=r"(r1) : "r"(a));
}
__device__ __forceinline__ void mma16816(float* c, const uint32* a, const uint32* b) {
    asm volatile(
        "mma.sync.aligned.m16n8k16.row.col.f32.bf16.bf16.f32 "
        "{%0,%1,%2,%3}, {%4,%5,%6,%7}, {%8,%9}, {%0,%1,%2,%3};"
        : "+f"(c[0]), "+f"(c[1]), "+f"(c[2]), "+f"(c[3])
        : "r"(a[0]), "r"(a[1]), "r"(a[2]), "r"(a[3]), "r"(b[0]), "r"(b[1]));
}
__device__ __forceinline__ uint32 pkbf2(float a, float b) {
    return (uint32)__bfloat16_as_ushort(__float2bfloat16(a))
         | ((uint32)__bfloat16_as_ushort(__float2bfloat16(b)) << 16);
}
__device__ __forceinline__ float bfres(float v) {
    return v - __bfloat162float(__float2bfloat16(v));
}

__device__ float g_h1[(size_t)NB * 128 * 64 * 64];
__device__ float g_h2[(size_t)NB * 128 * 32 * 32];
__device__ float g_ze[(size_t)NB * 64 * 32 * 32];
__device__ float g_zq[(size_t)NB * 64 * 32 * 32];
__device__ float g_d1[(size_t)NB * 128 * 64 * 64];
__device__ float g_d2[(size_t)NB * 128 * 128 * 128];
__device__ float g_vq_part[256];
__device__ float g_rec_part[4096];
__device__ float g_w1t[16 * 3 * 128];
__device__ float g_w2t[16 * 128 * 128];
__device__ float g_w3t[9 * 128 * 64];
__device__ float g_w3dt[128 * 9 * 3];
__device__ __align__(16) __nv_bfloat16 g_bw1[4 * 2 * 128 * 256];  // [cl][h][co][K]
__device__ __align__(16) __nv_bfloat16 g_bw2[4 * 2 * 128 * 512];  // [cl][h][co][K]

__global__ void wprep_k(const float* __restrict__ w1, const float* __restrict__ w2,
                        const float* __restrict__ w3, const float* __restrict__ dw1,
                        const float* __restrict__ dw2, const float* __restrict__ dw3)
{
    int st = gridDim.x * blockDim.x, g = blockIdx.x * blockDim.x + threadIdx.x;
    for (int t = g; t < 16 * 3 * 128; t += st) {
        int co = t & 127, r = t >> 7, ci = r % 3, kk = r / 3;
        g_w1t[(kk * 3 + ci) * 128 + co] = w1[((size_t)co * 3 + ci) * 16 + kk];
    }
    for (int t = g; t < 16 * 128 * 128; t += st) {
        int co = t & 127, r = t >> 7, ci = r & 127, kk = r >> 7;
        g_w2t[(kk * 128 + ci) * 128 + co] = w2[((size_t)co * 128 + ci) * 16 + kk];
    }
    for (int t = g; t < 9 * 128 * 64; t += st) {
        int co = t & 63, r = t >> 6, ci = r & 127, kk = r >> 7;
        g_w3t[(kk * 128 + ci) * 64 + co] = w3[((size_t)co * 128 + ci) * 9 + kk];
    }
    for (int t = g; t < 128 * 9 * 3; t += st) {
        int co = t % 3, r = t / 3, kk = r % 9, ci = r / 9;
        g_w3dt[t] = dw3[((size_t)co * 128 + ci) * 9 + kk];
    }
    for (int t = g; t < 4 * 2 * 128 * 256; t += st) {
        int k = t & 255, r2 = t >> 8, co = r2 & 127, h = (r2 >> 7) & 1, cl = r2 >> 8;
        int ci = k >> 2, rr = (k >> 1) & 1, cc = k & 1;
        int dh = cl >> 1, dw = cl & 1;
        float w = dw1[((size_t)ci * 128 + co) * 16 + (1 - dh + 2 * rr) * 4 + (1 - dw + 2 * cc)];
        g_bw1[t] = __float2bfloat16(h ? bfres(w) : w);
    }
    for (int t = g; t < 4 * 2 * 128 * 512; t += st) {
        int k = t & 511, r2 = t >> 9, co = r2 & 127, h = (r2 >> 7) & 1, cl = r2 >> 8;
        int ci = k >> 2, rr = (k >> 1) & 1, cc = k & 1;
        int dh = cl >> 1, dw = cl & 1;
        float w = dw2[((size_t)ci * 128 + co) * 16 + (1 - dh + 2 * rr) * 4 + (1 - dw + 2 * cc)];
        g_bw2[t] = __float2bfloat16(h ? bfres(w) : w);
    }
}

// enc1 (bit-exact scalar chain; weights fully resident, single sync).
template <int K, int S, int CIN, int COUT, int H, bool RELU>
__global__ void __launch_bounds__(512) conv_seq(const float* __restrict__ in,
                                                const float* __restrict__ wt,
                                                const float* __restrict__ bias,
                                                float* __restrict__ out)
{
    constexpr int W = H, OH = (H + 2 - K) / S + 1, OW = OH;
    constexpr int IHS = 7 * S + K, IWS = 7 * S + K, IWP = IWS + 1;
    constexpr int SW_OFF = ((CIN * IHS * IWP + 3) / 4) * 4;
    constexpr int WN = K * K * CIN * 64;
    extern __shared__ float sm[];
    float* s_in = sm;
    float* s_w  = sm + SW_OFF;
    const int n = blockIdx.z, co0 = blockIdx.y * 64;
    constexpr int TWn = OW / 8;
    const int oh0 = (blockIdx.x / TWn) * 8, ow0 = (blockIdx.x % TWn) * 8;
    const int tid = threadIdx.x, px = tid & 63, cog = tid >> 6;
    const int ohr = px >> 3, owr = px & 7;
    const int ihb = oh0 * S - 1, iwb = ow0 * S - 1;

    for (int t = tid; t < CIN * IHS * IWS; t += 512) {
        int ci = t / (IHS * IWS), r = t % (IHS * IWS), rr = r / IWS, cc = r % IWS;
        int ih = ihb + rr, iw = iwb + cc;
        float v = 0.f;
        if (ih >= 0 && ih < H && iw >= 0 && iw < W)
            v = in[(((size_t)n * CIN + ci) * H + ih) * W + iw];
        s_in[(ci * IHS + rr) * IWP + cc] = v;
    }
    for (int t = tid; t < WN; t += 512)
        s_w[t] = wt[(size_t)(t >> 6) * COUT + co0 + (t & 63)];
    __syncthreads();

    const int cob = co0 + cog * 8;
    float a[8];
    #pragma unroll
    for (int i = 0; i < 8; i++) a[i] = 0.f;
    #pragma unroll
    for (int kh = 0; kh < K; kh++)
    #pragma unroll
    for (int kw = 0; kw < K; kw++) {
        const float* ip = &s_in[(ohr * S + kh) * IWP + owr * S + kw];
        const float* wp = &s_w[((kh * K + kw) * CIN) * 64 + cog * 8];
        #pragma unroll 3
        for (int ci = 0; ci < CIN; ci++) {
            float iv = ip[ci * IHS * IWP];
            float4 w0 = *(const float4*)&wp[ci * 64];
            float4 w1 = *(const float4*)&wp[ci * 64 + 4];
            a[0] = __fmaf_rn(iv, w0.x, a[0]);
            a[1] = __fmaf_rn(iv, w0.y, a[1]);
            a[2] = __fmaf_rn(iv, w0.z, a[2]);
            a[3] = __fmaf_rn(iv, w0.w, a[3]);
            a[4] = __fmaf_rn(iv, w1.x, a[4]);
            a[5] = __fmaf_rn(iv, w1.y, a[5]);
            a[6] = __fmaf_rn(iv, w1.z, a[6]);
            a[7] = __fmaf_rn(iv, w1.w, a[7]);
        }
    }
    const int oh = oh0 + ohr, ow = ow0 + owr;
    #pragma unroll
    for (int c = 0; c < 8; c++) {
        float v = __fadd_rn(a[c], bias[cob + c]);
        if (RELU) v = fmaxf(v, 0.f);
        out[(((size_t)n * COUT + cob + c) * OH + oh) * OW + ow] = v;
    }
}

// enc2 (unchanged R6).
__global__ void __launch_bounds__(512) enc2_k(const float* __restrict__ in,
                                              const float* __restrict__ wt,
                                              const float* __restrict__ bias,
                                              float* __restrict__ out)
{
    extern __shared__ float sm[];
    float* s_in = sm;
    float* s_w  = sm + 128 * 18 * 19;
    const int n = blockIdx.z;
    const int oh0 = (blockIdx.x >> 2) * 8, ow0 = (blockIdx.x & 3) * 8;
    const int tid = threadIdx.x, px = tid & 31, cog = tid >> 5;
    const int ohr = px >> 2, owp = px & 3;
    const int ihb = oh0 * 2 - 1, iwb = ow0 * 2 - 1;

    for (int t = tid; t < 128 * 18 * 18; t += 512) {
        int ci = t / 324, r = t % 324, rr = r / 18, cc = r % 18;
        int ih = ihb + rr, iw = iwb + cc;
        float v = 0.f;
        if (ih >= 0 && ih < 64 && iw >= 0 && iw < 64)
            v = in[(((size_t)n * 128 + ci) * 64 + ih) * 64 + iw];
        s_in[(ci * 18 + rr) * 19 + cc] = v;
    }

    ull a[2][4];
    #pragma unroll
    for (int p = 0; p < 2; p++)
    #pragma unroll
    for (int j = 0; j < 4; j++) a[p][j] = 0ull;

    #pragma unroll
    for (int kh = 0; kh < 4; kh++)
    #pragma unroll
    for (int kw = 0; kw < 4; kw++) {
        for (int ci0 = 0; ci0 < 128; ci0 += 64) {
            __syncthreads();
            for (int t = tid; t < 64 * 128; t += 512)
                s_w[t] = wt[(size_t)((kh * 4 + kw) * 128 + ci0 + (t >> 7)) * 128 + (t & 127)];
            __syncthreads();
            const float* ip = &s_in[((ci0 * 18) + ohr * 2 + kh) * 19 + owp * 4 + kw];
            const float* wp = &s_w[cog * 8];
            #pragma unroll 2
            for (int ci = 0; ci < 64; ci++) {
                float i0 = ip[ci * 342];
                float i1 = ip[ci * 342 + 2];
                ull p0 = pack2(i0), p1 = pack2(i1);
                ulonglong2 wA = *(const ulonglong2*)&wp[ci * 128];
                ulonglong2 wB = *(const ulonglong2*)&wp[ci * 128 + 4];
                a[0][0] = fma2(p0, wA.x, a[0][0]);
                a[0][1] = fma2(p0, wA.y, a[0][1]);
                a[0][2] = fma2(p0, wB.x, a[0][2]);
                a[0][3] = fma2(p0, wB.y, a[0][3]);
                a[1][0] = fma2(p1, wA.x, a[1][0]);
                a[1][1] = fma2(p1, wA.y, a[1][1]);
                a[1][2] = fma2(p1, wB.x, a[1][2]);
                a[1][3] = fma2(p1, wB.y, a[1][3]);
            }
        }
    }
    const int oh = oh0 + ohr;
    #pragma unroll
    for (int p = 0; p < 2; p++) {
        int ow = ow0 + owp * 2 + p;
        #pragma unroll
        for (int j = 0; j < 4; j++) {
            int co = cog * 8 + 2 * j;
            float lo, hi;
            unpack2(a[p][j], lo, hi);
            out[(((size_t)n * 128 + co) * 32 + oh) * 32 + ow] =
                fmaxf(__fadd_rn(lo, bias[co]), 0.f);
            out[(((size_t)n * 128 + co + 1) * 32 + oh) * 32 + ow] =
                fmaxf(__fadd_rn(hi, bias[co + 1]), 0.f);
        }
    }
}

// enc3 (unchanged R6).
__global__ void __launch_bounds__(256) enc3_k(const float* __restrict__ in,
                                              const float* __restrict__ wt,
                                              const float* __restrict__ bias,
                                              float* __restrict__ out)
{
    extern __shared__ float sm[];
    float* s_in = sm;
    float* s_w  = sm + 128 * 10 * 11;
    const int n = blockIdx.z;
    const int oh0 = (blockIdx.x >> 2) * 8, ow0 = (blockIdx.x & 3) * 8;
    const int tid = threadIdx.x, px = tid & 31, cog = tid >> 5;
    const int ohr = px >> 2, owp = px & 3;
    const int ihb = oh0 - 1, iwb = ow0 - 1;

    for (int t = tid; t < 128 * 10 * 10; t += 256) {
        int ci = t / 100, r = t % 100, rr = r / 10, cc = r % 10;
        int ih = ihb + rr, iw = iwb + cc;
        float v = 0.f;
        if (ih >= 0 && ih < 32 && iw >= 0 && iw < 32)
            v = in[(((size_t)n * 128 + ci) * 32 + ih) * 32 + iw];
        s_in[(ci * 10 + rr) * 11 + cc] = v;
    }

    ull a[2][4];
    #pragma unroll
    for (int p = 0; p < 2; p++)
    #pragma unroll
    for (int j = 0; j < 4; j++) a[p][j] = 0ull;

    #pragma unroll
    for (int kh = 0; kh < 3; kh++)
    #pragma unroll
    for (int kw = 0; kw < 3; kw++) {
        __syncthreads();
        for (int t = tid; t < 128 * 64; t += 256)
            s_w[t] = wt[(size_t)((kh * 3 + kw) * 128 + (t >> 6)) * 64 + (t & 63)];
        __syncthreads();
        const float* ip = &s_in[(ohr + kh) * 11 + owp * 2 + kw];
        const float* wp = &s_w[cog * 8];
        #pragma unroll 2
        for (int ci = 0; ci < 128; ci++) {
            float i0 = ip[ci * 110];
            float i1 = ip[ci * 110 + 1];
            ull p0 = pack2(i0), p1 = pack2(i1);
            ulonglong2 wA = *(const ulonglong2*)&wp[ci * 64];
            ulonglong2 wB = *(const ulonglong2*)&wp[ci * 64 + 4];
            a[0][0] = fma2(p0, wA.x, a[0][0]);
            a[0][1] = fma2(p0, wA.y, a[0][1]);
            a[0][2] = fma2(p0, wB.x, a[0][2]);
            a[0][3] = fma2(p0, wB.y, a[0][3]);
            a[1][0] = fma2(p1, wA.x, a[1][0]);
            a[1][1] = fma2(p1, wA.y, a[1][1]);
            a[1][2] = fma2(p1, wB.x, a[1][2]);
            a[1][3] = fma2(p1, wB.y, a[1][3]);
        }
    }
    const int oh = oh0 + ohr;
    #pragma unroll
    for (int p = 0; p < 2; p++) {
        int ow = ow0 + owp * 2 + p;
        #pragma unroll
        for (int j = 0; j < 4; j++) {
            int co = cog * 8 + 2 * j;
            float lo, hi;
            unpack2(a[p][j], lo, hi);
            out[(((size_t)n * 64 + co) * 32 + oh) * 32 + ow] = __fadd_rn(lo, bias[co]);
            out[(((size_t)n * 64 + co + 1) * 32 + oh) * 32 + ow] = __fadd_rn(hi, bias[co + 1]);
        }
    }
}

// VQ (unchanged bit-exact numerics).
__global__ void __launch_bounds__(256) vq_k(const float* __restrict__ ze,
                                            const float* __restrict__ cb,
                                            float* __restrict__ zq,
                                            float* __restrict__ part)
{
    extern __shared__ float sm[];
    float* s_cb  = sm;
    float* s_cb2 = sm + 32768;
    __shared__ float red[256];
    const int tid = threadIdx.x;
    for (int t = tid; t < 32768; t += 256) s_cb[t] = cb[t];
    __syncthreads();
    for (int k = tid; k < 512; k += 256) {
        float s = 0.f;
        for (int d = 0; d < 64; d++) {
            float c = s_cb[k * 64 + d];
            s = __fadd_rn(s, __fmul_rn(c, c));
        }
        s_cb2[k] = s;
    }
    __syncthreads();

    const int v = blockIdx.x * 256 + tid;
    const int n = v >> 10, hw = v & 1023;
    const float* zp = ze + (size_t)n * 64 * 1024 + hw;
    float z[64];
    #pragma unroll
    for (int d = 0; d < 64; d++) z[d] = zp[(size_t)d * 1024];

    float z2 = 0.f;
    #pragma unroll
    for (int d = 0; d < 64; d++) z2 = __fadd_rn(z2, __fmul_rn(z[d], z[d]));

    float best = 3.4e38f;
    int bi = 0;
    for (int k0 = 0; k0 < 512; k0 += 4) {
        float dt0 = 0.f, dt1 = 0.f, dt2 = 0.f, dt3 = 0.f;
        const float* c0 = &s_cb[(k0 + 0) * 64];
        const float* c1 = &s_cb[(k0 + 1) * 64];
        const float* c2 = &s_cb[(k0 + 2) * 64];
        const float* c3 = &s_cb[(k0 + 3) * 64];
        #pragma unroll
        for (int d = 0; d < 64; d++) {
            float zd = z[d];
            dt0 = __fmaf_rn(zd, c0[d], dt0);
            dt1 = __fmaf_rn(zd, c1[d], dt1);
            dt2 = __fmaf_rn(zd, c2[d], dt2);
            dt3 = __fmaf_rn(zd, c3[d], dt3);
        }
        float s0 = __fsub_rn(__fadd_rn(z2, s_cb2[k0 + 0]), __fmul_rn(2.f, dt0));
        float s1 = __fsub_rn(__fadd_rn(z2, s_cb2[k0 + 1]), __fmul_rn(2.f, dt1));
        float s2 = __fsub_rn(__fadd_rn(z2, s_cb2[k0 + 2]), __fmul_rn(2.f, dt2));
        float s3 = __fsub_rn(__fadd_rn(z2, s_cb2[k0 + 3]), __fmul_rn(2.f, dt3));
        if (s0 < best) { best = s0; bi = k0; }
        if (s1 < best) { best = s1; bi = k0 + 1; }
        if (s2 < best) { best = s2; bi = k0 + 2; }
        if (s3 < best) { best = s3; bi = k0 + 3; }
    }

    float* zqp = zq + (size_t)n * 64 * 1024 + hw;
    float lsum = 0.f;
    #pragma unroll
    for (int d = 0; d < 64; d++) {
        float c = s_cb[bi * 64 + d];
        float df = z[d] - c;
        lsum = fmaf(df, df, lsum);
        zqp[(size_t)d * 1024] = __fadd_rn(z[d], __fsub_rn(c, z[d]));
    }
    red[tid] = lsum;
    __syncthreads();
    for (int s = 128; s > 0; s >>= 1) {
        if (tid < s) red[tid] += red[tid + s];
        __syncthreads();
    }
    if (tid == 0) part[blockIdx.x] = red[0];
}

// Deconv via mma.sync bf16, split-bf16 3-product; smem-staged coalesced output.
template <int CIN, int IHW>
__global__ void __launch_bounds__(256) deconv_mma_k(
    const float* __restrict__ in, const __nv_bfloat16* __restrict__ gB,
    const float* __restrict__ bias, float* __restrict__ out)
{
    constexpr int K = CIN * 4;
    constexpr int NCH = K / 64;
    constexpr int OH = IHW * 2, OW = IHW * 2;
    constexpr int TX = IHW / 16;
    constexpr int PATCH_B = CIN * 180 * 4;
    constexpr int AH_B = PATCH_B, AL_B = AH_B + 18432;
    constexpr int BH_B = AL_B + 18432, BL_B = BH_B + 18432;

    extern __shared__ char smc[];
    float* s_patch = (float*)smc;
    const uint32 sb = smem_u32(smc);

    const int tid = threadIdx.x;
    const int lane = tid & 31, wrp = tid >> 5;
    const int mg = wrp & 3, ng = wrp >> 2;
    const int n = blockIdx.z, cl = blockIdx.y;
    const int dh = cl >> 1, dw = cl & 1;
    const int y0 = (blockIdx.x / TX) * 8, x0 = (blockIdx.x % TX) * 16;

    for (int t = tid; t < CIN * 180; t += 256) {
        int ci = t / 180, r = t % 180, rr = r / 18, cc = r % 18;
        int yy = y0 - 1 + rr, xx = x0 - 1 + cc;
        float v = 0.f;
        if (yy >= 0 && yy < IHW && xx >= 0 && xx < IHW)
            v = in[(((size_t)n * CIN + ci) * IHW + yy) * IHW + xx];
        s_patch[t] = v;
    }

    float c[2][8][4];
    #pragma unroll
    for (int i = 0; i < 2; i++)
    #pragma unroll
    for (int j = 0; j < 8; j++)
    #pragma unroll
    for (int q = 0; q < 4; q++) c[i][j][q] = 0.f;

    const int am = tid >> 1, aks = (tid & 1) * 32;
    const int a_yl = am >> 4, a_xl = am & 15;
    const int a_pr0 = a_yl + dh + 1, a_pc0 = a_xl + dw + 1;

    for (int kc = 0; kc < NCH; kc++) {
        __syncthreads();
        {
            uint32* ah = (uint32*)(smc + AH_B);
            uint32* al = (uint32*)(smc + AL_B);
            const int kc16 = kc * 16;
            #pragma unroll 4
            for (int j2 = 0; j2 < 16; j2++) {
                int k = aks + 2 * j2;
                int ci = kc16 + (k >> 2);
                int r = (k >> 1) & 1;
                const float* pp = &s_patch[(ci * 10 + (a_pr0 - r)) * 18];
                float v0 = pp[a_pc0];
                float v1 = pp[a_pc0 - 1];
                int idx = (am * 72 + k) >> 1;
                ah[idx] = pkbf2(v0, v1);
                al[idx] = pkbf2(bfres(v0), bfres(v1));
            }
        }
        {
            const __nv_bfloat16* bh = gB + ((size_t)(cl * 2 + 0) * 128) * K + kc * 64;
            const __nv_bfloat16* bl = gB + ((size_t)(cl * 2 + 1) * 128) * K + kc * 64;
            for (int e = tid; e < 1024; e += 256) {
                int co = e >> 3, k8 = (e & 7) * 8;
                uint4 vh = *(const uint4*)(bh + (size_t)co * K + k8);
                uint4 vl = *(const uint4*)(bl + (size_t)co * K + k8);
                *(uint4*)(smc + BH_B + (co * 72 + k8) * 2) = vh;
                *(uint4*)(smc + BL_B + (co * 72 + k8) * 2) = vl;
            }
        }
        __syncthreads();

        #pragma unroll
        for (int k16i = 0; k16i < 4; k16i++) {
            const int k16 = k16i * 16;
            uint32 a_h[2][4], a_l[2][4];
            #pragma unroll
            for (int i = 0; i < 2; i++) {
                int row = mg * 32 + i * 16 + (lane & 15);
                uint32 off = (uint32)((row * 72 + k16 + ((lane >> 4) << 3)) * 2);
                ldm_x4(a_h[i][0], a_h[i][1], a_h[i][2], a_h[i][3], sb + AH_B + off);
                ldm_x4(a_l[i][0], a_l[i][1], a_l[i][2], a_l[i][3], sb + AL_B + off);
            }
            uint32 b_h[8][2], b_l[8][2];
            #pragma unroll
            for (int j = 0; j < 8; j++) {
                int nrow = ng * 64 + j * 8 + (lane & 7);
                uint32 off = (uint32)((nrow * 72 + k16 + (((lane >> 3) & 1) << 3)) * 2);
                ldm_x2(b_h[j][0], b_h[j][1], sb + BH_B + off);
                ldm_x2(b_l[j][0], b_l[j][1], sb + BL_B + off);
            }
            #pragma unroll
            for (int i = 0; i < 2; i++)
            #pragma unroll
            for (int j = 0; j < 8; j++) {
                mma16816(c[i][j], a_h[i], b_h[j]);
                mma16816(c[i][j], a_h[i], b_l[j]);
                mma16816(c[i][j], a_l[i], b_h[j]);
            }
        }
    }

    // stage C in smem (reuse A/B buffers), then coalesced strided stores.
    __syncthreads();
    float* s_out = (float*)(smc + AH_B);   // [128co][130] (px 0..127)
    #pragma unroll
    for (int i = 0; i < 2; i++) {
        #pragma unroll
        for (int rr = 0; rr < 2; rr++) {
            int row = mg * 32 + i * 16 + rr * 8 + (lane >> 2);
            #pragma unroll
            for (int j = 0; j < 8; j++) {
                int col = ng * 64 + j * 8 + (lane & 3) * 2;
                s_out[col * 130 + row] = c[i][j][rr * 2 + 0];
                s_out[(col + 1) * 130 + row] = c[i][j][rr * 2 + 1];
            }
        }
    }
    __syncthreads();
    const int xl = tid & 15, grp = tid >> 4;
    for (int g2 = grp; g2 < 1024; g2 += 16) {
        int co = g2 >> 3, y = g2 & 7;
        float v = s_out[co * 130 + y * 16 + xl] + bias[co];
        int oh = 2 * (y0 + y) + dh, ow = 2 * (x0 + xl) + dw;
        out[((size_t)n * 128 + co) * OH * OW + (size_t)oh * OW + ow] = fmaxf(v, 0.f);
    }
}

// dec3 + recon-MSE partial; 4-row tiles, 512 threads.
__global__ void __launch_bounds__(512) dec3_k(const float* __restrict__ in,
                                              const float* __restrict__ wtt,
                                              const float* __restrict__ bias,
                                              const float* __restrict__ x,
                                              float* __restrict__ out,
                                              float* __restrict__ rec_part)
{
    extern __shared__ float sm[];
    float* s_in = sm;                    // [16][6][130]
    float* s_w  = sm + 16 * 6 * 130;     // [128*9][4]
    __shared__ float red[512];
    const int n = blockIdx.y, oh0 = blockIdx.x * 4;
    const int tid = threadIdx.x, r = tid >> 7, col = tid & 127, oh = oh0 + r;

    for (int t = tid; t < 128 * 9 * 3; t += 512)
        s_w[(t / 3) * 4 + t % 3] = wtt[t];

    float a0 = 0.f, a1 = 0.f, a2 = 0.f;
    for (int ci0 = 0; ci0 < 128; ci0 += 16) {
        for (int t = tid; t < 16 * 6 * 130; t += 512) {
            int cil = t / 780, r2 = t % 780, rr = r2 / 130, cc = r2 % 130;
            int ih = oh0 - 1 + rr, iw = cc - 1;
            float v = 0.f;
            if (ih >= 0 && ih < 128 && iw >= 0 && iw < 128)
                v = in[(((size_t)n * 128 + ci0 + cil) * 128 + ih) * 128 + iw];
            s_in[t] = v;
        }
        __syncthreads();
        for (int cil = 0; cil < 16; cil++) {
            #pragma unroll
            for (int kh = 0; kh < 3; kh++) {
                const float* rp = &s_in[(cil * 6 + r + kh) * 130 + col];
                #pragma unroll
                for (int kw = 0; kw < 3; kw++) {
                    float iv = rp[kw];
                    float4 wv = *(const float4*)&s_w[((ci0 + cil) * 9 + kh * 3 + kw) * 4];
                    a0 = fmaf(wv.x, iv, a0);
                    a1 = fmaf(wv.y, iv, a1);
                    a2 = fmaf(wv.z, iv, a2);
                }
            }
        }
        __syncthreads();
    }
    float lsum = 0.f;
    float accs[3] = {a0, a1, a2};
    #pragma unroll
    for (int co = 0; co < 3; co++) {
        float v = accs[co] + bias[co];
        size_t idx = (((size_t)n * 3 + co) * 128 + oh) * 128 + col;
        out[idx] = v;
        float d = v - x[idx];
        lsum = fmaf(d, d, lsum);
    }
    red[tid] = lsum;
    __syncthreads();
    for (int s = 256; s > 0; s >>= 1) {
        if (tid < s) red[tid] += red[tid + s];
        __syncthreads();
    }
    if (tid == 0) rec_part[(size_t)n * 32 + blockIdx.x] = red[0];
}

__global__ void __launch_bounds__(256) finalize_k(const float* __restrict__ rec_part,
                                                  const float* __restrict__ vq_part,
                                                  float* __restrict__ out)
{
    __shared__ double rA[256], rB[256];
    const int tid = threadIdx.x;
    double s = 0.0;
    for (int t = tid; t < 2048; t += 256) s += (double)rec_part[t];
    rA[tid] = s;
    rB[tid] = (double)vq_part[tid];
    __syncthreads();
    for (int st = 128; st > 0; st >>= 1) {
        if (tid < st) { rA[tid] += rA[tid + st]; rB[tid] += rB[tid + st]; }
        __syncthreads();
    }
    if (tid == 0) {
        double recon = rA[0] / 3145728.0;
        double vq    = 1.25 * rB[0] / 4194304.0;
        out[3145728] = (float)(recon + vq);
        out[3145729] = (float)recon;
        out[3145730] = (float)vq;
    }
}

extern "C" void kernel_launch(void* const* d_in, const int* in_sizes, int n_in,
                              void* d_out, int out_size)
{
    (void)in_sizes; (void)n_in; (void)out_size;
    const float* x   = (const float*)d_in[0];
    const float* ew1 = (const float*)d_in[1];
    const float* eb1 = (const float*)d_in[2];
    const float* ew2 = (const float*)d_in[3];
    const float* eb2 = (const float*)d_in[4];
    const float* ew3 = (const float*)d_in[5];
    const float* eb3 = (const float*)d_in[6];
    const float* cb  = (const float*)d_in[7];
    const float* dw1 = (const float*)d_in[8];
    const float* db1 = (const float*)d_in[9];
    const float* dw2 = (const float*)d_in[10];
    const float* db2 = (const float*)d_in[11];
    const float* dw3 = (const float*)d_in[12];
    const float* db3 = (const float*)d_in[13];
    float* out = (float*)d_out;

    void *h1, *h2, *ze, *zq, *dd1, *dd2, *vqp, *recp;
    void *w1t, *w2t, *w3t, *w3dt, *bw1, *bw2;
    cudaGetSymbolAddress(&h1,  g_h1);
    cudaGetSymbolAddress(&h2,  g_h2);
    cudaGetSymbolAddress(&ze,  g_ze);
    cudaGetSymbolAddress(&zq,  g_zq);
    cudaGetSymbolAddress(&dd1, g_d1);
    cudaGetSymbolAddress(&dd2, g_d2);
    cudaGetSymbolAddress(&vqp,  g_vq_part);
    cudaGetSymbolAddress(&recp, g_rec_part);
    cudaGetSymbolAddress(&w1t,  g_w1t);
    cudaGetSymbolAddress(&w2t,  g_w2t);
    cudaGetSymbolAddress(&w3t,  g_w3t);
    cudaGetSymbolAddress(&w3dt, g_w3dt);
    cudaGetSymbolAddress(&bw1,  g_bw1);
    cudaGetSymbolAddress(&bw2,  g_bw2);

    const int SM_E1 = (1028 + 16 * 3 * 64) * 4;    // 16400
    const int SM_E2 = (128 * 18 * 19 + 64 * 128) * 4;
    const int SM_E3 = (128 * 10 * 11 + 128 * 64) * 4;
    const int SM_M1 = 64 * 180 * 4 + 4 * 18432;    // 119808
    const int SM_M2 = 128 * 180 * 4 + 4 * 18432;   // 165888
    const int SM_D3 = (16 * 6 * 130 + 128 * 9 * 4) * 4;  // 68352
    const int SM_VQ = (32768 + 512) * 4;

    cudaFuncSetAttribute((const void*)enc2_k,
                         cudaFuncAttributeMaxDynamicSharedMemorySize, SM_E2);
    cudaFuncSetAttribute((const void*)enc3_k,
                         cudaFuncAttributeMaxDynamicSharedMemorySize, SM_E3);
    cudaFuncSetAttribute((const void*)deconv_mma_k<64,32>,
                         cudaFuncAttributeMaxDynamicSharedMemorySize, SM_M1);
    cudaFuncSetAttribute((const void*)deconv_mma_k<128,64>,
                         cudaFuncAttributeMaxDynamicSharedMemorySize, SM_M2);
    cudaFuncSetAttribute((const void*)vq_k,
                         cudaFuncAttributeMaxDynamicSharedMemorySize, SM_VQ);
    cudaFuncSetAttribute((const void*)dec3_k,
                         cudaFuncAttributeMaxDynamicSharedMemorySize, SM_D3);

    wprep_k<<<256, 256>>>(ew1, ew2, ew3, dw1, dw2, dw3);
    conv_seq<4,2,3,128,128,true><<<dim3(64, 2, NB), 512, SM_E1>>>(
        x, (const float*)w1t, eb1, (float*)h1);
    enc2_k<<<dim3(16, 1, NB), 512, SM_E2>>>(
        (const float*)h1, (const float*)w2t, eb2, (float*)h2);
    enc3_k<<<dim3(16, 1, NB), 256, SM_E3>>>(
        (const float*)h2, (const float*)w3t, eb3, (float*)ze);
    vq_k<<<256, 256, SM_VQ>>>(
        (const float*)ze, cb, (float*)zq, (float*)vqp);
    deconv_mma_k<64,32><<<dim3(8, 4, NB), 256, SM_M1>>>(
        (const float*)zq, (const __nv_bfloat16*)bw1, db1, (float*)dd1);
    deconv_mma_k<128,64><<<dim3(32, 4, NB), 256, SM_M2>>>(
        (const float*)dd1, (const __nv_bfloat16*)bw2, db2, (float*)dd2);
    dec3_k<<<dim3(32, NB), 512, SM_D3>>>(
        (const float*)dd2, (const float*)w3dt, db3, x, out, (float*)recp);
    finalize_k<<<1, 256>>>(
        (const float*)recp, (const float*)vqp, out);
}

// round 12
// speedup vs baseline: 1.0045x; 1.0045x over previous
#include <cuda_runtime.h>
#include <cuda_bf16.h>
#include <cstdint>
#include <cstddef>

#define NB 64
typedef unsigned long long ull;
typedef unsigned int uint32;

__device__ __forceinline__ ull pack2(float x) {
    ull d; unsigned u = __float_as_uint(x);
    asm("mov.b64 %0, {%1, %1};" : "=l"(d) : "r"(u));
    return d;
}
__device__ __forceinline__ ull fma2(ull a, ull b, ull c) {
    ull d;
    asm("fma.rn.f32x2 %0, %1, %2, %3;" : "=l"(d) : "l"(a), "l"(b), "l"(c));
    return d;
}
__device__ __forceinline__ void unpack2(ull a, float& lo, float& hi) {
    unsigned l, h;
    asm("mov.b64 {%0, %1}, %2;" : "=r"(l), "=r"(h) : "l"(a));
    lo = __uint_as_float(l); hi = __uint_as_float(h);
}
__device__ __forceinline__ uint32 smem_u32(const void* p) {
    uint32 a;
    asm("{ .reg .u64 t; cvta.to.shared.u64 t, %1; cvt.u32.u64 %0, t; }" : "=r"(a) : "l"(p));
    return a;
}
__device__ __forceinline__ void ldm_x4(uint32& r0, uint32& r1, uint32& r2, uint32& r3, uint32 a) {
    asm volatile("ldmatrix.sync.aligned.m8n8.x4.shared.b16 {%0,%1,%2,%3}, [%4];"
                 : "=r"(r0), "=r"(r1), "=r"(r2), "=r"(r3) : "r"(a));
}
__device__ __forceinline__ void ldm_x2(uint32& r0, uint32& r1, uint32 a) {
    asm volatile("ldmatrix.sync.aligned.m8n8.x2.shared.b16 {%0,%1}, [%2];"
                 : "=r"(r0), "=r"(r1) : "r"(a));
}
__device__ __forceinline__ void mma16816(float* c, const uint32* a, const uint32* b) {
    asm volatile(
        "mma.sync.aligned.m16n8k16.row.col.f32.bf16.bf16.f32 "
        "{%0,%1,%2,%3}, {%4,%5,%6,%7}, {%8,%9}, {%0,%1,%2,%3};"
        : "+f"(c[0]), "+f"(c[1]), "+f"(c[2]), "+f"(c[3])
        : "r"(a[0]), "r"(a[1]), "r"(a[2]), "r"(a[3]), "r"(b[0]), "r"(b[1]));
}
__device__ __forceinline__ uint32 pkbf2(float a, float b) {
    return (uint32)__bfloat16_as_ushort(__float2bfloat16(a))
         | ((uint32)__bfloat16_as_ushort(__float2bfloat16(b)) << 16);
}
__device__ __forceinline__ float bfres(float v) {
    return v - __bfloat162float(__float2bfloat16(v));
}

__device__ float g_h1[(size_t)NB * 128 * 64 * 64];
__device__ float g_h2[(size_t)NB * 128 * 32 * 32];
__device__ float g_ze[(size_t)NB * 64 * 32 * 32];
__device__ float g_zq[(size_t)NB * 64 * 32 * 32];
__device__ float g_d1[(size_t)NB * 128 * 64 * 64];
__device__ float g_d2[(size_t)NB * 128 * 128 * 128];
__device__ float g_vq_part[256];
__device__ float g_rec_part[4096];
__device__ float g_w1t[16 * 3 * 128];
__device__ float g_w2t[16 * 128 * 128];
__device__ float g_w3t[9 * 128 * 64];
__device__ float g_w3dt[128 * 9 * 3];
__device__ __align__(16) __nv_bfloat16 g_bw1[4 * 2 * 128 * 256];  // [cl][h][co][K]
__device__ __align__(16) __nv_bfloat16 g_bw2[4 * 2 * 128 * 512];  // [cl][h][co][K]

__global__ void wprep_k(const float* __restrict__ w1, const float* __restrict__ w2,
                        const float* __restrict__ w3, const float* __restrict__ dw1,
                        const float* __restrict__ dw2, const float* __restrict__ dw3)
{
    int st = gridDim.x * blockDim.x, g = blockIdx.x * blockDim.x + threadIdx.x;
    for (int t = g; t < 16 * 3 * 128; t += st) {
        int co = t & 127, r = t >> 7, ci = r % 3, kk = r / 3;
        g_w1t[(kk * 3 + ci) * 128 + co] = w1[((size_t)co * 3 + ci) * 16 + kk];
    }
    for (int t = g; t < 16 * 128 * 128; t += st) {
        int co = t & 127, r = t >> 7, ci = r & 127, kk = r >> 7;
        g_w2t[(kk * 128 + ci) * 128 + co] = w2[((size_t)co * 128 + ci) * 16 + kk];
    }
    for (int t = g; t < 9 * 128 * 64; t += st) {
        int co = t & 63, r = t >> 6, ci = r & 127, kk = r >> 7;
        g_w3t[(kk * 128 + ci) * 64 + co] = w3[((size_t)co * 128 + ci) * 9 + kk];
    }
    for (int t = g; t < 128 * 9 * 3; t += st) {
        int co = t % 3, r = t / 3, kk = r % 9, ci = r / 9;
        g_w3dt[t] = dw3[((size_t)co * 128 + ci) * 9 + kk];
    }
    for (int t = g; t < 4 * 2 * 128 * 256; t += st) {
        int k = t & 255, r2 = t >> 8, co = r2 & 127, h = (r2 >> 7) & 1, cl = r2 >> 8;
        int ci = k >> 2, rr = (k >> 1) & 1, cc = k & 1;
        int dh = cl >> 1, dw = cl & 1;
        float w = dw1[((size_t)ci * 128 + co) * 16 + (1 - dh + 2 * rr) * 4 + (1 - dw + 2 * cc)];
        g_bw1[t] = __float2bfloat16(h ? bfres(w) : w);
    }
    for (int t = g; t < 4 * 2 * 128 * 512; t += st) {
        int k = t & 511, r2 = t >> 9, co = r2 & 127, h = (r2 >> 7) & 1, cl = r2 >> 8;
        int ci = k >> 2, rr = (k >> 1) & 1, cc = k & 1;
        int dh = cl >> 1, dw = cl & 1;
        float w = dw2[((size_t)ci * 128 + co) * 16 + (1 - dh + 2 * rr) * 4 + (1 - dw + 2 * cc)];
        g_bw2[t] = __float2bfloat16(h ? bfres(w) : w);
    }
}

// enc1 (bit-exact scalar chain; exact R10/R6 version).
template <int K, int S, int CIN, int COUT, int H, bool RELU>
__global__ void __launch_bounds__(512) conv_seq(const float* __restrict__ in,
                                                const float* __restrict__ wt,
                                                const float* __restrict__ bias,
                                                float* __restrict__ out)
{
    constexpr int W = H, OH = (H + 2 - K) / S + 1, OW = OH;
    constexpr int IHS = 7 * S + K, IWS = 7 * S + K, IWP = IWS + 1;
    constexpr int SW_OFF = ((CIN * IHS * IWP + 3) / 4) * 4;
    extern __shared__ float sm[];
    float* s_in = sm;
    float* s_w  = sm + SW_OFF;
    const int n = blockIdx.z, co0 = blockIdx.y * 64;
    constexpr int TWn = OW / 8;
    const int oh0 = (blockIdx.x / TWn) * 8, ow0 = (blockIdx.x % TWn) * 8;
    const int tid = threadIdx.x, px = tid & 63, cog = tid >> 6;
    const int ohr = px >> 3, owr = px & 7;
    const int ihb = oh0 * S - 1, iwb = ow0 * S - 1;

    for (int t = tid; t < CIN * IHS * IWS; t += 512) {
        int ci = t / (IHS * IWS), r = t % (IHS * IWS), rr = r / IWS, cc = r % IWS;
        int ih = ihb + rr, iw = iwb + cc;
        float v = 0.f;
        if (ih >= 0 && ih < H && iw >= 0 && iw < W)
            v = in[(((size_t)n * CIN + ci) * H + ih) * W + iw];
        s_in[(ci * IHS + rr) * IWP + cc] = v;
    }
    const int cob = co0 + cog * 8;
    float a[8];
    #pragma unroll
    for (int i = 0; i < 8; i++) a[i] = 0.f;
    #pragma unroll
    for (int kh = 0; kh < K; kh++)
    #pragma unroll
    for (int kw = 0; kw < K; kw++) {
        __syncthreads();
        for (int t = tid; t < CIN * 64; t += 512)
            s_w[t] = wt[(size_t)((kh * K + kw) * CIN + (t >> 6)) * COUT + co0 + (t & 63)];
        __syncthreads();
        const float* ip = &s_in[(ohr * S + kh) * IWP + owr * S + kw];
        const float* wp = &s_w[cog * 8];
        #pragma unroll 3
        for (int ci = 0; ci < CIN; ci++) {
            float iv = ip[ci * IHS * IWP];
            float4 w0 = *(const float4*)&wp[ci * 64];
            float4 w1 = *(const float4*)&wp[ci * 64 + 4];
            a[0] = __fmaf_rn(iv, w0.x, a[0]);
            a[1] = __fmaf_rn(iv, w0.y, a[1]);
            a[2] = __fmaf_rn(iv, w0.z, a[2]);
            a[3] = __fmaf_rn(iv, w0.w, a[3]);
            a[4] = __fmaf_rn(iv, w1.x, a[4]);
            a[5] = __fmaf_rn(iv, w1.y, a[5]);
            a[6] = __fmaf_rn(iv, w1.z, a[6]);
            a[7] = __fmaf_rn(iv, w1.w, a[7]);
        }
    }
    const int oh = oh0 + ohr, ow = ow0 + owr;
    #pragma unroll
    for (int c = 0; c < 8; c++) {
        float v = __fadd_rn(a[c], bias[cob + c]);
        if (RELU) v = fmaxf(v, 0.f);
        out[(((size_t)n * COUT + cob + c) * OH + oh) * OW + ow] = v;
    }
}

// enc2: 1024 threads, 4 co/thread; identical FMA chain per output.
__global__ void __launch_bounds__(1024) enc2_k(const float* __restrict__ in,
                                               const float* __restrict__ wt,
                                               const float* __restrict__ bias,
                                               float* __restrict__ out)
{
    extern __shared__ float sm[];
    float* s_in = sm;                 // [128][18][19]
    float* s_w  = sm + 128 * 18 * 19; // [64ci][128co]
    const int n = blockIdx.z;
    const int oh0 = (blockIdx.x >> 2) * 8, ow0 = (blockIdx.x & 3) * 8;
    const int tid = threadIdx.x, px = tid & 31, cog = tid >> 5;   // cog 0..31
    const int ohr = px >> 2, owp = px & 3;
    const int ihb = oh0 * 2 - 1, iwb = ow0 * 2 - 1;

    for (int t = tid; t < 128 * 18 * 18; t += 1024) {
        int ci = t / 324, r = t % 324, rr = r / 18, cc = r % 18;
        int ih = ihb + rr, iw = iwb + cc;
        float v = 0.f;
        if (ih >= 0 && ih < 64 && iw >= 0 && iw < 64)
            v = in[(((size_t)n * 128 + ci) * 64 + ih) * 64 + iw];
        s_in[(ci * 18 + rr) * 19 + cc] = v;
    }

    ull a[2][2];
    #pragma unroll
    for (int p = 0; p < 2; p++)
    #pragma unroll
    for (int j = 0; j < 2; j++) a[p][j] = 0ull;

    #pragma unroll
    for (int kh = 0; kh < 4; kh++)
    #pragma unroll
    for (int kw = 0; kw < 4; kw++) {
        for (int ci0 = 0; ci0 < 128; ci0 += 64) {
            __syncthreads();
            for (int t = tid; t < 64 * 128; t += 1024)
                s_w[t] = wt[(size_t)((kh * 4 + kw) * 128 + ci0 + (t >> 7)) * 128 + (t & 127)];
            __syncthreads();
            const float* ip = &s_in[((ci0 * 18) + ohr * 2 + kh) * 19 + owp * 4 + kw];
            const float* wp = &s_w[cog * 4];
            #pragma unroll 4
            for (int ci = 0; ci < 64; ci++) {
                float i0 = ip[ci * 342];
                float i1 = ip[ci * 342 + 2];
                ull p0 = pack2(i0), p1 = pack2(i1);
                ulonglong2 wA = *(const ulonglong2*)&wp[ci * 128];
                a[0][0] = fma2(p0, wA.x, a[0][0]);
                a[0][1] = fma2(p0, wA.y, a[0][1]);
                a[1][0] = fma2(p1, wA.x, a[1][0]);
                a[1][1] = fma2(p1, wA.y, a[1][1]);
            }
        }
    }
    const int oh = oh0 + ohr;
    #pragma unroll
    for (int p = 0; p < 2; p++) {
        int ow = ow0 + owp * 2 + p;
        #pragma unroll
        for (int j = 0; j < 2; j++) {
            int co = cog * 4 + 2 * j;
            float lo, hi;
            unpack2(a[p][j], lo, hi);
            out[(((size_t)n * 128 + co) * 32 + oh) * 32 + ow] =
                fmaxf(__fadd_rn(lo, bias[co]), 0.f);
            out[(((size_t)n * 128 + co + 1) * 32 + oh) * 32 + ow] =
                fmaxf(__fadd_rn(hi, bias[co + 1]), 0.f);
        }
    }
}

// enc3: 512 threads, 4 co/thread; identical FMA chain per output.
__global__ void __launch_bounds__(512) enc3_k(const float* __restrict__ in,
                                              const float* __restrict__ wt,
                                              const float* __restrict__ bias,
                                              float* __restrict__ out)
{
    extern __shared__ float sm[];
    float* s_in = sm;                 // [128][10][11]
    float* s_w  = sm + 128 * 10 * 11; // [128ci][64co]
    const int n = blockIdx.z;
    const int oh0 = (blockIdx.x >> 2) * 8, ow0 = (blockIdx.x & 3) * 8;
    const int tid = threadIdx.x, px = tid & 31, cog = tid >> 5;   // cog 0..15
    const int ohr = px >> 2, owp = px & 3;
    const int ihb = oh0 - 1, iwb = ow0 - 1;

    for (int t = tid; t < 128 * 10 * 10; t += 512) {
        int ci = t / 100, r = t % 100, rr = r / 10, cc = r % 10;
        int ih = ihb + rr, iw = iwb + cc;
        float v = 0.f;
        if (ih >= 0 && ih < 32 && iw >= 0 && iw < 32)
            v = in[(((size_t)n * 128 + ci) * 32 + ih) * 32 + iw];
        s_in[(ci * 10 + rr) * 11 + cc] = v;
    }

    ull a[2][2];
    #pragma unroll
    for (int p = 0; p < 2; p++)
    #pragma unroll
    for (int j = 0; j < 2; j++) a[p][j] = 0ull;

    #pragma unroll
    for (int kh = 0; kh < 3; kh++)
    #pragma unroll
    for (int kw = 0; kw < 3; kw++) {
        __syncthreads();
        for (int t = tid; t < 128 * 64; t += 512)
            s_w[t] = wt[(size_t)((kh * 3 + kw) * 128 + (t >> 6)) * 64 + (t & 63)];
        __syncthreads();
        const float* ip = &s_in[(ohr + kh) * 11 + owp * 2 + kw];
        const float* wp = &s_w[cog * 4];
        #pragma unroll 4
        for (int ci = 0; ci < 128; ci++) {
            float i0 = ip[ci * 110];
            float i1 = ip[ci * 110 + 1];
            ull p0 = pack2(i0), p1 = pack2(i1);
            ulonglong2 wA = *(const ulonglong2*)&wp[ci * 64];
            a[0][0] = fma2(p0, wA.x, a[0][0]);
            a[0][1] = fma2(p0, wA.y, a[0][1]);
            a[1][0] = fma2(p1, wA.x, a[1][0]);
            a[1][1] = fma2(p1, wA.y, a[1][1]);
        }
    }
    const int oh = oh0 + ohr;
    #pragma unroll
    for (int p = 0; p < 2; p++) {
        int ow = ow0 + owp * 2 + p;
        #pragma unroll
        for (int j = 0; j < 2; j++) {
            int co = cog * 4 + 2 * j;
            float lo, hi;
            unpack2(a[p][j], lo, hi);
            out[(((size_t)n * 64 + co) * 32 + oh) * 32 + ow] = __fadd_rn(lo, bias[co]);
            out[(((size_t)n * 64 + co + 1) * 32 + oh) * 32 + ow] = __fadd_rn(hi, bias[co + 1]);
        }
    }
}

// VQ (unchanged bit-exact numerics).
__global__ void __launch_bounds__(256) vq_k(const float* __restrict__ ze,
                                            const float* __restrict__ cb,
                                            float* __restrict__ zq,
                                            float* __restrict__ part)
{
    extern __shared__ float sm[];
    float* s_cb  = sm;
    float* s_cb2 = sm + 32768;
    __shared__ float red[256];
    const int tid = threadIdx.x;
    for (int t = tid; t < 32768; t += 256) s_cb[t] = cb[t];
    __syncthreads();
    for (int k = tid; k < 512; k += 256) {
        float s = 0.f;
        for (int d = 0; d < 64; d++) {
            float c = s_cb[k * 64 + d];
            s = __fadd_rn(s, __fmul_rn(c, c));
        }
        s_cb2[k] = s;
    }
    __syncthreads();

    const int v = blockIdx.x * 256 + tid;
    const int n = v >> 10, hw = v & 1023;
    const float* zp = ze + (size_t)n * 64 * 1024 + hw;
    float z[64];
    #pragma unroll
    for (int d = 0; d < 64; d++) z[d] = zp[(size_t)d * 1024];

    float z2 = 0.f;
    #pragma unroll
    for (int d = 0; d < 64; d++) z2 = __fadd_rn(z2, __fmul_rn(z[d], z[d]));

    float best = 3.4e38f;
    int bi = 0;
    for (int k0 = 0; k0 < 512; k0 += 4) {
        float dt0 = 0.f, dt1 = 0.f, dt2 = 0.f, dt3 = 0.f;
        const float* c0 = &s_cb[(k0 + 0) * 64];
        const float* c1 = &s_cb[(k0 + 1) * 64];
        const float* c2 = &s_cb[(k0 + 2) * 64];
        const float* c3 = &s_cb[(k0 + 3) * 64];
        #pragma unroll
        for (int d = 0; d < 64; d++) {
            float zd = z[d];
            dt0 = __fmaf_rn(zd, c0[d], dt0);
            dt1 = __fmaf_rn(zd, c1[d], dt1);
            dt2 = __fmaf_rn(zd, c2[d], dt2);
            dt3 = __fmaf_rn(zd, c3[d], dt3);
        }
        float s0 = __fsub_rn(__fadd_rn(z2, s_cb2[k0 + 0]), __fmul_rn(2.f, dt0));
        float s1 = __fsub_rn(__fadd_rn(z2, s_cb2[k0 + 1]), __fmul_rn(2.f, dt1));
        float s2 = __fsub_rn(__fadd_rn(z2, s_cb2[k0 + 2]), __fmul_rn(2.f, dt2));
        float s3 = __fsub_rn(__fadd_rn(z2, s_cb2[k0 + 3]), __fmul_rn(2.f, dt3));
        if (s0 < best) { best = s0; bi = k0; }
        if (s1 < best) { best = s1; bi = k0 + 1; }
        if (s2 < best) { best = s2; bi = k0 + 2; }
        if (s3 < best) { best = s3; bi = k0 + 3; }
    }

    float* zqp = zq + (size_t)n * 64 * 1024 + hw;
    float lsum = 0.f;
    #pragma unroll
    for (int d = 0; d < 64; d++) {
        float c = s_cb[bi * 64 + d];
        float df = z[d] - c;
        lsum = fmaf(df, df, lsum);
        zqp[(size_t)d * 1024] = __fadd_rn(z[d], __fsub_rn(c, z[d]));
    }
    red[tid] = lsum;
    __syncthreads();
    for (int s = 128; s > 0; s >>= 1) {
        if (tid < s) red[tid] += red[tid + s];
        __syncthreads();
    }
    if (tid == 0) part[blockIdx.x] = red[0];
}

// Deconv via mma.sync bf16, split-bf16 3-product. 512 thr / 16 warps,
// warp tile 32px x 32co; direct global stores (R10 path).
template <int CIN, int IHW>
__global__ void __launch_bounds__(512) deconv_mma_k(
    const float* __restrict__ in, const __nv_bfloat16* __restrict__ gB,
    const float* __restrict__ bias, float* __restrict__ out)
{
    constexpr int K = CIN * 4;
    constexpr int NCH = K / 64;
    constexpr int OH = IHW * 2, OW = IHW * 2;
    constexpr int TX = IHW / 16;
    constexpr int PATCH_B = CIN * 180 * 4;
    constexpr int AH_B = PATCH_B, AL_B = AH_B + 18432;
    constexpr int BH_B = AL_B + 18432, BL_B = BH_B + 18432;

    extern __shared__ char smc[];
    float* s_patch = (float*)smc;
    const uint32 sb = smem_u32(smc);

    const int tid = threadIdx.x;
    const int lane = tid & 31, wrp = tid >> 5;     // 16 warps
    const int mg = wrp & 3, ng = wrp >> 2;          // 4x 32px, 4x 32co
    const int n = blockIdx.z, cl = blockIdx.y;
    const int dh = cl >> 1, dw = cl & 1;
    const int y0 = (blockIdx.x / TX) * 8, x0 = (blockIdx.x % TX) * 16;

    for (int t = tid; t < CIN * 180; t += 512) {
        int ci = t / 180, r = t % 180, rr = r / 18, cc = r % 18;
        int yy = y0 - 1 + rr, xx = x0 - 1 + cc;
        float v = 0.f;
        if (yy >= 0 && yy < IHW && xx >= 0 && xx < IHW)
            v = in[(((size_t)n * CIN + ci) * IHW + yy) * IHW + xx];
        s_patch[t] = v;
    }

    float c[2][4][4];
    #pragma unroll
    for (int i = 0; i < 2; i++)
    #pragma unroll
    for (int j = 0; j < 4; j++)
    #pragma unroll
    for (int q = 0; q < 4; q++) c[i][j][q] = 0.f;

    const int am = tid >> 2, aks = (tid & 3) * 16;
    const int a_yl = am >> 4, a_xl = am & 15;
    const int a_pr0 = a_yl + dh + 1, a_pc0 = a_xl + dw + 1;

    for (int kc = 0; kc < NCH; kc++) {
        __syncthreads();
        {
            uint32* ah = (uint32*)(smc + AH_B);
            uint32* al = (uint32*)(smc + AL_B);
            const int kc16 = kc * 16;
            #pragma unroll 4
            for (int j2 = 0; j2 < 8; j2++) {
                int k = aks + 2 * j2;
                int ci = kc16 + (k >> 2);
                int r = (k >> 1) & 1;
                const float* pp = &s_patch[(ci * 10 + (a_pr0 - r)) * 18];
                float v0 = pp[a_pc0];
                float v1 = pp[a_pc0 - 1];
                int idx = (am * 72 + k) >> 1;
                ah[idx] = pkbf2(v0, v1);
                al[idx] = pkbf2(bfres(v0), bfres(v1));
            }
        }
        {
            const __nv_bfloat16* bh = gB + ((size_t)(cl * 2 + 0) * 128) * K + kc * 64;
            const __nv_bfloat16* bl = gB + ((size_t)(cl * 2 + 1) * 128) * K + kc * 64;
            for (int e = tid; e < 1024; e += 512) {
                int co = e >> 3, k8 = (e & 7) * 8;
                uint4 vh = *(const uint4*)(bh + (size_t)co * K + k8);
                uint4 vl = *(const uint4*)(bl + (size_t)co * K + k8);
                *(uint4*)(smc + BH_B + (co * 72 + k8) * 2) = vh;
                *(uint4*)(smc + BL_B + (co * 72 + k8) * 2) = vl;
            }
        }
        __syncthreads();

        #pragma unroll
        for (int k16i = 0; k16i < 4; k16i++) {
            const int k16 = k16i * 16;
            uint32 a_h[2][4], a_l[2][4];
            #pragma unroll
            for (int i = 0; i < 2; i++) {
                int row = mg * 32 + i * 16 + (lane & 15);
                uint32 off = (uint32)((row * 72 + k16 + ((lane >> 4) << 3)) * 2);
                ldm_x4(a_h[i][0], a_h[i][1], a_h[i][2], a_h[i][3], sb + AH_B + off);
                ldm_x4(a_l[i][0], a_l[i][1], a_l[i][2], a_l[i][3], sb + AL_B + off);
            }
            uint32 b_h[4][2], b_l[4][2];
            #pragma unroll
            for (int j = 0; j < 4; j++) {
                int nrow = ng * 32 + j * 8 + (lane & 7);
                uint32 off = (uint32)((nrow * 72 + k16 + (((lane >> 3) & 1) << 3)) * 2);
                ldm_x2(b_h[j][0], b_h[j][1], sb + BH_B + off);
                ldm_x2(b_l[j][0], b_l[j][1], sb + BL_B + off);
            }
            #pragma unroll
            for (int i = 0; i < 2; i++)
            #pragma unroll
            for (int j = 0; j < 4; j++) {
                mma16816(c[i][j], a_h[i], b_h[j]);
                mma16816(c[i][j], a_h[i], b_l[j]);
                mma16816(c[i][j], a_l[i], b_h[j]);
            }
        }
    }

    #pragma unroll
    for (int i = 0; i < 2; i++) {
        int row0 = mg * 32 + i * 16 + (lane >> 2);
        #pragma unroll
        for (int rr = 0; rr < 2; rr++) {
            int row = row0 + rr * 8;
            int y_l = row >> 4, x_l = row & 15;
            int oh = 2 * (y0 + y_l) + dh, ow = 2 * (x0 + x_l) + dw;
            size_t ob = ((size_t)n * 128) * OH * OW + (size_t)oh * OW + ow;
            #pragma unroll
            for (int j = 0; j < 4; j++) {
                int col = ng * 32 + j * 8 + (lane & 3) * 2;
                float v0 = c[i][j][rr * 2 + 0] + bias[col];
                float v1 = c[i][j][rr * 2 + 1] + bias[col + 1];
                out[ob + (size_t)col * OH * OW] = fmaxf(v0, 0.f);
                out[ob + (size_t)(col + 1) * OH * OW] = fmaxf(v1, 0.f);
            }
        }
    }
}

// dec3 + recon-MSE partial (exact R10).
__global__ void __launch_bounds__(256) dec3_k(const float* __restrict__ in,
                                              const float* __restrict__ wtt,
                                              const float* __restrict__ bias,
                                              const float* __restrict__ x,
                                              float* __restrict__ out,
                                              float* __restrict__ rec_part)
{
    extern __shared__ float sm[];
    float* s_in = sm;
    float* s_w  = sm + 16 * 4 * 130;
    __shared__ float red[256];
    const int n = blockIdx.y, oh0 = blockIdx.x * 2;
    const int tid = threadIdx.x, r = tid >> 7, col = tid & 127, oh = oh0 + r;

    for (int t = tid; t < 128 * 9 * 3; t += 256)
        s_w[(t / 3) * 4 + t % 3] = wtt[t];

    float a0 = 0.f, a1 = 0.f, a2 = 0.f;
    for (int ci0 = 0; ci0 < 128; ci0 += 16) {
        for (int t = tid; t < 16 * 4 * 130; t += 256) {
            int cil = t / 520, r2 = t % 520, rr = r2 / 130, cc = r2 % 130;
            int ih = oh0 - 1 + rr, iw = cc - 1;
            float v = 0.f;
            if (ih >= 0 && ih < 128 && iw >= 0 && iw < 128)
                v = in[(((size_t)n * 128 + ci0 + cil) * 128 + ih) * 128 + iw];
            s_in[t] = v;
        }
        __syncthreads();
        for (int cil = 0; cil < 16; cil++) {
            #pragma unroll
            for (int kh = 0; kh < 3; kh++) {
                const float* rp = &s_in[(cil * 4 + r + kh) * 130 + col];
                #pragma unroll
                for (int kw = 0; kw < 3; kw++) {
                    float iv = rp[kw];
                    float4 wv = *(const float4*)&s_w[((ci0 + cil) * 9 + kh * 3 + kw) * 4];
                    a0 = fmaf(wv.x, iv, a0);
                    a1 = fmaf(wv.y, iv, a1);
                    a2 = fmaf(wv.z, iv, a2);
                }
            }
        }
        __syncthreads();
    }
    float lsum = 0.f;
    float accs[3] = {a0, a1, a2};
    #pragma unroll
    for (int co = 0; co < 3; co++) {
        float v = accs[co] + bias[co];
        size_t idx = (((size_t)n * 3 + co) * 128 + oh) * 128 + col;
        out[idx] = v;
        float d = v - x[idx];
        lsum = fmaf(d, d, lsum);
    }
    red[tid] = lsum;
    __syncthreads();
    for (int s = 128; s > 0; s >>= 1) {
        if (tid < s) red[tid] += red[tid + s];
        __syncthreads();
    }
    if (tid == 0) rec_part[(size_t)n * 64 + blockIdx.x] = red[0];
}

__global__ void __launch_bounds__(256) finalize_k(const float* __restrict__ rec_part,
                                                  const float* __restrict__ vq_part,
                                                  float* __restrict__ out)
{
    __shared__ double rA[256], rB[256];
    const int tid = threadIdx.x;
    double s = 0.0;
    for (int t = tid; t < 4096; t += 256) s += (double)rec_part[t];
    rA[tid] = s;
    rB[tid] = (double)vq_part[tid];
    __syncthreads();
    for (int st = 128; st > 0; st >>= 1) {
        if (tid < st) { rA[tid] += rA[tid + st]; rB[tid] += rB[tid + st]; }
        __syncthreads();
    }
    if (tid == 0) {
        double recon = rA[0] / 3145728.0;
        double vq    = 1.25 * rB[0] / 4194304.0;
        out[3145728] = (float)(recon + vq);
        out[3145729] = (float)recon;
        out[3145730] = (float)vq;
    }
}

extern "C" void kernel_launch(void* const* d_in, const int* in_sizes, int n_in,
                              void* d_out, int out_size)
{
    (void)in_sizes; (void)n_in; (void)out_size;
    const float* x   = (const float*)d_in[0];
    const float* ew1 = (const float*)d_in[1];
    const float* eb1 = (const float*)d_in[2];
    const float* ew2 = (const float*)d_in[3];
    const float* eb2 = (const float*)d_in[4];
    const float* ew3 = (const float*)d_in[5];
    const float* eb3 = (const float*)d_in[6];
    const float* cb  = (const float*)d_in[7];
    const float* dw1 = (const float*)d_in[8];
    const float* db1 = (const float*)d_in[9];
    const float* dw2 = (const float*)d_in[10];
    const float* db2 = (const float*)d_in[11];
    const float* dw3 = (const float*)d_in[12];
    const float* db3 = (const float*)d_in[13];
    float* out = (float*)d_out;

    void *h1, *h2, *ze, *zq, *dd1, *dd2, *vqp, *recp;
    void *w1t, *w2t, *w3t, *w3dt, *bw1, *bw2;
    cudaGetSymbolAddress(&h1,  g_h1);
    cudaGetSymbolAddress(&h2,  g_h2);
    cudaGetSymbolAddress(&ze,  g_ze);
    cudaGetSymbolAddress(&zq,  g_zq);
    cudaGetSymbolAddress(&dd1, g_d1);
    cudaGetSymbolAddress(&dd2, g_d2);
    cudaGetSymbolAddress(&vqp,  g_vq_part);
    cudaGetSymbolAddress(&recp, g_rec_part);
    cudaGetSymbolAddress(&w1t,  g_w1t);
    cudaGetSymbolAddress(&w2t,  g_w2t);
    cudaGetSymbolAddress(&w3t,  g_w3t);
    cudaGetSymbolAddress(&w3dt, g_w3dt);
    cudaGetSymbolAddress(&bw1,  g_bw1);
    cudaGetSymbolAddress(&bw2,  g_bw2);

    const int SM_E1 = (1028 + 3 * 64) * 4;
    const int SM_E2 = (128 * 18 * 19 + 64 * 128) * 4;
    const int SM_E3 = (128 * 10 * 11 + 128 * 64) * 4;
    const int SM_M1 = 64 * 180 * 4 + 4 * 18432;    // 119808
    const int SM_M2 = 128 * 180 * 4 + 4 * 18432;   // 165888
    const int SM_D3 = (8320 + 128 * 9 * 4) * 4;
    const int SM_VQ = (32768 + 512) * 4;

    cudaFuncSetAttribute((const void*)enc2_k,
                         cudaFuncAttributeMaxDynamicSharedMemorySize, SM_E2);
    cudaFuncSetAttribute((const void*)enc3_k,
                         cudaFuncAttributeMaxDynamicSharedMemorySize, SM_E3);
    cudaFuncSetAttribute((const void*)deconv_mma_k<64,32>,
                         cudaFuncAttributeMaxDynamicSharedMemorySize, SM_M1);
    cudaFuncSetAttribute((const void*)deconv_mma_k<128,64>,
                         cudaFuncAttributeMaxDynamicSharedMemorySize, SM_M2);
    cudaFuncSetAttribute((const void*)vq_k,
                         cudaFuncAttributeMaxDynamicSharedMemorySize, SM_VQ);
    cudaFuncSetAttribute((const void*)dec3_k,
                         cudaFuncAttributeMaxDynamicSharedMemorySize, SM_D3);

    wprep_k<<<256, 256>>>(ew1, ew2, ew3, dw1, dw2, dw3);
    conv_seq<4,2,3,128,128,true><<<dim3(64, 2, NB), 512, SM_E1>>>(
        x, (const float*)w1t, eb1, (float*)h1);
    enc2_k<<<dim3(16, 1, NB), 1024, SM_E2>>>(
        (const float*)h1, (const float*)w2t, eb2, (float*)h2);
    enc3_k<<<dim3(16, 1, NB), 512, SM_E3>>>(
        (const float*)h2, (const float*)w3t, eb3, (float*)ze);
    vq_k<<<256, 256, SM_VQ>>>(
        (const float*)ze, cb, (float*)zq, (float*)vqp);
    deconv_mma_k<64,32><<<dim3(8, 4, NB), 512, SM_M1>>>(
        (const float*)zq, (const __nv_bfloat16*)bw1, db1, (float*)dd1);
    deconv_mma_k<128,64><<<dim3(32, 4, NB), 512, SM_M2>>>(
        (const float*)dd1, (const __nv_bfloat16*)bw2, db2, (float*)dd2);
    dec3_k<<<dim3(64, NB), 256, SM_D3>>>(
        (const float*)dd2, (const float*)w3dt, db3, x, out, (float*)recp);
    finalize_k<<<1, 256>>>(
        (const float*)recp, (const float*)vqp, out);
}

// round 13
// speedup vs baseline: 1.0456x; 1.0409x over previous
#include <cuda_runtime.h>
#include <cuda_bf16.h>
#include <cstdint>
#include <cstddef>

#define NB 64
typedef unsigned long long ull;
typedef unsigned int uint32;

__device__ __forceinline__ ull pack2(float x) {
    ull d; unsigned u = __float_as_uint(x);
    asm("mov.b64 %0, {%1, %1};" : "=l"(d) : "r"(u));
    return d;
}
__device__ __forceinline__ ull fma2(ull a, ull b, ull c) {
    ull d;
    asm("fma.rn.f32x2 %0, %1, %2, %3;" : "=l"(d) : "l"(a), "l"(b), "l"(c));
    return d;
}
__device__ __forceinline__ void unpack2(ull a, float& lo, float& hi) {
    unsigned l, h;
    asm("mov.b64 {%0, %1}, %2;" : "=r"(l), "=r"(h) : "l"(a));
    lo = __uint_as_float(l); hi = __uint_as_float(h);
}
__device__ __forceinline__ uint32 smem_u32(const void* p) {
    uint32 a;
    asm("{ .reg .u64 t; cvta.to.shared.u64 t, %1; cvt.u32.u64 %0, t; }" : "=r"(a) : "l"(p));
    return a;
}
__device__ __forceinline__ void ldm_x4(uint32& r0, uint32& r1, uint32& r2, uint32& r3, uint32 a) {
    asm volatile("ldmatrix.sync.aligned.m8n8.x4.shared.b16 {%0,%1,%2,%3}, [%4];"
                 : "=r"(r0), "=r"(r1), "=r"(r2), "=r"(r3) : "r"(a));
}
__device__ __forceinline__ void ldm_x2(uint32& r0, uint32& r1, uint32 a) {
    asm volatile("ldmatrix.sync.aligned.m8n8.x2.shared.b16 {%0,%1}, [%2];"
                 : "=r"(r0), "=r"(r1) : "r"(a));
}
__device__ __forceinline__ void mma16816(float* c, const uint32* a, const uint32* b) {
    asm volatile(
        "mma.sync.aligned.m16n8k16.row.col.f32.bf16.bf16.f32 "
        "{%0,%1,%2,%3}, {%4,%5,%6,%7}, {%8,%9}, {%0,%1,%2,%3};"
        : "+f"(c[0]), "+f"(c[1]), "+f"(c[2]), "+f"(c[3])
        : "r"(a[0]), "r"(a[1]), "r"(a[2]), "r"(a[3]), "r"(b[0]), "r"(b[1]));
}
__device__ __forceinline__ uint32 pkbf2(float a, float b) {
    return (uint32)__bfloat16_as_ushort(__float2bfloat16(a))
         | ((uint32)__bfloat16_as_ushort(__float2bfloat16(b)) << 16);
}
__device__ __forceinline__ float bfres(float v) {
    return v - __bfloat162float(__float2bfloat16(v));
}

__device__ float g_h1[(size_t)NB * 128 * 64 * 64];
__device__ float g_h2[(size_t)NB * 128 * 32 * 32];
__device__ float g_ze[(size_t)NB * 64 * 32 * 32];
__device__ float g_zq[(size_t)NB * 64 * 32 * 32];
__device__ float g_d1[(size_t)NB * 128 * 64 * 64];
__device__ float g_d2[(size_t)NB * 128 * 128 * 128];
__device__ float g_vq_part[256];
__device__ float g_rec_part[4096];
__device__ float g_w1t[16 * 3 * 128];
__device__ float g_w2t[16 * 128 * 128];
__device__ float g_w3t[9 * 128 * 64];
__device__ float g_w3dt[128 * 9 * 3];
__device__ __align__(16) __nv_bfloat16 g_bw1[4 * 2 * 128 * 256];  // [cl][h][co][K]
__device__ __align__(16) __nv_bfloat16 g_bw2[4 * 2 * 128 * 512];  // [cl][h][co][K]

__global__ void wprep_k(const float* __restrict__ w1, const float* __restrict__ w2,
                        const float* __restrict__ w3, const float* __restrict__ dw1,
                        const float* __restrict__ dw2, const float* __restrict__ dw3)
{
    int st = gridDim.x * blockDim.x, g = blockIdx.x * blockDim.x + threadIdx.x;
    for (int t = g; t < 16 * 3 * 128; t += st) {
        int co = t & 127, r = t >> 7, ci = r % 3, kk = r / 3;
        g_w1t[(kk * 3 + ci) * 128 + co] = w1[((size_t)co * 3 + ci) * 16 + kk];
    }
    for (int t = g; t < 16 * 128 * 128; t += st) {
        int co = t & 127, r = t >> 7, ci = r & 127, kk = r >> 7;
        g_w2t[(kk * 128 + ci) * 128 + co] = w2[((size_t)co * 128 + ci) * 16 + kk];
    }
    for (int t = g; t < 9 * 128 * 64; t += st) {
        int co = t & 63, r = t >> 6, ci = r & 127, kk = r >> 7;
        g_w3t[(kk * 128 + ci) * 64 + co] = w3[((size_t)co * 128 + ci) * 9 + kk];
    }
    for (int t = g; t < 128 * 9 * 3; t += st) {
        int co = t % 3, r = t / 3, kk = r % 9, ci = r / 9;
        g_w3dt[t] = dw3[((size_t)co * 128 + ci) * 9 + kk];
    }
    for (int t = g; t < 4 * 2 * 128 * 256; t += st) {
        int k = t & 255, r2 = t >> 8, co = r2 & 127, h = (r2 >> 7) & 1, cl = r2 >> 8;
        int ci = k >> 2, rr = (k >> 1) & 1, cc = k & 1;
        int dh = cl >> 1, dw = cl & 1;
        float w = dw1[((size_t)ci * 128 + co) * 16 + (1 - dh + 2 * rr) * 4 + (1 - dw + 2 * cc)];
        g_bw1[t] = __float2bfloat16(h ? bfres(w) : w);
    }
    for (int t = g; t < 4 * 2 * 128 * 512; t += st) {
        int k = t & 511, r2 = t >> 9, co = r2 & 127, h = (r2 >> 7) & 1, cl = r2 >> 8;
        int ci = k >> 2, rr = (k >> 1) & 1, cc = k & 1;
        int dh = cl >> 1, dw = cl & 1;
        float w = dw2[((size_t)ci * 128 + co) * 16 + (1 - dh + 2 * rr) * 4 + (1 - dw + 2 * cc)];
        g_bw2[t] = __float2bfloat16(h ? bfres(w) : w);
    }
}

// enc1: bit-exact scalar chain; all weights resident, single sync.
template <int K, int S, int CIN, int COUT, int H, bool RELU>
__global__ void __launch_bounds__(512) conv_seq(const float* __restrict__ in,
                                                const float* __restrict__ wt,
                                                const float* __restrict__ bias,
                                                float* __restrict__ out)
{
    constexpr int W = H, OH = (H + 2 - K) / S + 1, OW = OH;
    constexpr int IHS = 7 * S + K, IWS = 7 * S + K, IWP = IWS + 1;
    constexpr int SW_OFF = ((CIN * IHS * IWP + 3) / 4) * 4;
    constexpr int WN = K * K * CIN * 64;
    extern __shared__ float sm[];
    float* s_in = sm;
    float* s_w  = sm + SW_OFF;
    const int n = blockIdx.z, co0 = blockIdx.y * 64;
    constexpr int TWn = OW / 8;
    const int oh0 = (blockIdx.x / TWn) * 8, ow0 = (blockIdx.x % TWn) * 8;
    const int tid = threadIdx.x, px = tid & 63, cog = tid >> 6;
    const int ohr = px >> 3, owr = px & 7;
    const int ihb = oh0 * S - 1, iwb = ow0 * S - 1;

    for (int t = tid; t < CIN * IHS * IWS; t += 512) {
        int ci = t / (IHS * IWS), r = t % (IHS * IWS), rr = r / IWS, cc = r % IWS;
        int ih = ihb + rr, iw = iwb + cc;
        float v = 0.f;
        if (ih >= 0 && ih < H && iw >= 0 && iw < W)
            v = in[(((size_t)n * CIN + ci) * H + ih) * W + iw];
        s_in[(ci * IHS + rr) * IWP + cc] = v;
    }
    for (int t = tid; t < WN; t += 512)
        s_w[t] = wt[(size_t)(t >> 6) * COUT + co0 + (t & 63)];
    __syncthreads();

    const int cob = co0 + cog * 8;
    float a[8];
    #pragma unroll
    for (int i = 0; i < 8; i++) a[i] = 0.f;
    #pragma unroll
    for (int kh = 0; kh < K; kh++)
    #pragma unroll
    for (int kw = 0; kw < K; kw++) {
        const float* ip = &s_in[(ohr * S + kh) * IWP + owr * S + kw];
        const float* wp = &s_w[((kh * K + kw) * CIN) * 64 + cog * 8];
        #pragma unroll 3
        for (int ci = 0; ci < CIN; ci++) {
            float iv = ip[ci * IHS * IWP];
            float4 w0 = *(const float4*)&wp[ci * 64];
            float4 w1 = *(const float4*)&wp[ci * 64 + 4];
            a[0] = __fmaf_rn(iv, w0.x, a[0]);
            a[1] = __fmaf_rn(iv, w0.y, a[1]);
            a[2] = __fmaf_rn(iv, w0.z, a[2]);
            a[3] = __fmaf_rn(iv, w0.w, a[3]);
            a[4] = __fmaf_rn(iv, w1.x, a[4]);
            a[5] = __fmaf_rn(iv, w1.y, a[5]);
            a[6] = __fmaf_rn(iv, w1.z, a[6]);
            a[7] = __fmaf_rn(iv, w1.w, a[7]);
        }
    }
    const int oh = oh0 + ohr, ow = ow0 + owr;
    #pragma unroll
    for (int c = 0; c < 8; c++) {
        float v = __fadd_rn(a[c], bias[cob + c]);
        if (RELU) v = fmaxf(v, 0.f);
        out[(((size_t)n * COUT + cob + c) * OH + oh) * OW + ow] = v;
    }
}

// enc2 (exact R10/R6).
__global__ void __launch_bounds__(512) enc2_k(const float* __restrict__ in,
                                              const float* __restrict__ wt,
                                              const float* __restrict__ bias,
                                              float* __restrict__ out)
{
    extern __shared__ float sm[];
    float* s_in = sm;
    float* s_w  = sm + 128 * 18 * 19;
    const int n = blockIdx.z;
    const int oh0 = (blockIdx.x >> 2) * 8, ow0 = (blockIdx.x & 3) * 8;
    const int tid = threadIdx.x, px = tid & 31, cog = tid >> 5;
    const int ohr = px >> 2, owp = px & 3;
    const int ihb = oh0 * 2 - 1, iwb = ow0 * 2 - 1;

    for (int t = tid; t < 128 * 18 * 18; t += 512) {
        int ci = t / 324, r = t % 324, rr = r / 18, cc = r % 18;
        int ih = ihb + rr, iw = iwb + cc;
        float v = 0.f;
        if (ih >= 0 && ih < 64 && iw >= 0 && iw < 64)
            v = in[(((size_t)n * 128 + ci) * 64 + ih) * 64 + iw];
        s_in[(ci * 18 + rr) * 19 + cc] = v;
    }

    ull a[2][4];
    #pragma unroll
    for (int p = 0; p < 2; p++)
    #pragma unroll
    for (int j = 0; j < 4; j++) a[p][j] = 0ull;

    #pragma unroll
    for (int kh = 0; kh < 4; kh++)
    #pragma unroll
    for (int kw = 0; kw < 4; kw++) {
        for (int ci0 = 0; ci0 < 128; ci0 += 64) {
            __syncthreads();
            for (int t = tid; t < 64 * 128; t += 512)
                s_w[t] = wt[(size_t)((kh * 4 + kw) * 128 + ci0 + (t >> 7)) * 128 + (t & 127)];
            __syncthreads();
            const float* ip = &s_in[((ci0 * 18) + ohr * 2 + kh) * 19 + owp * 4 + kw];
            const float* wp = &s_w[cog * 8];
            #pragma unroll 2
            for (int ci = 0; ci < 64; ci++) {
                float i0 = ip[ci * 342];
                float i1 = ip[ci * 342 + 2];
                ull p0 = pack2(i0), p1 = pack2(i1);
                ulonglong2 wA = *(const ulonglong2*)&wp[ci * 128];
                ulonglong2 wB = *(const ulonglong2*)&wp[ci * 128 + 4];
                a[0][0] = fma2(p0, wA.x, a[0][0]);
                a[0][1] = fma2(p0, wA.y, a[0][1]);
                a[0][2] = fma2(p0, wB.x, a[0][2]);
                a[0][3] = fma2(p0, wB.y, a[0][3]);
                a[1][0] = fma2(p1, wA.x, a[1][0]);
                a[1][1] = fma2(p1, wA.y, a[1][1]);
                a[1][2] = fma2(p1, wB.x, a[1][2]);
                a[1][3] = fma2(p1, wB.y, a[1][3]);
            }
        }
    }
    const int oh = oh0 + ohr;
    #pragma unroll
    for (int p = 0; p < 2; p++) {
        int ow = ow0 + owp * 2 + p;
        #pragma unroll
        for (int j = 0; j < 4; j++) {
            int co = cog * 8 + 2 * j;
            float lo, hi;
            unpack2(a[p][j], lo, hi);
            out[(((size_t)n * 128 + co) * 32 + oh) * 32 + ow] =
                fmaxf(__fadd_rn(lo, bias[co]), 0.f);
            out[(((size_t)n * 128 + co + 1) * 32 + oh) * 32 + ow] =
                fmaxf(__fadd_rn(hi, bias[co + 1]), 0.f);
        }
    }
}

// enc3 (exact R10/R6).
__global__ void __launch_bounds__(256) enc3_k(const float* __restrict__ in,
                                              const float* __restrict__ wt,
                                              const float* __restrict__ bias,
                                              float* __restrict__ out)
{
    extern __shared__ float sm[];
    float* s_in = sm;
    float* s_w  = sm + 128 * 10 * 11;
    const int n = blockIdx.z;
    const int oh0 = (blockIdx.x >> 2) * 8, ow0 = (blockIdx.x & 3) * 8;
    const int tid = threadIdx.x, px = tid & 31, cog = tid >> 5;
    const int ohr = px >> 2, owp = px & 3;
    const int ihb = oh0 - 1, iwb = ow0 - 1;

    for (int t = tid; t < 128 * 10 * 10; t += 256) {
        int ci = t / 100, r = t % 100, rr = r / 10, cc = r % 10;
        int ih = ihb + rr, iw = iwb + cc;
        float v = 0.f;
        if (ih >= 0 && ih < 32 && iw >= 0 && iw < 32)
            v = in[(((size_t)n * 128 + ci) * 32 + ih) * 32 + iw];
        s_in[(ci * 10 + rr) * 11 + cc] = v;
    }

    ull a[2][4];
    #pragma unroll
    for (int p = 0; p < 2; p++)
    #pragma unroll
    for (int j = 0; j < 4; j++) a[p][j] = 0ull;

    #pragma unroll
    for (int kh = 0; kh < 3; kh++)
    #pragma unroll
    for (int kw = 0; kw < 3; kw++) {
        __syncthreads();
        for (int t = tid; t < 128 * 64; t += 256)
            s_w[t] = wt[(size_t)((kh * 3 + kw) * 128 + (t >> 6)) * 64 + (t & 63)];
        __syncthreads();
        const float* ip = &s_in[(ohr + kh) * 11 + owp * 2 + kw];
        const float* wp = &s_w[cog * 8];
        #pragma unroll 2
        for (int ci = 0; ci < 128; ci++) {
            float i0 = ip[ci * 110];
            float i1 = ip[ci * 110 + 1];
            ull p0 = pack2(i0), p1 = pack2(i1);
            ulonglong2 wA = *(const ulonglong2*)&wp[ci * 64];
            ulonglong2 wB = *(const ulonglong2*)&wp[ci * 64 + 4];
            a[0][0] = fma2(p0, wA.x, a[0][0]);
            a[0][1] = fma2(p0, wA.y, a[0][1]);
            a[0][2] = fma2(p0, wB.x, a[0][2]);
            a[0][3] = fma2(p0, wB.y, a[0][3]);
            a[1][0] = fma2(p1, wA.x, a[1][0]);
            a[1][1] = fma2(p1, wA.y, a[1][1]);
            a[1][2] = fma2(p1, wB.x, a[1][2]);
            a[1][3] = fma2(p1, wB.y, a[1][3]);
        }
    }
    const int oh = oh0 + ohr;
    #pragma unroll
    for (int p = 0; p < 2; p++) {
        int ow = ow0 + owp * 2 + p;
        #pragma unroll
        for (int j = 0; j < 4; j++) {
            int co = cog * 8 + 2 * j;
            float lo, hi;
            unpack2(a[p][j], lo, hi);
            out[(((size_t)n * 64 + co) * 32 + oh) * 32 + ow] = __fadd_rn(lo, bias[co]);
            out[(((size_t)n * 64 + co + 1) * 32 + oh) * 32 + ow] = __fadd_rn(hi, bias[co + 1]);
        }
    }
}

// VQ (unchanged bit-exact numerics).
__global__ void __launch_bounds__(256) vq_k(const float* __restrict__ ze,
                                            const float* __restrict__ cb,
                                            float* __restrict__ zq,
                                            float* __restrict__ part)
{
    extern __shared__ float sm[];
    float* s_cb  = sm;
    float* s_cb2 = sm + 32768;
    __shared__ float red[256];
    const int tid = threadIdx.x;
    for (int t = tid; t < 32768; t += 256) s_cb[t] = cb[t];
    __syncthreads();
    for (int k = tid; k < 512; k += 256) {
        float s = 0.f;
        for (int d = 0; d < 64; d++) {
            float c = s_cb[k * 64 + d];
            s = __fadd_rn(s, __fmul_rn(c, c));
        }
        s_cb2[k] = s;
    }
    __syncthreads();

    const int v = blockIdx.x * 256 + tid;
    const int n = v >> 10, hw = v & 1023;
    const float* zp = ze + (size_t)n * 64 * 1024 + hw;
    float z[64];
    #pragma unroll
    for (int d = 0; d < 64; d++) z[d] = zp[(size_t)d * 1024];

    float z2 = 0.f;
    #pragma unroll
    for (int d = 0; d < 64; d++) z2 = __fadd_rn(z2, __fmul_rn(z[d], z[d]));

    float best = 3.4e38f;
    int bi = 0;
    for (int k0 = 0; k0 < 512; k0 += 4) {
        float dt0 = 0.f, dt1 = 0.f, dt2 = 0.f, dt3 = 0.f;
        const float* c0 = &s_cb[(k0 + 0) * 64];
        const float* c1 = &s_cb[(k0 + 1) * 64];
        const float* c2 = &s_cb[(k0 + 2) * 64];
        const float* c3 = &s_cb[(k0 + 3) * 64];
        #pragma unroll
        for (int d = 0; d < 64; d++) {
            float zd = z[d];
            dt0 = __fmaf_rn(zd, c0[d], dt0);
            dt1 = __fmaf_rn(zd, c1[d], dt1);
            dt2 = __fmaf_rn(zd, c2[d], dt2);
            dt3 = __fmaf_rn(zd, c3[d], dt3);
        }
        float s0 = __fsub_rn(__fadd_rn(z2, s_cb2[k0 + 0]), __fmul_rn(2.f, dt0));
        float s1 = __fsub_rn(__fadd_rn(z2, s_cb2[k0 + 1]), __fmul_rn(2.f, dt1));
        float s2 = __fsub_rn(__fadd_rn(z2, s_cb2[k0 + 2]), __fmul_rn(2.f, dt2));
        float s3 = __fsub_rn(__fadd_rn(z2, s_cb2[k0 + 3]), __fmul_rn(2.f, dt3));
        if (s0 < best) { best = s0; bi = k0; }
        if (s1 < best) { best = s1; bi = k0 + 1; }
        if (s2 < best) { best = s2; bi = k0 + 2; }
        if (s3 < best) { best = s3; bi = k0 + 3; }
    }

    float* zqp = zq + (size_t)n * 64 * 1024 + hw;
    float lsum = 0.f;
    #pragma unroll
    for (int d = 0; d < 64; d++) {
        float c = s_cb[bi * 64 + d];
        float df = z[d] - c;
        lsum = fmaf(df, df, lsum);
        zqp[(size_t)d * 1024] = __fadd_rn(z[d], __fsub_rn(c, z[d]));
    }
    red[tid] = lsum;
    __syncthreads();
    for (int s = 128; s > 0; s >>= 1) {
        if (tid < s) red[tid] += red[tid + s];
        __syncthreads();
    }
    if (tid == 0) part[blockIdx.x] = red[0];
}

// Deconv via mma.sync bf16 (exact R10: 256 thr / 8 warps, direct stores).
template <int CIN, int IHW>
__global__ void __launch_bounds__(256) deconv_mma_k(
    const float* __restrict__ in, const __nv_bfloat16* __restrict__ gB,
    const float* __restrict__ bias, float* __restrict__ out)
{
    constexpr int K = CIN * 4;
    constexpr int NCH = K / 64;
    constexpr int OH = IHW * 2, OW = IHW * 2;
    constexpr int TX = IHW / 16;
    constexpr int PATCH_B = CIN * 180 * 4;
    constexpr int AH_B = PATCH_B, AL_B = AH_B + 18432;
    constexpr int BH_B = AL_B + 18432, BL_B = BH_B + 18432;

    extern __shared__ char smc[];
    float* s_patch = (float*)smc;
    const uint32 sb = smem_u32(smc);

    const int tid = threadIdx.x;
    const int lane = tid & 31, wrp = tid >> 5;
    const int mg = wrp & 3, ng = wrp >> 2;
    const int n = blockIdx.z, cl = blockIdx.y;
    const int dh = cl >> 1, dw = cl & 1;
    const int y0 = (blockIdx.x / TX) * 8, x0 = (blockIdx.x % TX) * 16;

    for (int t = tid; t < CIN * 180; t += 256) {
        int ci = t / 180, r = t % 180, rr = r / 18, cc = r % 18;
        int yy = y0 - 1 + rr, xx = x0 - 1 + cc;
        float v = 0.f;
        if (yy >= 0 && yy < IHW && xx >= 0 && xx < IHW)
            v = in[(((size_t)n * CIN + ci) * IHW + yy) * IHW + xx];
        s_patch[t] = v;
    }

    float c[2][8][4];
    #pragma unroll
    for (int i = 0; i < 2; i++)
    #pragma unroll
    for (int j = 0; j < 8; j++)
    #pragma unroll
    for (int q = 0; q < 4; q++) c[i][j][q] = 0.f;

    const int am = tid >> 1, aks = (tid & 1) * 32;
    const int a_yl = am >> 4, a_xl = am & 15;
    const int a_pr0 = a_yl + dh + 1, a_pc0 = a_xl + dw + 1;

    for (int kc = 0; kc < NCH; kc++) {
        __syncthreads();
        {
            uint32* ah = (uint32*)(smc + AH_B);
            uint32* al = (uint32*)(smc + AL_B);
            const int kc16 = kc * 16;
            #pragma unroll 4
            for (int j2 = 0; j2 < 16; j2++) {
                int k = aks + 2 * j2;
                int ci = kc16 + (k >> 2);
                int r = (k >> 1) & 1;
                const float* pp = &s_patch[(ci * 10 + (a_pr0 - r)) * 18];
                float v0 = pp[a_pc0];
                float v1 = pp[a_pc0 - 1];
                int idx = (am * 72 + k) >> 1;
                ah[idx] = pkbf2(v0, v1);
                al[idx] = pkbf2(bfres(v0), bfres(v1));
            }
        }
        {
            const __nv_bfloat16* bh = gB + ((size_t)(cl * 2 + 0) * 128) * K + kc * 64;
            const __nv_bfloat16* bl = gB + ((size_t)(cl * 2 + 1) * 128) * K + kc * 64;
            for (int e = tid; e < 1024; e += 256) {
                int co = e >> 3, k8 = (e & 7) * 8;
                uint4 vh = *(const uint4*)(bh + (size_t)co * K + k8);
                uint4 vl = *(const uint4*)(bl + (size_t)co * K + k8);
                *(uint4*)(smc + BH_B + (co * 72 + k8) * 2) = vh;
                *(uint4*)(smc + BL_B + (co * 72 + k8) * 2) = vl;
            }
        }
        __syncthreads();

        #pragma unroll
        for (int k16i = 0; k16i < 4; k16i++) {
            const int k16 = k16i * 16;
            uint32 a_h[2][4], a_l[2][4];
            #pragma unroll
            for (int i = 0; i < 2; i++) {
                int row = mg * 32 + i * 16 + (lane & 15);
                uint32 off = (uint32)((row * 72 + k16 + ((lane >> 4) << 3)) * 2);
                ldm_x4(a_h[i][0], a_h[i][1], a_h[i][2], a_h[i][3], sb + AH_B + off);
                ldm_x4(a_l[i][0], a_l[i][1], a_l[i][2], a_l[i][3], sb + AL_B + off);
            }
            uint32 b_h[8][2], b_l[8][2];
            #pragma unroll
            for (int j = 0; j < 8; j++) {
                int nrow = ng * 64 + j * 8 + (lane & 7);
                uint32 off = (uint32)((nrow * 72 + k16 + (((lane >> 3) & 1) << 3)) * 2);
                ldm_x2(b_h[j][0], b_h[j][1], sb + BH_B + off);
                ldm_x2(b_l[j][0], b_l[j][1], sb + BL_B + off);
            }
            #pragma unroll
            for (int i = 0; i < 2; i++)
            #pragma unroll
            for (int j = 0; j < 8; j++) {
                mma16816(c[i][j], a_h[i], b_h[j]);
                mma16816(c[i][j], a_h[i], b_l[j]);
                mma16816(c[i][j], a_l[i], b_h[j]);
            }
        }
    }

    #pragma unroll
    for (int i = 0; i < 2; i++) {
        int row0 = mg * 32 + i * 16 + (lane >> 2);
        #pragma unroll
        for (int rr = 0; rr < 2; rr++) {
            int row = row0 + rr * 8;
            int y_l = row >> 4, x_l = row & 15;
            int oh = 2 * (y0 + y_l) + dh, ow = 2 * (x0 + x_l) + dw;
            size_t ob = ((size_t)n * 128) * OH * OW + (size_t)oh * OW + ow;
            #pragma unroll
            for (int j = 0; j < 8; j++) {
                int col = ng * 64 + j * 8 + (lane & 3) * 2;
                float v0 = c[i][j][rr * 2 + 0] + bias[col];
                float v1 = c[i][j][rr * 2 + 1] + bias[col + 1];
                out[ob + (size_t)col * OH * OW] = fmaxf(v0, 0.f);
                out[ob + (size_t)(col + 1) * OH * OW] = fmaxf(v1, 0.f);
            }
        }
    }
}

// dec3: 2 output rows per thread (4-row tile), fused recon-MSE partial.
// Per-output FMA chain identical to R10 (ci0 -> cil -> kh -> kw).
__global__ void __launch_bounds__(256) dec3_k(const float* __restrict__ in,
                                              const float* __restrict__ wtt,
                                              const float* __restrict__ bias,
                                              const float* __restrict__ x,
                                              float* __restrict__ out,
                                              float* __restrict__ rec_part)
{
    extern __shared__ float sm[];
    float* s_in = sm;                    // [16][6][130]
    float* s_w  = sm + 16 * 6 * 130;     // [128*9][4]
    __shared__ float red[256];
    const int n = blockIdx.y, oh0 = blockIdx.x * 4;
    const int tid = threadIdx.x, rg = tid >> 7, col = tid & 127;

    for (int t = tid; t < 128 * 9 * 3; t += 256)
        s_w[(t / 3) * 4 + t % 3] = wtt[t];

    float a[2][3];
    #pragma unroll
    for (int p = 0; p < 2; p++)
    #pragma unroll
    for (int co = 0; co < 3; co++) a[p][co] = 0.f;

    for (int ci0 = 0; ci0 < 128; ci0 += 16) {
        for (int t = tid; t < 16 * 6 * 130; t += 256) {
            int cil = t / 780, r2 = t % 780, rr = r2 / 130, cc = r2 % 130;
            int ih = oh0 - 1 + rr, iw = cc - 1;
            float v = 0.f;
            if (ih >= 0 && ih < 128 && iw >= 0 && iw < 128)
                v = in[(((size_t)n * 128 + ci0 + cil) * 128 + ih) * 128 + iw];
            s_in[t] = v;
        }
        __syncthreads();
        for (int cil = 0; cil < 16; cil++) {
            float riv[4][3];
            const float* bp = &s_in[(cil * 6 + 2 * rg) * 130 + col];
            #pragma unroll
            for (int dr = 0; dr < 4; dr++)
            #pragma unroll
            for (int kw = 0; kw < 3; kw++) riv[dr][kw] = bp[dr * 130 + kw];
            #pragma unroll
            for (int kh = 0; kh < 3; kh++) {
                #pragma unroll
                for (int kw = 0; kw < 3; kw++) {
                    float4 wv = *(const float4*)&s_w[((ci0 + cil) * 9 + kh * 3 + kw) * 4];
                    float iv0 = riv[kh][kw];
                    float iv1 = riv[kh + 1][kw];
                    a[0][0] = fmaf(wv.x, iv0, a[0][0]);
                    a[0][1] = fmaf(wv.y, iv0, a[0][1]);
                    a[0][2] = fmaf(wv.z, iv0, a[0][2]);
                    a[1][0] = fmaf(wv.x, iv1, a[1][0]);
                    a[1][1] = fmaf(wv.y, iv1, a[1][1]);
                    a[1][2] = fmaf(wv.z, iv1, a[1][2]);
                }
            }
        }
        __syncthreads();
    }
    float lsum = 0.f;
    #pragma unroll
    for (int p = 0; p < 2; p++) {
        int oh = oh0 + 2 * rg + p;
        #pragma unroll
        for (int co = 0; co < 3; co++) {
            float v = a[p][co] + bias[co];
            size_t idx = (((size_t)n * 3 + co) * 128 + oh) * 128 + col;
            out[idx] = v;
            float d = v - x[idx];
            lsum = fmaf(d, d, lsum);
        }
    }
    red[tid] = lsum;
    __syncthreads();
    for (int s = 128; s > 0; s >>= 1) {
        if (tid < s) red[tid] += red[tid + s];
        __syncthreads();
    }
    if (tid == 0) rec_part[(size_t)n * 32 + blockIdx.x] = red[0];
}

__global__ void __launch_bounds__(256) finalize_k(const float* __restrict__ rec_part,
                                                  const float* __restrict__ vq_part,
                                                  float* __restrict__ out)
{
    __shared__ double rA[256], rB[256];
    const int tid = threadIdx.x;
    double s = 0.0;
    for (int t = tid; t < 2048; t += 256) s += (double)rec_part[t];
    rA[tid] = s;
    rB[tid] = (double)vq_part[tid];
    __syncthreads();
    for (int st = 128; st > 0; st >>= 1) {
        if (tid < st) { rA[tid] += rA[tid + st]; rB[tid] += rB[tid + st]; }
        __syncthreads();
    }
    if (tid == 0) {
        double recon = rA[0] / 3145728.0;
        double vq    = 1.25 * rB[0] / 4194304.0;
        out[3145728] = (float)(recon + vq);
        out[3145729] = (float)recon;
        out[3145730] = (float)vq;
    }
}

extern "C" void kernel_launch(void* const* d_in, const int* in_sizes, int n_in,
                              void* d_out, int out_size)
{
    (void)in_sizes; (void)n_in; (void)out_size;
    const float* x   = (const float*)d_in[0];
    const float* ew1 = (const float*)d_in[1];
    const float* eb1 = (const float*)d_in[2];
    const float* ew2 = (const float*)d_in[3];
    const float* eb2 = (const float*)d_in[4];
    const float* ew3 = (const float*)d_in[5];
    const float* eb3 = (const float*)d_in[6];
    const float* cb  = (const float*)d_in[7];
    const float* dw1 = (const float*)d_in[8];
    const float* db1 = (const float*)d_in[9];
    const float* dw2 = (const float*)d_in[10];
    const float* db2 = (const float*)d_in[11];
    const float* dw3 = (const float*)d_in[12];
    const float* db3 = (const float*)d_in[13];
    float* out = (float*)d_out;

    void *h1, *h2, *ze, *zq, *dd1, *dd2, *vqp, *recp;
    void *w1t, *w2t, *w3t, *w3dt, *bw1, *bw2;
    cudaGetSymbolAddress(&h1,  g_h1);
    cudaGetSymbolAddress(&h2,  g_h2);
    cudaGetSymbolAddress(&ze,  g_ze);
    cudaGetSymbolAddress(&zq,  g_zq);
    cudaGetSymbolAddress(&dd1, g_d1);
    cudaGetSymbolAddress(&dd2, g_d2);
    cudaGetSymbolAddress(&vqp,  g_vq_part);
    cudaGetSymbolAddress(&recp, g_rec_part);
    cudaGetSymbolAddress(&w1t,  g_w1t);
    cudaGetSymbolAddress(&w2t,  g_w2t);
    cudaGetSymbolAddress(&w3t,  g_w3t);
    cudaGetSymbolAddress(&w3dt, g_w3dt);
    cudaGetSymbolAddress(&bw1,  g_bw1);
    cudaGetSymbolAddress(&bw2,  g_bw2);

    const int SM_E1 = (1028 + 16 * 3 * 64) * 4;            // 16400
    const int SM_E2 = (128 * 18 * 19 + 64 * 128) * 4;
    const int SM_E3 = (128 * 10 * 11 + 128 * 64) * 4;
    const int SM_M1 = 64 * 180 * 4 + 4 * 18432;            // 119808
    const int SM_M2 = 128 * 180 * 4 + 4 * 18432;           // 165888
    const int SM_D3 = (16 * 6 * 130 + 128 * 9 * 4) * 4;    // 68352
    const int SM_VQ = (32768 + 512) * 4;

    cudaFuncSetAttribute((const void*)enc2_k,
                         cudaFuncAttributeMaxDynamicSharedMemorySize, SM_E2);
    cudaFuncSetAttribute((const void*)enc3_k,
                         cudaFuncAttributeMaxDynamicSharedMemorySize, SM_E3);
    cudaFuncSetAttribute((const void*)deconv_mma_k<64,32>,
                         cudaFuncAttributeMaxDynamicSharedMemorySize, SM_M1);
    cudaFuncSetAttribute((const void*)deconv_mma_k<128,64>,
                         cudaFuncAttributeMaxDynamicSharedMemorySize, SM_M2);
    cudaFuncSetAttribute((const void*)vq_k,
                         cudaFuncAttributeMaxDynamicSharedMemorySize, SM_VQ);
    cudaFuncSetAttribute((const void*)dec3_k,
                         cudaFuncAttributeMaxDynamicSharedMemorySize, SM_D3);

    wprep_k<<<256, 256>>>(ew1, ew2, ew3, dw1, dw2, dw3);
    conv_seq<4,2,3,128,128,true><<<dim3(64, 2, NB), 512, SM_E1>>>(
        x, (const float*)w1t, eb1, (float*)h1);
    enc2_k<<<dim3(16, 1, NB), 512, SM_E2>>>(
        (const float*)h1, (const float*)w2t, eb2, (float*)h2);
    enc3_k<<<dim3(16, 1, NB), 256, SM_E3>>>(
        (const float*)h2, (const float*)w3t, eb3, (float*)ze);
    vq_k<<<256, 256, SM_VQ>>>(
        (const float*)ze, cb, (float*)zq, (float*)vqp);
    deconv_mma_k<64,32><<<dim3(8, 4, NB), 256, SM_M1>>>(
        (const float*)zq, (const __nv_bfloat16*)bw1, db1, (float*)dd1);
    deconv_mma_k<128,64><<<dim3(32, 4, NB), 256, SM_M2>>>(
        (const float*)dd1, (const __nv_bfloat16*)bw2, db2, (float*)dd2);
    dec3_k<<<dim3(32, NB), 256, SM_D3>>>(
        (const float*)dd2, (const float*)w3dt, db3, x, out, (float*)recp);
    finalize_k<<<1, 256>>>(
        (const float*)recp, (const float*)vqp, out);
}

// round 14
// speedup vs baseline: 1.0565x; 1.0105x over previous
#include <cuda_runtime.h>
#include <cuda_bf16.h>
#include <cstdint>
#include <cstddef>

#define NB 64
typedef unsigned long long ull;
typedef unsigned int uint32;

__device__ __forceinline__ ull pack2(float x) {
    ull d; unsigned u = __float_as_uint(x);
    asm("mov.b64 %0, {%1, %1};" : "=l"(d) : "r"(u));
    return d;
}
__device__ __forceinline__ ull fma2(ull a, ull b, ull c) {
    ull d;
    asm("fma.rn.f32x2 %0, %1, %2, %3;" : "=l"(d) : "l"(a), "l"(b), "l"(c));
    return d;
}
__device__ __forceinline__ void unpack2(ull a, float& lo, float& hi) {
    unsigned l, h;
    asm("mov.b64 {%0, %1}, %2;" : "=r"(l), "=r"(h) : "l"(a));
    lo = __uint_as_float(l); hi = __uint_as_float(h);
}
__device__ __forceinline__ uint32 smem_u32(const void* p) {
    uint32 a;
    asm("{ .reg .u64 t; cvta.to.shared.u64 t, %1; cvt.u32.u64 %0, t; }" : "=r"(a) : "l"(p));
    return a;
}
__device__ __forceinline__ void ldm_x4(uint32& r0, uint32& r1, uint32& r2, uint32& r3, uint32 a) {
    asm volatile("ldmatrix.sync.aligned.m8n8.x4.shared.b16 {%0,%1,%2,%3}, [%4];"
                 : "=r"(r0), "=r"(r1), "=r"(r2), "=r"(r3) : "r"(a));
}
__device__ __forceinline__ void ldm_x2(uint32& r0, uint32& r1, uint32 a) {
    asm volatile("ldmatrix.sync.aligned.m8n8.x2.shared.b16 {%0,%1}, [%2];"
                 : "=r"(r0), "=r"(r1) : "r"(a));
}
__device__ __forceinline__ void mma16816(float* c, const uint32* a, const uint32* b) {
    asm volatile(
        "mma.sync.aligned.m16n8k16.row.col.f32.bf16.bf16.f32 "
        "{%0,%1,%2,%3}, {%4,%5,%6,%7}, {%8,%9}, {%0,%1,%2,%3};"
        : "+f"(c[0]), "+f"(c[1]), "+f"(c[2]), "+f"(c[3])
        : "r"(a[0]), "r"(a[1]), "r"(a[2]), "r"(a[3]), "r"(b[0]), "r"(b[1]));
}
__device__ __forceinline__ uint32 pkbf2(float a, float b) {
    return (uint32)__bfloat16_as_ushort(__float2bfloat16(a))
         | ((uint32)__bfloat16_as_ushort(__float2bfloat16(b)) << 16);
}
__device__ __forceinline__ float bfres(float v) {
    return v - __bfloat162float(__float2bfloat16(v));
}

__device__ float g_h1[(size_t)NB * 128 * 64 * 64];
__device__ float g_h2[(size_t)NB * 128 * 32 * 32];
__device__ float g_ze[(size_t)NB * 64 * 32 * 32];
__device__ float g_zq[(size_t)NB * 64 * 32 * 32];
__device__ float g_d1[(size_t)NB * 128 * 64 * 64];
__device__ float g_d2[(size_t)NB * 128 * 128 * 128];
__device__ float g_vq_part[256];
__device__ float g_rec_part[4096];
__device__ float g_w1t[16 * 3 * 128];
__device__ float g_w2t[16 * 128 * 128];
__device__ float g_w3t[9 * 128 * 64];
__device__ float g_w3dt[128 * 9 * 3];
__device__ __align__(16) __nv_bfloat16 g_bw1[4 * 2 * 128 * 256];  // [cl][h][co][K]
__device__ __align__(16) __nv_bfloat16 g_bw2[4 * 2 * 128 * 512];  // [cl][h][co][K]

__global__ void wprep_k(const float* __restrict__ w1, const float* __restrict__ w2,
                        const float* __restrict__ w3, const float* __restrict__ dw1,
                        const float* __restrict__ dw2, const float* __restrict__ dw3)
{
    int st = gridDim.x * blockDim.x, g = blockIdx.x * blockDim.x + threadIdx.x;
    for (int t = g; t < 16 * 3 * 128; t += st) {
        int co = t & 127, r = t >> 7, ci = r % 3, kk = r / 3;
        g_w1t[(kk * 3 + ci) * 128 + co] = w1[((size_t)co * 3 + ci) * 16 + kk];
    }
    for (int t = g; t < 16 * 128 * 128; t += st) {
        int co = t & 127, r = t >> 7, ci = r & 127, kk = r >> 7;
        g_w2t[(kk * 128 + ci) * 128 + co] = w2[((size_t)co * 128 + ci) * 16 + kk];
    }
    for (int t = g; t < 9 * 128 * 64; t += st) {
        int co = t & 63, r = t >> 6, ci = r & 127, kk = r >> 7;
        g_w3t[(kk * 128 + ci) * 64 + co] = w3[((size_t)co * 128 + ci) * 9 + kk];
    }
    for (int t = g; t < 128 * 9 * 3; t += st) {
        int co = t % 3, r = t / 3, kk = r % 9, ci = r / 9;
        g_w3dt[t] = dw3[((size_t)co * 128 + ci) * 9 + kk];
    }
    for (int t = g; t < 4 * 2 * 128 * 256; t += st) {
        int k = t & 255, r2 = t >> 8, co = r2 & 127, h = (r2 >> 7) & 1, cl = r2 >> 8;
        int ci = k >> 2, rr = (k >> 1) & 1, cc = k & 1;
        int dh = cl >> 1, dw = cl & 1;
        float w = dw1[((size_t)ci * 128 + co) * 16 + (1 - dh + 2 * rr) * 4 + (1 - dw + 2 * cc)];
        g_bw1[t] = __float2bfloat16(h ? bfres(w) : w);
    }
    for (int t = g; t < 4 * 2 * 128 * 512; t += st) {
        int k = t & 511, r2 = t >> 9, co = r2 & 127, h = (r2 >> 7) & 1, cl = r2 >> 8;
        int ci = k >> 2, rr = (k >> 1) & 1, cc = k & 1;
        int dh = cl >> 1, dw = cl & 1;
        float w = dw2[((size_t)ci * 128 + co) * 16 + (1 - dh + 2 * rr) * 4 + (1 - dw + 2 * cc)];
        g_bw2[t] = __float2bfloat16(h ? bfres(w) : w);
    }
}

// enc1: bit-exact scalar chain; all weights resident, single sync (R13).
template <int K, int S, int CIN, int COUT, int H, bool RELU>
__global__ void __launch_bounds__(512) conv_seq(const float* __restrict__ in,
                                                const float* __restrict__ wt,
                                                const float* __restrict__ bias,
                                                float* __restrict__ out)
{
    constexpr int W = H, OH = (H + 2 - K) / S + 1, OW = OH;
    constexpr int IHS = 7 * S + K, IWS = 7 * S + K, IWP = IWS + 1;
    constexpr int SW_OFF = ((CIN * IHS * IWP + 3) / 4) * 4;
    constexpr int WN = K * K * CIN * 64;
    extern __shared__ float sm[];
    float* s_in = sm;
    float* s_w  = sm + SW_OFF;
    const int n = blockIdx.z, co0 = blockIdx.y * 64;
    constexpr int TWn = OW / 8;
    const int oh0 = (blockIdx.x / TWn) * 8, ow0 = (blockIdx.x % TWn) * 8;
    const int tid = threadIdx.x, px = tid & 63, cog = tid >> 6;
    const int ohr = px >> 3, owr = px & 7;
    const int ihb = oh0 * S - 1, iwb = ow0 * S - 1;

    for (int t = tid; t < CIN * IHS * IWS; t += 512) {
        int ci = t / (IHS * IWS), r = t % (IHS * IWS), rr = r / IWS, cc = r % IWS;
        int ih = ihb + rr, iw = iwb + cc;
        float v = 0.f;
        if (ih >= 0 && ih < H && iw >= 0 && iw < W)
            v = in[(((size_t)n * CIN + ci) * H + ih) * W + iw];
        s_in[(ci * IHS + rr) * IWP + cc] = v;
    }
    for (int t = tid; t < WN; t += 512)
        s_w[t] = wt[(size_t)(t >> 6) * COUT + co0 + (t & 63)];
    __syncthreads();

    const int cob = co0 + cog * 8;
    float a[8];
    #pragma unroll
    for (int i = 0; i < 8; i++) a[i] = 0.f;
    #pragma unroll
    for (int kh = 0; kh < K; kh++)
    #pragma unroll
    for (int kw = 0; kw < K; kw++) {
        const float* ip = &s_in[(ohr * S + kh) * IWP + owr * S + kw];
        const float* wp = &s_w[((kh * K + kw) * CIN) * 64 + cog * 8];
        #pragma unroll 3
        for (int ci = 0; ci < CIN; ci++) {
            float iv = ip[ci * IHS * IWP];
            float4 w0 = *(const float4*)&wp[ci * 64];
            float4 w1 = *(const float4*)&wp[ci * 64 + 4];
            a[0] = __fmaf_rn(iv, w0.x, a[0]);
            a[1] = __fmaf_rn(iv, w0.y, a[1]);
            a[2] = __fmaf_rn(iv, w0.z, a[2]);
            a[3] = __fmaf_rn(iv, w0.w, a[3]);
            a[4] = __fmaf_rn(iv, w1.x, a[4]);
            a[5] = __fmaf_rn(iv, w1.y, a[5]);
            a[6] = __fmaf_rn(iv, w1.z, a[6]);
            a[7] = __fmaf_rn(iv, w1.w, a[7]);
        }
    }
    const int oh = oh0 + ohr, ow = ow0 + owr;
    #pragma unroll
    for (int c = 0; c < 8; c++) {
        float v = __fadd_rn(a[c], bias[cob + c]);
        if (RELU) v = fmaxf(v, 0.f);
        out[(((size_t)n * COUT + cob + c) * OH + oh) * OW + ow] = v;
    }
}

// enc2 (R13 compute; float4 panel staging).
__global__ void __launch_bounds__(512) enc2_k(const float* __restrict__ in,
                                              const float* __restrict__ wt,
                                              const float* __restrict__ bias,
                                              float* __restrict__ out)
{
    extern __shared__ float sm[];
    float* s_in = sm;
    float* s_w  = sm + 128 * 18 * 19;
    const int n = blockIdx.z;
    const int oh0 = (blockIdx.x >> 2) * 8, ow0 = (blockIdx.x & 3) * 8;
    const int tid = threadIdx.x, px = tid & 31, cog = tid >> 5;
    const int ohr = px >> 2, owp = px & 3;
    const int ihb = oh0 * 2 - 1, iwb = ow0 * 2 - 1;

    for (int t = tid; t < 128 * 18 * 18; t += 512) {
        int ci = t / 324, r = t % 324, rr = r / 18, cc = r % 18;
        int ih = ihb + rr, iw = iwb + cc;
        float v = 0.f;
        if (ih >= 0 && ih < 64 && iw >= 0 && iw < 64)
            v = in[(((size_t)n * 128 + ci) * 64 + ih) * 64 + iw];
        s_in[(ci * 18 + rr) * 19 + cc] = v;
    }

    ull a[2][4];
    #pragma unroll
    for (int p = 0; p < 2; p++)
    #pragma unroll
    for (int j = 0; j < 4; j++) a[p][j] = 0ull;

    float4* sw4 = (float4*)s_w;
    #pragma unroll
    for (int kh = 0; kh < 4; kh++)
    #pragma unroll
    for (int kw = 0; kw < 4; kw++) {
        for (int ci0 = 0; ci0 < 128; ci0 += 64) {
            __syncthreads();
            const float4* wp4 =
                (const float4*)(wt + (size_t)((kh * 4 + kw) * 128 + ci0) * 128);
            for (int t = tid; t < 2048; t += 512) sw4[t] = wp4[t];
            __syncthreads();
            const float* ip = &s_in[((ci0 * 18) + ohr * 2 + kh) * 19 + owp * 4 + kw];
            const float* wp = &s_w[cog * 8];
            #pragma unroll 2
            for (int ci = 0; ci < 64; ci++) {
                float i0 = ip[ci * 342];
                float i1 = ip[ci * 342 + 2];
                ull p0 = pack2(i0), p1 = pack2(i1);
                ulonglong2 wA = *(const ulonglong2*)&wp[ci * 128];
                ulonglong2 wB = *(const ulonglong2*)&wp[ci * 128 + 4];
                a[0][0] = fma2(p0, wA.x, a[0][0]);
                a[0][1] = fma2(p0, wA.y, a[0][1]);
                a[0][2] = fma2(p0, wB.x, a[0][2]);
                a[0][3] = fma2(p0, wB.y, a[0][3]);
                a[1][0] = fma2(p1, wA.x, a[1][0]);
                a[1][1] = fma2(p1, wA.y, a[1][1]);
                a[1][2] = fma2(p1, wB.x, a[1][2]);
                a[1][3] = fma2(p1, wB.y, a[1][3]);
            }
        }
    }
    const int oh = oh0 + ohr;
    #pragma unroll
    for (int p = 0; p < 2; p++) {
        int ow = ow0 + owp * 2 + p;
        #pragma unroll
        for (int j = 0; j < 4; j++) {
            int co = cog * 8 + 2 * j;
            float lo, hi;
            unpack2(a[p][j], lo, hi);
            out[(((size_t)n * 128 + co) * 32 + oh) * 32 + ow] =
                fmaxf(__fadd_rn(lo, bias[co]), 0.f);
            out[(((size_t)n * 128 + co + 1) * 32 + oh) * 32 + ow] =
                fmaxf(__fadd_rn(hi, bias[co + 1]), 0.f);
        }
    }
}

// enc3 (R13 compute; float4 panel staging).
__global__ void __launch_bounds__(256) enc3_k(const float* __restrict__ in,
                                              const float* __restrict__ wt,
                                              const float* __restrict__ bias,
                                              float* __restrict__ out)
{
    extern __shared__ float sm[];
    float* s_in = sm;
    float* s_w  = sm + 128 * 10 * 11;
    const int n = blockIdx.z;
    const int oh0 = (blockIdx.x >> 2) * 8, ow0 = (blockIdx.x & 3) * 8;
    const int tid = threadIdx.x, px = tid & 31, cog = tid >> 5;
    const int ohr = px >> 2, owp = px & 3;
    const int ihb = oh0 - 1, iwb = ow0 - 1;

    for (int t = tid; t < 128 * 10 * 10; t += 256) {
        int ci = t / 100, r = t % 100, rr = r / 10, cc = r % 10;
        int ih = ihb + rr, iw = iwb + cc;
        float v = 0.f;
        if (ih >= 0 && ih < 32 && iw >= 0 && iw < 32)
            v = in[(((size_t)n * 128 + ci) * 32 + ih) * 32 + iw];
        s_in[(ci * 10 + rr) * 11 + cc] = v;
    }

    ull a[2][4];
    #pragma unroll
    for (int p = 0; p < 2; p++)
    #pragma unroll
    for (int j = 0; j < 4; j++) a[p][j] = 0ull;

    float4* sw4 = (float4*)s_w;
    #pragma unroll
    for (int kh = 0; kh < 3; kh++)
    #pragma unroll
    for (int kw = 0; kw < 3; kw++) {
        __syncthreads();
        const float4* wp4 = (const float4*)(wt + (size_t)(kh * 3 + kw) * 8192);
        for (int t = tid; t < 2048; t += 256) sw4[t] = wp4[t];
        __syncthreads();
        const float* ip = &s_in[(ohr + kh) * 11 + owp * 2 + kw];
        const float* wp = &s_w[cog * 8];
        #pragma unroll 2
        for (int ci = 0; ci < 128; ci++) {
            float i0 = ip[ci * 110];
            float i1 = ip[ci * 110 + 1];
            ull p0 = pack2(i0), p1 = pack2(i1);
            ulonglong2 wA = *(const ulonglong2*)&wp[ci * 64];
            ulonglong2 wB = *(const ulonglong2*)&wp[ci * 64 + 4];
            a[0][0] = fma2(p0, wA.x, a[0][0]);
            a[0][1] = fma2(p0, wA.y, a[0][1]);
            a[0][2] = fma2(p0, wB.x, a[0][2]);
            a[0][3] = fma2(p0, wB.y, a[0][3]);
            a[1][0] = fma2(p1, wA.x, a[1][0]);
            a[1][1] = fma2(p1, wA.y, a[1][1]);
            a[1][2] = fma2(p1, wB.x, a[1][2]);
            a[1][3] = fma2(p1, wB.y, a[1][3]);
        }
    }
    const int oh = oh0 + ohr;
    #pragma unroll
    for (int p = 0; p < 2; p++) {
        int ow = ow0 + owp * 2 + p;
        #pragma unroll
        for (int j = 0; j < 4; j++) {
            int co = cog * 8 + 2 * j;
            float lo, hi;
            unpack2(a[p][j], lo, hi);
            out[(((size_t)n * 64 + co) * 32 + oh) * 32 + ow] = __fadd_rn(lo, bias[co]);
            out[(((size_t)n * 64 + co + 1) * 32 + oh) * 32 + ow] = __fadd_rn(hi, bias[co + 1]);
        }
    }
}

// VQ: f32x2 dual-codeword chains; per-chain fp32 sequence identical to R13.
// Codebook in smem interleaved as [kpair][d][2].
__global__ void __launch_bounds__(256) vq_k(const float* __restrict__ ze,
                                            const float* __restrict__ cb,
                                            float* __restrict__ zq,
                                            float* __restrict__ part)
{
    extern __shared__ float sm[];
    float* s_cbp = sm;            // [256][64][2]
    float* s_cb2 = sm + 32768;    // [512]
    __shared__ float red[256];
    const int tid = threadIdx.x;
    for (int t = tid; t < 32768; t += 256) {
        int j = t & 1, d = (t >> 1) & 63, kp = t >> 7;
        s_cbp[t] = cb[(size_t)(2 * kp + j) * 64 + d];
    }
    __syncthreads();
    for (int k = tid; k < 512; k += 256) {
        const float* cp = &s_cbp[((k >> 1) * 64) * 2 + (k & 1)];
        float s = 0.f;
        for (int d = 0; d < 64; d++) {
            float c = cp[2 * d];
            s = __fadd_rn(s, __fmul_rn(c, c));
        }
        s_cb2[k] = s;
    }
    __syncthreads();

    const int v = blockIdx.x * 256 + tid;
    const int n = v >> 10, hw = v & 1023;
    const float* zp = ze + (size_t)n * 64 * 1024 + hw;
    float z[64];
    #pragma unroll
    for (int d = 0; d < 64; d++) z[d] = zp[(size_t)d * 1024];

    float z2 = 0.f;
    #pragma unroll
    for (int d = 0; d < 64; d++) z2 = __fadd_rn(z2, __fmul_rn(z[d], z[d]));

    float best = 3.4e38f;
    int bi = 0;
    for (int kp0 = 0; kp0 < 256; kp0 += 2) {
        ull dt01 = 0ull, dt23 = 0ull;
        const ull* p0 = (const ull*)&s_cbp[kp0 * 128];
        const ull* p1 = (const ull*)&s_cbp[(kp0 + 1) * 128];
        #pragma unroll
        for (int d = 0; d < 64; d += 2) {
            ulonglong2 ua = *(const ulonglong2*)&p0[d];
            ulonglong2 ub = *(const ulonglong2*)&p1[d];
            ull zd0 = pack2(z[d]), zd1 = pack2(z[d + 1]);
            dt01 = fma2(zd0, ua.x, dt01);
            dt01 = fma2(zd1, ua.y, dt01);
            dt23 = fma2(zd0, ub.x, dt23);
            dt23 = fma2(zd1, ub.y, dt23);
        }
        float dt0, dt1, dt2, dt3;
        unpack2(dt01, dt0, dt1);
        unpack2(dt23, dt2, dt3);
        const int k0 = 2 * kp0;
        float s0 = __fsub_rn(__fadd_rn(z2, s_cb2[k0 + 0]), __fmul_rn(2.f, dt0));
        float s1 = __fsub_rn(__fadd_rn(z2, s_cb2[k0 + 1]), __fmul_rn(2.f, dt1));
        float s2 = __fsub_rn(__fadd_rn(z2, s_cb2[k0 + 2]), __fmul_rn(2.f, dt2));
        float s3 = __fsub_rn(__fadd_rn(z2, s_cb2[k0 + 3]), __fmul_rn(2.f, dt3));
        if (s0 < best) { best = s0; bi = k0; }
        if (s1 < best) { best = s1; bi = k0 + 1; }
        if (s2 < best) { best = s2; bi = k0 + 2; }
        if (s3 < best) { best = s3; bi = k0 + 3; }
    }

    float* zqp = zq + (size_t)n * 64 * 1024 + hw;
    const float* cbi = &s_cbp[((bi >> 1) * 64) * 2 + (bi & 1)];
    float lsum = 0.f;
    #pragma unroll
    for (int d = 0; d < 64; d++) {
        float c = cbi[2 * d];
        float df = z[d] - c;
        lsum = fmaf(df, df, lsum);
        zqp[(size_t)d * 1024] = __fadd_rn(z[d], __fsub_rn(c, z[d]));
    }
    red[tid] = lsum;
    __syncthreads();
    for (int s = 128; s > 0; s >>= 1) {
        if (tid < s) red[tid] += red[tid + s];
        __syncthreads();
    }
    if (tid == 0) part[blockIdx.x] = red[0];
}

// Deconv via mma.sync bf16 (exact R10/R13).
template <int CIN, int IHW>
__global__ void __launch_bounds__(256) deconv_mma_k(
    const float* __restrict__ in, const __nv_bfloat16* __restrict__ gB,
    const float* __restrict__ bias, float* __restrict__ out)
{
    constexpr int K = CIN * 4;
    constexpr int NCH = K / 64;
    constexpr int OH = IHW * 2, OW = IHW * 2;
    constexpr int TX = IHW / 16;
    constexpr int PATCH_B = CIN * 180 * 4;
    constexpr int AH_B = PATCH_B, AL_B = AH_B + 18432;
    constexpr int BH_B = AL_B + 18432, BL_B = BH_B + 18432;

    extern __shared__ char smc[];
    float* s_patch = (float*)smc;
    const uint32 sb = smem_u32(smc);

    const int tid = threadIdx.x;
    const int lane = tid & 31, wrp = tid >> 5;
    const int mg = wrp & 3, ng = wrp >> 2;
    const int n = blockIdx.z, cl = blockIdx.y;
    const int dh = cl >> 1, dw = cl & 1;
    const int y0 = (blockIdx.x / TX) * 8, x0 = (blockIdx.x % TX) * 16;

    for (int t = tid; t < CIN * 180; t += 256) {
        int ci = t / 180, r = t % 180, rr = r / 18, cc = r % 18;
        int yy = y0 - 1 + rr, xx = x0 - 1 + cc;
        float v = 0.f;
        if (yy >= 0 && yy < IHW && xx >= 0 && xx < IHW)
            v = in[(((size_t)n * CIN + ci) * IHW + yy) * IHW + xx];
        s_patch[t] = v;
    }

    float c[2][8][4];
    #pragma unroll
    for (int i = 0; i < 2; i++)
    #pragma unroll
    for (int j = 0; j < 8; j++)
    #pragma unroll
    for (int q = 0; q < 4; q++) c[i][j][q] = 0.f;

    const int am = tid >> 1, aks = (tid & 1) * 32;
    const int a_yl = am >> 4, a_xl = am & 15;
    const int a_pr0 = a_yl + dh + 1, a_pc0 = a_xl + dw + 1;

    for (int kc = 0; kc < NCH; kc++) {
        __syncthreads();
        {
            uint32* ah = (uint32*)(smc + AH_B);
            uint32* al = (uint32*)(smc + AL_B);
            const int kc16 = kc * 16;
            #pragma unroll 4
            for (int j2 = 0; j2 < 16; j2++) {
                int k = aks + 2 * j2;
                int ci = kc16 + (k >> 2);
                int r = (k >> 1) & 1;
                const float* pp = &s_patch[(ci * 10 + (a_pr0 - r)) * 18];
                float v0 = pp[a_pc0];
                float v1 = pp[a_pc0 - 1];
                int idx = (am * 72 + k) >> 1;
                ah[idx] = pkbf2(v0, v1);
                al[idx] = pkbf2(bfres(v0), bfres(v1));
            }
        }
        {
            const __nv_bfloat16* bh = gB + ((size_t)(cl * 2 + 0) * 128) * K + kc * 64;
            const __nv_bfloat16* bl = gB + ((size_t)(cl * 2 + 1) * 128) * K + kc * 64;
            for (int e = tid; e < 1024; e += 256) {
                int co = e >> 3, k8 = (e & 7) * 8;
                uint4 vh = *(const uint4*)(bh + (size_t)co * K + k8);
                uint4 vl = *(const uint4*)(bl + (size_t)co * K + k8);
                *(uint4*)(smc + BH_B + (co * 72 + k8) * 2) = vh;
                *(uint4*)(smc + BL_B + (co * 72 + k8) * 2) = vl;
            }
        }
        __syncthreads();

        #pragma unroll
        for (int k16i = 0; k16i < 4; k16i++) {
            const int k16 = k16i * 16;
            uint32 a_h[2][4], a_l[2][4];
            #pragma unroll
            for (int i = 0; i < 2; i++) {
                int row = mg * 32 + i * 16 + (lane & 15);
                uint32 off = (uint32)((row * 72 + k16 + ((lane >> 4) << 3)) * 2);
                ldm_x4(a_h[i][0], a_h[i][1], a_h[i][2], a_h[i][3], sb + AH_B + off);
                ldm_x4(a_l[i][0], a_l[i][1], a_l[i][2], a_l[i][3], sb + AL_B + off);
            }
            uint32 b_h[8][2], b_l[8][2];
            #pragma unroll
            for (int j = 0; j < 8; j++) {
                int nrow = ng * 64 + j * 8 + (lane & 7);
                uint32 off = (uint32)((nrow * 72 + k16 + (((lane >> 3) & 1) << 3)) * 2);
                ldm_x2(b_h[j][0], b_h[j][1], sb + BH_B + off);
                ldm_x2(b_l[j][0], b_l[j][1], sb + BL_B + off);
            }
            #pragma unroll
            for (int i = 0; i < 2; i++)
            #pragma unroll
            for (int j = 0; j < 8; j++) {
                mma16816(c[i][j], a_h[i], b_h[j]);
                mma16816(c[i][j], a_h[i], b_l[j]);
                mma16816(c[i][j], a_l[i], b_h[j]);
            }
        }
    }

    #pragma unroll
    for (int i = 0; i < 2; i++) {
        int row0 = mg * 32 + i * 16 + (lane >> 2);
        #pragma unroll
        for (int rr = 0; rr < 2; rr++) {
            int row = row0 + rr * 8;
            int y_l = row >> 4, x_l = row & 15;
            int oh = 2 * (y0 + y_l) + dh, ow = 2 * (x0 + x_l) + dw;
            size_t ob = ((size_t)n * 128) * OH * OW + (size_t)oh * OW + ow;
            #pragma unroll
            for (int j = 0; j < 8; j++) {
                int col = ng * 64 + j * 8 + (lane & 3) * 2;
                float v0 = c[i][j][rr * 2 + 0] + bias[col];
                float v1 = c[i][j][rr * 2 + 1] + bias[col + 1];
                out[ob + (size_t)col * OH * OW] = fmaxf(v0, 0.f);
                out[ob + (size_t)(col + 1) * OH * OW] = fmaxf(v1, 0.f);
            }
        }
    }
}

// dec3: 2 output rows per thread (exact R13).
__global__ void __launch_bounds__(256) dec3_k(const float* __restrict__ in,
                                              const float* __restrict__ wtt,
                                              const float* __restrict__ bias,
                                              const float* __restrict__ x,
                                              float* __restrict__ out,
                                              float* __restrict__ rec_part)
{
    extern __shared__ float sm[];
    float* s_in = sm;
    float* s_w  = sm + 16 * 6 * 130;
    __shared__ float red[256];
    const int n = blockIdx.y, oh0 = blockIdx.x * 4;
    const int tid = threadIdx.x, rg = tid >> 7, col = tid & 127;

    for (int t = tid; t < 128 * 9 * 3; t += 256)
        s_w[(t / 3) * 4 + t % 3] = wtt[t];

    float a[2][3];
    #pragma unroll
    for (int p = 0; p < 2; p++)
    #pragma unroll
    for (int co = 0; co < 3; co++) a[p][co] = 0.f;

    for (int ci0 = 0; ci0 < 128; ci0 += 16) {
        for (int t = tid; t < 16 * 6 * 130; t += 256) {
            int cil = t / 780, r2 = t % 780, rr = r2 / 130, cc = r2 % 130;
            int ih = oh0 - 1 + rr, iw = cc - 1;
            float v = 0.f;
            if (ih >= 0 && ih < 128 && iw >= 0 && iw < 128)
                v = in[(((size_t)n * 128 + ci0 + cil) * 128 + ih) * 128 + iw];
            s_in[t] = v;
        }
        __syncthreads();
        for (int cil = 0; cil < 16; cil++) {
            float riv[4][3];
            const float* bp = &s_in[(cil * 6 + 2 * rg) * 130 + col];
            #pragma unroll
            for (int dr = 0; dr < 4; dr++)
            #pragma unroll
            for (int kw = 0; kw < 3; kw++) riv[dr][kw] = bp[dr * 130 + kw];
            #pragma unroll
            for (int kh = 0; kh < 3; kh++) {
                #pragma unroll
                for (int kw = 0; kw < 3; kw++) {
                    float4 wv = *(const float4*)&s_w[((ci0 + cil) * 9 + kh * 3 + kw) * 4];
                    float iv0 = riv[kh][kw];
                    float iv1 = riv[kh + 1][kw];
                    a[0][0] = fmaf(wv.x, iv0, a[0][0]);
                    a[0][1] = fmaf(wv.y, iv0, a[0][1]);
                    a[0][2] = fmaf(wv.z, iv0, a[0][2]);
                    a[1][0] = fmaf(wv.x, iv1, a[1][0]);
                    a[1][1] = fmaf(wv.y, iv1, a[1][1]);
                    a[1][2] = fmaf(wv.z, iv1, a[1][2]);
                }
            }
        }
        __syncthreads();
    }
    float lsum = 0.f;
    #pragma unroll
    for (int p = 0; p < 2; p++) {
        int oh = oh0 + 2 * rg + p;
        #pragma unroll
        for (int co = 0; co < 3; co++) {
            float v = a[p][co] + bias[co];
            size_t idx = (((size_t)n * 3 + co) * 128 + oh) * 128 + col;
            out[idx] = v;
            float d = v - x[idx];
            lsum = fmaf(d, d, lsum);
        }
    }
    red[tid] = lsum;
    __syncthreads();
    for (int s = 128; s > 0; s >>= 1) {
        if (tid < s) red[tid] += red[tid + s];
        __syncthreads();
    }
    if (tid == 0) rec_part[(size_t)n * 32 + blockIdx.x] = red[0];
}

__global__ void __launch_bounds__(256) finalize_k(const float* __restrict__ rec_part,
                                                  const float* __restrict__ vq_part,
                                                  float* __restrict__ out)
{
    __shared__ double rA[256], rB[256];
    const int tid = threadIdx.x;
    double s = 0.0;
    for (int t = tid; t < 2048; t += 256) s += (double)rec_part[t];
    rA[tid] = s;
    rB[tid] = (double)vq_part[tid];
    __syncthreads();
    for (int st = 128; st > 0; st >>= 1) {
        if (tid < st) { rA[tid] += rA[tid + st]; rB[tid] += rB[tid + st]; }
        __syncthreads();
    }
    if (tid == 0) {
        double recon = rA[0] / 3145728.0;
        double vq    = 1.25 * rB[0] / 4194304.0;
        out[3145728] = (float)(recon + vq);
        out[3145729] = (float)recon;
        out[3145730] = (float)vq;
    }
}

extern "C" void kernel_launch(void* const* d_in, const int* in_sizes, int n_in,
                              void* d_out, int out_size)
{
    (void)in_sizes; (void)n_in; (void)out_size;
    const float* x   = (const float*)d_in[0];
    const float* ew1 = (const float*)d_in[1];
    const float* eb1 = (const float*)d_in[2];
    const float* ew2 = (const float*)d_in[3];
    const float* eb2 = (const float*)d_in[4];
    const float* ew3 = (const float*)d_in[5];
    const float* eb3 = (const float*)d_in[6];
    const float* cb  = (const float*)d_in[7];
    const float* dw1 = (const float*)d_in[8];
    const float* db1 = (const float*)d_in[9];
    const float* dw2 = (const float*)d_in[10];
    const float* db2 = (const float*)d_in[11];
    const float* dw3 = (const float*)d_in[12];
    const float* db3 = (const float*)d_in[13];
    float* out = (float*)d_out;

    void *h1, *h2, *ze, *zq, *dd1, *dd2, *vqp, *recp;
    void *w1t, *w2t, *w3t, *w3dt, *bw1, *bw2;
    cudaGetSymbolAddress(&h1,  g_h1);
    cudaGetSymbolAddress(&h2,  g_h2);
    cudaGetSymbolAddress(&ze,  g_ze);
    cudaGetSymbolAddress(&zq,  g_zq);
    cudaGetSymbolAddress(&dd1, g_d1);
    cudaGetSymbolAddress(&dd2, g_d2);
    cudaGetSymbolAddress(&vqp,  g_vq_part);
    cudaGetSymbolAddress(&recp, g_rec_part);
    cudaGetSymbolAddress(&w1t,  g_w1t);
    cudaGetSymbolAddress(&w2t,  g_w2t);
    cudaGetSymbolAddress(&w3t,  g_w3t);
    cudaGetSymbolAddress(&w3dt, g_w3dt);
    cudaGetSymbolAddress(&bw1,  g_bw1);
    cudaGetSymbolAddress(&bw2,  g_bw2);

    const int SM_E1 = (1028 + 16 * 3 * 64) * 4;
    const int SM_E2 = (128 * 18 * 19 + 64 * 128) * 4;
    const int SM_E3 = (128 * 10 * 11 + 128 * 64) * 4;
    const int SM_M1 = 64 * 180 * 4 + 4 * 18432;
    const int SM_M2 = 128 * 180 * 4 + 4 * 18432;
    const int SM_D3 = (16 * 6 * 130 + 128 * 9 * 4) * 4;
    const int SM_VQ = (32768 + 512) * 4;

    cudaFuncSetAttribute((const void*)enc2_k,
                         cudaFuncAttributeMaxDynamicSharedMemorySize, SM_E2);
    cudaFuncSetAttribute((const void*)enc3_k,
                         cudaFuncAttributeMaxDynamicSharedMemorySize, SM_E3);
    cudaFuncSetAttribute((const void*)deconv_mma_k<64,32>,
                         cudaFuncAttributeMaxDynamicSharedMemorySize, SM_M1);
    cudaFuncSetAttribute((const void*)deconv_mma_k<128,64>,
                         cudaFuncAttributeMaxDynamicSharedMemorySize, SM_M2);
    cudaFuncSetAttribute((const void*)vq_k,
                         cudaFuncAttributeMaxDynamicSharedMemorySize, SM_VQ);
    cudaFuncSetAttribute((const void*)dec3_k,
                         cudaFuncAttributeMaxDynamicSharedMemorySize, SM_D3);

    wprep_k<<<256, 256>>>(ew1, ew2, ew3, dw1, dw2, dw3);
    conv_seq<4,2,3,128,128,true><<<dim3(64, 2, NB), 512, SM_E1>>>(
        x, (const float*)w1t, eb1, (float*)h1);
    enc2_k<<<dim3(16, 1, NB), 512, SM_E2>>>(
        (const float*)h1, (const float*)w2t, eb2, (float*)h2);
    enc3_k<<<dim3(16, 1, NB), 256, SM_E3>>>(
        (const float*)h2, (const float*)w3t, eb3, (float*)ze);
    vq_k<<<256, 256, SM_VQ>>>(
        (const float*)ze, cb, (float*)zq, (float*)vqp);
    deconv_mma_k<64,32><<<dim3(8, 4, NB), 256, SM_M1>>>(
        (const float*)zq, (const __nv_bfloat16*)bw1, db1, (float*)dd1);
    deconv_mma_k<128,64><<<dim3(32, 4, NB), 256, SM_M2>>>(
        (const float*)dd1, (const __nv_bfloat16*)bw2, db2, (float*)dd2);
    dec3_k<<<dim3(32, NB), 256, SM_D3>>>(
        (const float*)dd2, (const float*)w3dt, db3, x, out, (float*)recp);
    finalize_k<<<1, 256>>>(
        (const float*)recp, (const float*)vqp, out);
}

// round 15
// speedup vs baseline: 1.1166x; 1.0569x over previous
#include <cuda_runtime.h>
#include <cuda_bf16.h>
#include <cstdint>
#include <cstddef>

#define NB 64
typedef unsigned long long ull;
typedef unsigned int uint32;

__device__ __forceinline__ ull pack2(float x) {
    ull d; unsigned u = __float_as_uint(x);
    asm("mov.b64 %0, {%1, %1};" : "=l"(d) : "r"(u));
    return d;
}
__device__ __forceinline__ ull fma2(ull a, ull b, ull c) {
    ull d;
    asm("fma.rn.f32x2 %0, %1, %2, %3;" : "=l"(d) : "l"(a), "l"(b), "l"(c));
    return d;
}
__device__ __forceinline__ void unpack2(ull a, float& lo, float& hi) {
    unsigned l, h;
    asm("mov.b64 {%0, %1}, %2;" : "=r"(l), "=r"(h) : "l"(a));
    lo = __uint_as_float(l); hi = __uint_as_float(h);
}
__device__ __forceinline__ uint32 smem_u32(const void* p) {
    uint32 a;
    asm("{ .reg .u64 t; cvta.to.shared.u64 t, %1; cvt.u32.u64 %0, t; }" : "=r"(a) : "l"(p));
    return a;
}
__device__ __forceinline__ void ldm_x4(uint32& r0, uint32& r1, uint32& r2, uint32& r3, uint32 a) {
    asm volatile("ldmatrix.sync.aligned.m8n8.x4.shared.b16 {%0,%1,%2,%3}, [%4];"
                 : "=r"(r0), "=r"(r1), "=r"(r2), "=r"(r3) : "r"(a));
}
__device__ __forceinline__ void ldm_x2(uint32& r0, uint32& r1, uint32 a) {
    asm volatile("ldmatrix.sync.aligned.m8n8.x2.shared.b16 {%0,%1}, [%2];"
                 : "=r"(r0), "=r"(r1) : "r"(a));
}
__device__ __forceinline__ void mma16816(float* c, const uint32* a, const uint32* b) {
    asm volatile(
        "mma.sync.aligned.m16n8k16.row.col.f32.bf16.bf16.f32 "
        "{%0,%1,%2,%3}, {%4,%5,%6,%7}, {%8,%9}, {%0,%1,%2,%3};"
        : "+f"(c[0]), "+f"(c[1]), "+f"(c[2]), "+f"(c[3])
        : "r"(a[0]), "r"(a[1]), "r"(a[2]), "r"(a[3]), "r"(b[0]), "r"(b[1]));
}
__device__ __forceinline__ uint32 pkbf2(float a, float b) {
    return (uint32)__bfloat16_as_ushort(__float2bfloat16(a))
         | ((uint32)__bfloat16_as_ushort(__float2bfloat16(b)) << 16);
}
__device__ __forceinline__ float bfres(float v) {
    return v - __bfloat162float(__float2bfloat16(v));
}

__device__ float g_h1[(size_t)NB * 128 * 64 * 64];
__device__ float g_h2[(size_t)NB * 128 * 32 * 32];
__device__ float g_ze[(size_t)NB * 64 * 32 * 32];
__device__ float g_zq[(size_t)NB * 64 * 32 * 32];
__device__ float g_d1[(size_t)NB * 128 * 64 * 64];
__device__ float g_d2[(size_t)NB * 128 * 128 * 128];
__device__ float g_vq_part[256];
__device__ float g_rec_part[4096];
__device__ float g_w1t[16 * 3 * 128];
__device__ float g_w2t[16 * 128 * 128];
__device__ float g_w3t[9 * 128 * 64];
__device__ float g_w3dt[128 * 9 * 3];
__device__ __align__(16) __nv_bfloat16 g_bw1[4 * 2 * 128 * 256];  // [cl][h][co][K]
__device__ __align__(16) __nv_bfloat16 g_bw2[4 * 2 * 128 * 512];  // [cl][h][co][K]

__global__ void wprep_k(const float* __restrict__ w1, const float* __restrict__ w2,
                        const float* __restrict__ w3, const float* __restrict__ dw1,
                        const float* __restrict__ dw2, const float* __restrict__ dw3)
{
    int st = gridDim.x * blockDim.x, g = blockIdx.x * blockDim.x + threadIdx.x;
    for (int t = g; t < 16 * 3 * 128; t += st) {
        int co = t & 127, r = t >> 7, ci = r % 3, kk = r / 3;
        g_w1t[(kk * 3 + ci) * 128 + co] = w1[((size_t)co * 3 + ci) * 16 + kk];
    }
    for (int t = g; t < 16 * 128 * 128; t += st) {
        int co = t & 127, r = t >> 7, ci = r & 127, kk = r >> 7;
        g_w2t[(kk * 128 + ci) * 128 + co] = w2[((size_t)co * 128 + ci) * 16 + kk];
    }
    for (int t = g; t < 9 * 128 * 64; t += st) {
        int co = t & 63, r = t >> 6, ci = r & 127, kk = r >> 7;
        g_w3t[(kk * 128 + ci) * 64 + co] = w3[((size_t)co * 128 + ci) * 9 + kk];
    }
    for (int t = g; t < 128 * 9 * 3; t += st) {
        int co = t % 3, r = t / 3, kk = r % 9, ci = r / 9;
        g_w3dt[t] = dw3[((size_t)co * 128 + ci) * 9 + kk];
    }
    for (int t = g; t < 4 * 2 * 128 * 256; t += st) {
        int k = t & 255, r2 = t >> 8, co = r2 & 127, h = (r2 >> 7) & 1, cl = r2 >> 8;
        int ci = k >> 2, rr = (k >> 1) & 1, cc = k & 1;
        int dh = cl >> 1, dw = cl & 1;
        float w = dw1[((size_t)ci * 128 + co) * 16 + (1 - dh + 2 * rr) * 4 + (1 - dw + 2 * cc)];
        g_bw1[t] = __float2bfloat16(h ? bfres(w) : w);
    }
    for (int t = g; t < 4 * 2 * 128 * 512; t += st) {
        int k = t & 511, r2 = t >> 9, co = r2 & 127, h = (r2 >> 7) & 1, cl = r2 >> 8;
        int ci = k >> 2, rr = (k >> 1) & 1, cc = k & 1;
        int dh = cl >> 1, dw = cl & 1;
        float w = dw2[((size_t)ci * 128 + co) * 16 + (1 - dh + 2 * rr) * 4 + (1 - dw + 2 * cc)];
        g_bw2[t] = __float2bfloat16(h ? bfres(w) : w);
    }
}

// enc1: bit-exact scalar chain; all weights resident, single sync (R13).
template <int K, int S, int CIN, int COUT, int H, bool RELU>
__global__ void __launch_bounds__(512) conv_seq(const float* __restrict__ in,
                                                const float* __restrict__ wt,
                                                const float* __restrict__ bias,
                                                float* __restrict__ out)
{
    constexpr int W = H, OH = (H + 2 - K) / S + 1, OW = OH;
    constexpr int IHS = 7 * S + K, IWS = 7 * S + K, IWP = IWS + 1;
    constexpr int SW_OFF = ((CIN * IHS * IWP + 3) / 4) * 4;
    constexpr int WN = K * K * CIN * 64;
    extern __shared__ float sm[];
    float* s_in = sm;
    float* s_w  = sm + SW_OFF;
    const int n = blockIdx.z, co0 = blockIdx.y * 64;
    constexpr int TWn = OW / 8;
    const int oh0 = (blockIdx.x / TWn) * 8, ow0 = (blockIdx.x % TWn) * 8;
    const int tid = threadIdx.x, px = tid & 63, cog = tid >> 6;
    const int ohr = px >> 3, owr = px & 7;
    const int ihb = oh0 * S - 1, iwb = ow0 * S - 1;

    for (int t = tid; t < CIN * IHS * IWS; t += 512) {
        int ci = t / (IHS * IWS), r = t % (IHS * IWS), rr = r / IWS, cc = r % IWS;
        int ih = ihb + rr, iw = iwb + cc;
        float v = 0.f;
        if (ih >= 0 && ih < H && iw >= 0 && iw < W)
            v = in[(((size_t)n * CIN + ci) * H + ih) * W + iw];
        s_in[(ci * IHS + rr) * IWP + cc] = v;
    }
    for (int t = tid; t < WN; t += 512)
        s_w[t] = wt[(size_t)(t >> 6) * COUT + co0 + (t & 63)];
    __syncthreads();

    const int cob = co0 + cog * 8;
    float a[8];
    #pragma unroll
    for (int i = 0; i < 8; i++) a[i] = 0.f;
    #pragma unroll
    for (int kh = 0; kh < K; kh++)
    #pragma unroll
    for (int kw = 0; kw < K; kw++) {
        const float* ip = &s_in[(ohr * S + kh) * IWP + owr * S + kw];
        const float* wp = &s_w[((kh * K + kw) * CIN) * 64 + cog * 8];
        #pragma unroll 3
        for (int ci = 0; ci < CIN; ci++) {
            float iv = ip[ci * IHS * IWP];
            float4 w0 = *(const float4*)&wp[ci * 64];
            float4 w1 = *(const float4*)&wp[ci * 64 + 4];
            a[0] = __fmaf_rn(iv, w0.x, a[0]);
            a[1] = __fmaf_rn(iv, w0.y, a[1]);
            a[2] = __fmaf_rn(iv, w0.z, a[2]);
            a[3] = __fmaf_rn(iv, w0.w, a[3]);
            a[4] = __fmaf_rn(iv, w1.x, a[4]);
            a[5] = __fmaf_rn(iv, w1.y, a[5]);
            a[6] = __fmaf_rn(iv, w1.z, a[6]);
            a[7] = __fmaf_rn(iv, w1.w, a[7]);
        }
    }
    const int oh = oh0 + ohr, ow = ow0 + owr;
    #pragma unroll
    for (int c = 0; c < 8; c++) {
        float v = __fadd_rn(a[c], bias[cob + c]);
        if (RELU) v = fmaxf(v, 0.f);
        out[(((size_t)n * COUT + cob + c) * OH + oh) * OW + ow] = v;
    }
}

// enc2 (R14: R13 compute; float4 panel staging).
__global__ void __launch_bounds__(512) enc2_k(const float* __restrict__ in,
                                              const float* __restrict__ wt,
                                              const float* __restrict__ bias,
                                              float* __restrict__ out)
{
    extern __shared__ float sm[];
    float* s_in = sm;
    float* s_w  = sm + 128 * 18 * 19;
    const int n = blockIdx.z;
    const int oh0 = (blockIdx.x >> 2) * 8, ow0 = (blockIdx.x & 3) * 8;
    const int tid = threadIdx.x, px = tid & 31, cog = tid >> 5;
    const int ohr = px >> 2, owp = px & 3;
    const int ihb = oh0 * 2 - 1, iwb = ow0 * 2 - 1;

    for (int t = tid; t < 128 * 18 * 18; t += 512) {
        int ci = t / 324, r = t % 324, rr = r / 18, cc = r % 18;
        int ih = ihb + rr, iw = iwb + cc;
        float v = 0.f;
        if (ih >= 0 && ih < 64 && iw >= 0 && iw < 64)
            v = in[(((size_t)n * 128 + ci) * 64 + ih) * 64 + iw];
        s_in[(ci * 18 + rr) * 19 + cc] = v;
    }

    ull a[2][4];
    #pragma unroll
    for (int p = 0; p < 2; p++)
    #pragma unroll
    for (int j = 0; j < 4; j++) a[p][j] = 0ull;

    float4* sw4 = (float4*)s_w;
    #pragma unroll
    for (int kh = 0; kh < 4; kh++)
    #pragma unroll
    for (int kw = 0; kw < 4; kw++) {
        for (int ci0 = 0; ci0 < 128; ci0 += 64) {
            __syncthreads();
            const float4* wp4 =
                (const float4*)(wt + (size_t)((kh * 4 + kw) * 128 + ci0) * 128);
            for (int t = tid; t < 2048; t += 512) sw4[t] = wp4[t];
            __syncthreads();
            const float* ip = &s_in[((ci0 * 18) + ohr * 2 + kh) * 19 + owp * 4 + kw];
            const float* wp = &s_w[cog * 8];
            #pragma unroll 2
            for (int ci = 0; ci < 64; ci++) {
                float i0 = ip[ci * 342];
                float i1 = ip[ci * 342 + 2];
                ull p0 = pack2(i0), p1 = pack2(i1);
                ulonglong2 wA = *(const ulonglong2*)&wp[ci * 128];
                ulonglong2 wB = *(const ulonglong2*)&wp[ci * 128 + 4];
                a[0][0] = fma2(p0, wA.x, a[0][0]);
                a[0][1] = fma2(p0, wA.y, a[0][1]);
                a[0][2] = fma2(p0, wB.x, a[0][2]);
                a[0][3] = fma2(p0, wB.y, a[0][3]);
                a[1][0] = fma2(p1, wA.x, a[1][0]);
                a[1][1] = fma2(p1, wA.y, a[1][1]);
                a[1][2] = fma2(p1, wB.x, a[1][2]);
                a[1][3] = fma2(p1, wB.y, a[1][3]);
            }
        }
    }
    const int oh = oh0 + ohr;
    #pragma unroll
    for (int p = 0; p < 2; p++) {
        int ow = ow0 + owp * 2 + p;
        #pragma unroll
        for (int j = 0; j < 4; j++) {
            int co = cog * 8 + 2 * j;
            float lo, hi;
            unpack2(a[p][j], lo, hi);
            out[(((size_t)n * 128 + co) * 32 + oh) * 32 + ow] =
                fmaxf(__fadd_rn(lo, bias[co]), 0.f);
            out[(((size_t)n * 128 + co + 1) * 32 + oh) * 32 + ow] =
                fmaxf(__fadd_rn(hi, bias[co + 1]), 0.f);
        }
    }
}

// enc3 (R14: R13 compute; float4 panel staging).
__global__ void __launch_bounds__(256) enc3_k(const float* __restrict__ in,
                                              const float* __restrict__ wt,
                                              const float* __restrict__ bias,
                                              float* __restrict__ out)
{
    extern __shared__ float sm[];
    float* s_in = sm;
    float* s_w  = sm + 128 * 10 * 11;
    const int n = blockIdx.z;
    const int oh0 = (blockIdx.x >> 2) * 8, ow0 = (blockIdx.x & 3) * 8;
    const int tid = threadIdx.x, px = tid & 31, cog = tid >> 5;
    const int ohr = px >> 2, owp = px & 3;
    const int ihb = oh0 - 1, iwb = ow0 - 1;

    for (int t = tid; t < 128 * 10 * 10; t += 256) {
        int ci = t / 100, r = t % 100, rr = r / 10, cc = r % 10;
        int ih = ihb + rr, iw = iwb + cc;
        float v = 0.f;
        if (ih >= 0 && ih < 32 && iw >= 0 && iw < 32)
            v = in[(((size_t)n * 128 + ci) * 32 + ih) * 32 + iw];
        s_in[(ci * 10 + rr) * 11 + cc] = v;
    }

    ull a[2][4];
    #pragma unroll
    for (int p = 0; p < 2; p++)
    #pragma unroll
    for (int j = 0; j < 4; j++) a[p][j] = 0ull;

    float4* sw4 = (float4*)s_w;
    #pragma unroll
    for (int kh = 0; kh < 3; kh++)
    #pragma unroll
    for (int kw = 0; kw < 3; kw++) {
        __syncthreads();
        const float4* wp4 = (const float4*)(wt + (size_t)(kh * 3 + kw) * 8192);
        for (int t = tid; t < 2048; t += 256) sw4[t] = wp4[t];
        __syncthreads();
        const float* ip = &s_in[(ohr + kh) * 11 + owp * 2 + kw];
        const float* wp = &s_w[cog * 8];
        #pragma unroll 2
        for (int ci = 0; ci < 128; ci++) {
            float i0 = ip[ci * 110];
            float i1 = ip[ci * 110 + 1];
            ull p0 = pack2(i0), p1 = pack2(i1);
            ulonglong2 wA = *(const ulonglong2*)&wp[ci * 64];
            ulonglong2 wB = *(const ulonglong2*)&wp[ci * 64 + 4];
            a[0][0] = fma2(p0, wA.x, a[0][0]);
            a[0][1] = fma2(p0, wA.y, a[0][1]);
            a[0][2] = fma2(p0, wB.x, a[0][2]);
            a[0][3] = fma2(p0, wB.y, a[0][3]);
            a[1][0] = fma2(p1, wA.x, a[1][0]);
            a[1][1] = fma2(p1, wA.y, a[1][1]);
            a[1][2] = fma2(p1, wB.x, a[1][2]);
            a[1][3] = fma2(p1, wB.y, a[1][3]);
        }
    }
    const int oh = oh0 + ohr;
    #pragma unroll
    for (int p = 0; p < 2; p++) {
        int ow = ow0 + owp * 2 + p;
        #pragma unroll
        for (int j = 0; j < 4; j++) {
            int co = cog * 8 + 2 * j;
            float lo, hi;
            unpack2(a[p][j], lo, hi);
            out[(((size_t)n * 64 + co) * 32 + oh) * 32 + ow] = __fadd_rn(lo, bias[co]);
            out[(((size_t)n * 64 + co + 1) * 32 + oh) * 32 + ow] = __fadd_rn(hi, bias[co + 1]);
        }
    }
}

// VQ (R14: f32x2 dual-codeword chains, bit-exact).
__global__ void __launch_bounds__(256) vq_k(const float* __restrict__ ze,
                                            const float* __restrict__ cb,
                                            float* __restrict__ zq,
                                            float* __restrict__ part)
{
    extern __shared__ float sm[];
    float* s_cbp = sm;            // [256][64][2]
    float* s_cb2 = sm + 32768;    // [512]
    __shared__ float red[256];
    const int tid = threadIdx.x;
    for (int t = tid; t < 32768; t += 256) {
        int j = t & 1, d = (t >> 1) & 63, kp = t >> 7;
        s_cbp[t] = cb[(size_t)(2 * kp + j) * 64 + d];
    }
    __syncthreads();
    for (int k = tid; k < 512; k += 256) {
        const float* cp = &s_cbp[((k >> 1) * 64) * 2 + (k & 1)];
        float s = 0.f;
        for (int d = 0; d < 64; d++) {
            float c = cp[2 * d];
            s = __fadd_rn(s, __fmul_rn(c, c));
        }
        s_cb2[k] = s;
    }
    __syncthreads();

    const int v = blockIdx.x * 256 + tid;
    const int n = v >> 10, hw = v & 1023;
    const float* zp = ze + (size_t)n * 64 * 1024 + hw;
    float z[64];
    #pragma unroll
    for (int d = 0; d < 64; d++) z[d] = zp[(size_t)d * 1024];

    float z2 = 0.f;
    #pragma unroll
    for (int d = 0; d < 64; d++) z2 = __fadd_rn(z2, __fmul_rn(z[d], z[d]));

    float best = 3.4e38f;
    int bi = 0;
    for (int kp0 = 0; kp0 < 256; kp0 += 2) {
        ull dt01 = 0ull, dt23 = 0ull;
        const ull* p0 = (const ull*)&s_cbp[kp0 * 128];
        const ull* p1 = (const ull*)&s_cbp[(kp0 + 1) * 128];
        #pragma unroll
        for (int d = 0; d < 64; d += 2) {
            ulonglong2 ua = *(const ulonglong2*)&p0[d];
            ulonglong2 ub = *(const ulonglong2*)&p1[d];
            ull zd0 = pack2(z[d]), zd1 = pack2(z[d + 1]);
            dt01 = fma2(zd0, ua.x, dt01);
            dt01 = fma2(zd1, ua.y, dt01);
            dt23 = fma2(zd0, ub.x, dt23);
            dt23 = fma2(zd1, ub.y, dt23);
        }
        float dt0, dt1, dt2, dt3;
        unpack2(dt01, dt0, dt1);
        unpack2(dt23, dt2, dt3);
        const int k0 = 2 * kp0;
        float s0 = __fsub_rn(__fadd_rn(z2, s_cb2[k0 + 0]), __fmul_rn(2.f, dt0));
        float s1 = __fsub_rn(__fadd_rn(z2, s_cb2[k0 + 1]), __fmul_rn(2.f, dt1));
        float s2 = __fsub_rn(__fadd_rn(z2, s_cb2[k0 + 2]), __fmul_rn(2.f, dt2));
        float s3 = __fsub_rn(__fadd_rn(z2, s_cb2[k0 + 3]), __fmul_rn(2.f, dt3));
        if (s0 < best) { best = s0; bi = k0; }
        if (s1 < best) { best = s1; bi = k0 + 1; }
        if (s2 < best) { best = s2; bi = k0 + 2; }
        if (s3 < best) { best = s3; bi = k0 + 3; }
    }

    float* zqp = zq + (size_t)n * 64 * 1024 + hw;
    const float* cbi = &s_cbp[((bi >> 1) * 64) * 2 + (bi & 1)];
    float lsum = 0.f;
    #pragma unroll
    for (int d = 0; d < 64; d++) {
        float c = cbi[2 * d];
        float df = z[d] - c;
        lsum = fmaf(df, df, lsum);
        zqp[(size_t)d * 1024] = __fadd_rn(z[d], __fsub_rn(c, z[d]));
    }
    red[tid] = lsum;
    __syncthreads();
    for (int s = 128; s > 0; s >>= 1) {
        if (tid < s) red[tid] += red[tid + s];
        __syncthreads();
    }
    if (tid == 0) part[blockIdx.x] = red[0];
}

// Deconv via mma.sync bf16: one block serves ALL 4 parity classes (patch
// staged once, looped cl). Per-class MMA sequence identical to R14.
template <int CIN, int IHW>
__global__ void __launch_bounds__(256) deconv_mma_k(
    const float* __restrict__ in, const __nv_bfloat16* __restrict__ gB,
    const float* __restrict__ bias, float* __restrict__ out)
{
    constexpr int K = CIN * 4;
    constexpr int NCH = K / 64;
    constexpr int OH = IHW * 2, OW = IHW * 2;
    constexpr int TX = IHW / 16;
    constexpr int PATCH_B = CIN * 180 * 4;
    constexpr int AH_B = PATCH_B, AL_B = AH_B + 18432;
    constexpr int BH_B = AL_B + 18432, BL_B = BH_B + 18432;

    extern __shared__ char smc[];
    float* s_patch = (float*)smc;
    const uint32 sb = smem_u32(smc);

    const int tid = threadIdx.x;
    const int lane = tid & 31, wrp = tid >> 5;
    const int mg = wrp & 3, ng = wrp >> 2;
    const int n = blockIdx.z;
    const int y0 = (blockIdx.x / TX) * 8, x0 = (blockIdx.x % TX) * 16;

    for (int t = tid; t < CIN * 180; t += 256) {
        int ci = t / 180, r = t % 180, rr = r / 18, cc = r % 18;
        int yy = y0 - 1 + rr, xx = x0 - 1 + cc;
        float v = 0.f;
        if (yy >= 0 && yy < IHW && xx >= 0 && xx < IHW)
            v = in[(((size_t)n * CIN + ci) * IHW + yy) * IHW + xx];
        s_patch[t] = v;
    }

    const int am = tid >> 1, aks = (tid & 1) * 32;
    const int a_yl = am >> 4, a_xl = am & 15;

    for (int cl = 0; cl < 4; cl++) {
        const int dh = cl >> 1, dw = cl & 1;
        const int a_pr0 = a_yl + dh + 1, a_pc0 = a_xl + dw + 1;

        float c[2][8][4];
        #pragma unroll
        for (int i = 0; i < 2; i++)
        #pragma unroll
        for (int j = 0; j < 8; j++)
        #pragma unroll
        for (int q = 0; q < 4; q++) c[i][j][q] = 0.f;

        for (int kc = 0; kc < NCH; kc++) {
            __syncthreads();
            {
                uint32* ah = (uint32*)(smc + AH_B);
                uint32* al = (uint32*)(smc + AL_B);
                const int kc16 = kc * 16;
                #pragma unroll 4
                for (int j2 = 0; j2 < 16; j2++) {
                    int k = aks + 2 * j2;
                    int ci = kc16 + (k >> 2);
                    int r = (k >> 1) & 1;
                    const float* pp = &s_patch[(ci * 10 + (a_pr0 - r)) * 18];
                    float v0 = pp[a_pc0];
                    float v1 = pp[a_pc0 - 1];
                    int idx = (am * 72 + k) >> 1;
                    ah[idx] = pkbf2(v0, v1);
                    al[idx] = pkbf2(bfres(v0), bfres(v1));
                }
            }
            {
                const __nv_bfloat16* bh = gB + ((size_t)(cl * 2 + 0) * 128) * K + kc * 64;
                const __nv_bfloat16* bl = gB + ((size_t)(cl * 2 + 1) * 128) * K + kc * 64;
                for (int e = tid; e < 1024; e += 256) {
                    int co = e >> 3, k8 = (e & 7) * 8;
                    uint4 vh = *(const uint4*)(bh + (size_t)co * K + k8);
                    uint4 vl = *(const uint4*)(bl + (size_t)co * K + k8);
                    *(uint4*)(smc + BH_B + (co * 72 + k8) * 2) = vh;
                    *(uint4*)(smc + BL_B + (co * 72 + k8) * 2) = vl;
                }
            }
            __syncthreads();

            #pragma unroll
            for (int k16i = 0; k16i < 4; k16i++) {
                const int k16 = k16i * 16;
                uint32 a_h[2][4], a_l[2][4];
                #pragma unroll
                for (int i = 0; i < 2; i++) {
                    int row = mg * 32 + i * 16 + (lane & 15);
                    uint32 off = (uint32)((row * 72 + k16 + ((lane >> 4) << 3)) * 2);
                    ldm_x4(a_h[i][0], a_h[i][1], a_h[i][2], a_h[i][3], sb + AH_B + off);
                    ldm_x4(a_l[i][0], a_l[i][1], a_l[i][2], a_l[i][3], sb + AL_B + off);
                }
                uint32 b_h[8][2], b_l[8][2];
                #pragma unroll
                for (int j = 0; j < 8; j++) {
                    int nrow = ng * 64 + j * 8 + (lane & 7);
                    uint32 off = (uint32)((nrow * 72 + k16 + (((lane >> 3) & 1) << 3)) * 2);
                    ldm_x2(b_h[j][0], b_h[j][1], sb + BH_B + off);
                    ldm_x2(b_l[j][0], b_l[j][1], sb + BL_B + off);
                }
                #pragma unroll
                for (int i = 0; i < 2; i++)
                #pragma unroll
                for (int j = 0; j < 8; j++) {
                    mma16816(c[i][j], a_h[i], b_h[j]);
                    mma16816(c[i][j], a_h[i], b_l[j]);
                    mma16816(c[i][j], a_l[i], b_h[j]);
                }
            }
        }

        #pragma unroll
        for (int i = 0; i < 2; i++) {
            int row0 = mg * 32 + i * 16 + (lane >> 2);
            #pragma unroll
            for (int rr = 0; rr < 2; rr++) {
                int row = row0 + rr * 8;
                int y_l = row >> 4, x_l = row & 15;
                int oh = 2 * (y0 + y_l) + dh, ow = 2 * (x0 + x_l) + dw;
                size_t ob = ((size_t)n * 128) * OH * OW + (size_t)oh * OW + ow;
                #pragma unroll
                for (int j = 0; j < 8; j++) {
                    int col = ng * 64 + j * 8 + (lane & 3) * 2;
                    float v0 = c[i][j][rr * 2 + 0] + bias[col];
                    float v1 = c[i][j][rr * 2 + 1] + bias[col + 1];
                    out[ob + (size_t)col * OH * OW] = fmaxf(v0, 0.f);
                    out[ob + (size_t)(col + 1) * OH * OW] = fmaxf(v1, 0.f);
                }
            }
        }
    }
}

// dec3: 2 output rows per thread (exact R13).
__global__ void __launch_bounds__(256) dec3_k(const float* __restrict__ in,
                                              const float* __restrict__ wtt,
                                              const float* __restrict__ bias,
                                              const float* __restrict__ x,
                                              float* __restrict__ out,
                                              float* __restrict__ rec_part)
{
    extern __shared__ float sm[];
    float* s_in = sm;
    float* s_w  = sm + 16 * 6 * 130;
    __shared__ float red[256];
    const int n = blockIdx.y, oh0 = blockIdx.x * 4;
    const int tid = threadIdx.x, rg = tid >> 7, col = tid & 127;

    for (int t = tid; t < 128 * 9 * 3; t += 256)
        s_w[(t / 3) * 4 + t % 3] = wtt[t];

    float a[2][3];
    #pragma unroll
    for (int p = 0; p < 2; p++)
    #pragma unroll
    for (int co = 0; co < 3; co++) a[p][co] = 0.f;

    for (int ci0 = 0; ci0 < 128; ci0 += 16) {
        for (int t = tid; t < 16 * 6 * 130; t += 256) {
            int cil = t / 780, r2 = t % 780, rr = r2 / 130, cc = r2 % 130;
            int ih = oh0 - 1 + rr, iw = cc - 1;
            float v = 0.f;
            if (ih >= 0 && ih < 128 && iw >= 0 && iw < 128)
                v = in[(((size_t)n * 128 + ci0 + cil) * 128 + ih) * 128 + iw];
            s_in[t] = v;
        }
        __syncthreads();
        for (int cil = 0; cil < 16; cil++) {
            float riv[4][3];
            const float* bp = &s_in[(cil * 6 + 2 * rg) * 130 + col];
            #pragma unroll
            for (int dr = 0; dr < 4; dr++)
            #pragma unroll
            for (int kw = 0; kw < 3; kw++) riv[dr][kw] = bp[dr * 130 + kw];
            #pragma unroll
            for (int kh = 0; kh < 3; kh++) {
                #pragma unroll
                for (int kw = 0; kw < 3; kw++) {
                    float4 wv = *(const float4*)&s_w[((ci0 + cil) * 9 + kh * 3 + kw) * 4];
                    float iv0 = riv[kh][kw];
                    float iv1 = riv[kh + 1][kw];
                    a[0][0] = fmaf(wv.x, iv0, a[0][0]);
                    a[0][1] = fmaf(wv.y, iv0, a[0][1]);
                    a[0][2] = fmaf(wv.z, iv0, a[0][2]);
                    a[1][0] = fmaf(wv.x, iv1, a[1][0]);
                    a[1][1] = fmaf(wv.y, iv1, a[1][1]);
                    a[1][2] = fmaf(wv.z, iv1, a[1][2]);
                }
            }
        }
        __syncthreads();
    }
    float lsum = 0.f;
    #pragma unroll
    for (int p = 0; p < 2; p++) {
        int oh = oh0 + 2 * rg + p;
        #pragma unroll
        for (int co = 0; co < 3; co++) {
            float v = a[p][co] + bias[co];
            size_t idx = (((size_t)n * 3 + co) * 128 + oh) * 128 + col;
            out[idx] = v;
            float d = v - x[idx];
            lsum = fmaf(d, d, lsum);
        }
    }
    red[tid] = lsum;
    __syncthreads();
    for (int s = 128; s > 0; s >>= 1) {
        if (tid < s) red[tid] += red[tid + s];
        __syncthreads();
    }
    if (tid == 0) rec_part[(size_t)n * 32 + blockIdx.x] = red[0];
}

__global__ void __launch_bounds__(256) finalize_k(const float* __restrict__ rec_part,
                                                  const float* __restrict__ vq_part,
                                                  float* __restrict__ out)
{
    __shared__ double rA[256], rB[256];
    const int tid = threadIdx.x;
    double s = 0.0;
    for (int t = tid; t < 2048; t += 256) s += (double)rec_part[t];
    rA[tid] = s;
    rB[tid] = (double)vq_part[tid];
    __syncthreads();
    for (int st = 128; st > 0; st >>= 1) {
        if (tid < st) { rA[tid] += rA[tid + st]; rB[tid] += rB[tid + st]; }
        __syncthreads();
    }
    if (tid == 0) {
        double recon = rA[0] / 3145728.0;
        double vq    = 1.25 * rB[0] / 4194304.0;
        out[3145728] = (float)(recon + vq);
        out[3145729] = (float)recon;
        out[3145730] = (float)vq;
    }
}

extern "C" void kernel_launch(void* const* d_in, const int* in_sizes, int n_in,
                              void* d_out, int out_size)
{
    (void)in_sizes; (void)n_in; (void)out_size;
    const float* x   = (const float*)d_in[0];
    const float* ew1 = (const float*)d_in[1];
    const float* eb1 = (const float*)d_in[2];
    const float* ew2 = (const float*)d_in[3];
    const float* eb2 = (const float*)d_in[4];
    const float* ew3 = (const float*)d_in[5];
    const float* eb3 = (const float*)d_in[6];
    const float* cb  = (const float*)d_in[7];
    const float* dw1 = (const float*)d_in[8];
    const float* db1 = (const float*)d_in[9];
    const float* dw2 = (const float*)d_in[10];
    const float* db2 = (const float*)d_in[11];
    const float* dw3 = (const float*)d_in[12];
    const float* db3 = (const float*)d_in[13];
    float* out = (float*)d_out;

    void *h1, *h2, *ze, *zq, *dd1, *dd2, *vqp, *recp;
    void *w1t, *w2t, *w3t, *w3dt, *bw1, *bw2;
    cudaGetSymbolAddress(&h1,  g_h1);
    cudaGetSymbolAddress(&h2,  g_h2);
    cudaGetSymbolAddress(&ze,  g_ze);
    cudaGetSymbolAddress(&zq,  g_zq);
    cudaGetSymbolAddress(&dd1, g_d1);
    cudaGetSymbolAddress(&dd2, g_d2);
    cudaGetSymbolAddress(&vqp,  g_vq_part);
    cudaGetSymbolAddress(&recp, g_rec_part);
    cudaGetSymbolAddress(&w1t,  g_w1t);
    cudaGetSymbolAddress(&w2t,  g_w2t);
    cudaGetSymbolAddress(&w3t,  g_w3t);
    cudaGetSymbolAddress(&w3dt, g_w3dt);
    cudaGetSymbolAddress(&bw1,  g_bw1);
    cudaGetSymbolAddress(&bw2,  g_bw2);

    const int SM_E1 = (1028 + 16 * 3 * 64) * 4;
    const int SM_E2 = (128 * 18 * 19 + 64 * 128) * 4;
    const int SM_E3 = (128 * 10 * 11 + 128 * 64) * 4;
    const int SM_M1 = 64 * 180 * 4 + 4 * 18432;
    const int SM_M2 = 128 * 180 * 4 + 4 * 18432;
    const int SM_D3 = (16 * 6 * 130 + 128 * 9 * 4) * 4;
    const int SM_VQ = (32768 + 512) * 4;

    cudaFuncSetAttribute((const void*)enc2_k,
                         cudaFuncAttributeMaxDynamicSharedMemorySize, SM_E2);
    cudaFuncSetAttribute((const void*)enc3_k,
                         cudaFuncAttributeMaxDynamicSharedMemorySize, SM_E3);
    cudaFuncSetAttribute((const void*)deconv_mma_k<64,32>,
                         cudaFuncAttributeMaxDynamicSharedMemorySize, SM_M1);
    cudaFuncSetAttribute((const void*)deconv_mma_k<128,64>,
                         cudaFuncAttributeMaxDynamicSharedMemorySize, SM_M2);
    cudaFuncSetAttribute((const void*)vq_k,
                         cudaFuncAttributeMaxDynamicSharedMemorySize, SM_VQ);
    cudaFuncSetAttribute((const void*)dec3_k,
                         cudaFuncAttributeMaxDynamicSharedMemorySize, SM_D3);

    wprep_k<<<256, 256>>>(ew1, ew2, ew3, dw1, dw2, dw3);
    conv_seq<4,2,3,128,128,true><<<dim3(64, 2, NB), 512, SM_E1>>>(
        x, (const float*)w1t, eb1, (float*)h1);
    enc2_k<<<dim3(16, 1, NB), 512, SM_E2>>>(
        (const float*)h1, (const float*)w2t, eb2, (float*)h2);
    enc3_k<<<dim3(16, 1, NB), 256, SM_E3>>>(
        (const float*)h2, (const float*)w3t, eb3, (float*)ze);
    vq_k<<<256, 256, SM_VQ>>>(
        (const float*)ze, cb, (float*)zq, (float*)vqp);
    deconv_mma_k<64,32><<<dim3(8, 1, NB), 256, SM_M1>>>(
        (const float*)zq, (const __nv_bfloat16*)bw1, db1, (float*)dd1);
    deconv_mma_k<128,64><<<dim3(32, 1, NB), 256, SM_M2>>>(
        (const float*)dd1, (const __nv_bfloat16*)bw2, db2, (float*)dd2);
    dec3_k<<<dim3(32, NB), 256, SM_D3>>>(
        (const float*)dd2, (const float*)w3dt, db3, x, out, (float*)recp);
    finalize_k<<<1, 256>>>(
        (const float*)recp, (const float*)vqp, out);
}

// round 16
// speedup vs baseline: 1.1311x; 1.0129x over previous
#include <cuda_runtime.h>
#include <cuda_bf16.h>
#include <cstdint>
#include <cstddef>

#define NB 64
typedef unsigned long long ull;
typedef unsigned int uint32;

__device__ __forceinline__ ull pack2(float x) {
    ull d; unsigned u = __float_as_uint(x);
    asm("mov.b64 %0, {%1, %1};" : "=l"(d) : "r"(u));
    return d;
}
__device__ __forceinline__ ull fma2(ull a, ull b, ull c) {
    ull d;
    asm("fma.rn.f32x2 %0, %1, %2, %3;" : "=l"(d) : "l"(a), "l"(b), "l"(c));
    return d;
}
__device__ __forceinline__ void unpack2(ull a, float& lo, float& hi) {
    unsigned l, h;
    asm("mov.b64 {%0, %1}, %2;" : "=r"(l), "=r"(h) : "l"(a));
    lo = __uint_as_float(l); hi = __uint_as_float(h);
}
__device__ __forceinline__ uint32 smem_u32(const void* p) {
    uint32 a;
    asm("{ .reg .u64 t; cvta.to.shared.u64 t, %1; cvt.u32.u64 %0, t; }" : "=r"(a) : "l"(p));
    return a;
}
__device__ __forceinline__ void ldm_x4(uint32& r0, uint32& r1, uint32& r2, uint32& r3, uint32 a) {
    asm volatile("ldmatrix.sync.aligned.m8n8.x4.shared.b16 {%0,%1,%2,%3}, [%4];"
                 : "=r"(r0), "=r"(r1), "=r"(r2), "=r"(r3) : "r"(a));
}
__device__ __forceinline__ void ldm_x2(uint32& r0, uint32& r1, uint32 a) {
    asm volatile("ldmatrix.sync.aligned.m8n8.x2.shared.b16 {%0,%1}, [%2];"
                 : "=r"(r0), "=r"(r1) : "r"(a));
}
__device__ __forceinline__ void mma16816(float* c, const uint32* a, const uint32* b) {
    asm volatile(
        "mma.sync.aligned.m16n8k16.row.col.f32.bf16.bf16.f32 "
        "{%0,%1,%2,%3}, {%4,%5,%6,%7}, {%8,%9}, {%0,%1,%2,%3};"
        : "+f"(c[0]), "+f"(c[1]), "+f"(c[2]), "+f"(c[3])
        : "r"(a[0]), "r"(a[1]), "r"(a[2]), "r"(a[3]), "r"(b[0]), "r"(b[1]));
}
__device__ __forceinline__ uint32 pkbf2(float a, float b) {
    return (uint32)__bfloat16_as_ushort(__float2bfloat16(a))
         | ((uint32)__bfloat16_as_ushort(__float2bfloat16(b)) << 16);
}
__device__ __forceinline__ float bfres(float v) {
    return v - __bfloat162float(__float2bfloat16(v));
}

__device__ float g_h1[(size_t)NB * 128 * 64 * 64];
__device__ float g_h2[(size_t)NB * 128 * 32 * 32];
__device__ float g_ze[(size_t)NB * 64 * 32 * 32];
__device__ float g_zq[(size_t)NB * 64 * 32 * 32];
__device__ float g_d1[(size_t)NB * 128 * 64 * 64];
__device__ float g_d2[(size_t)NB * 128 * 128 * 128];
__device__ float g_vq_part[256];
__device__ float g_rec_part[4096];
__device__ float g_w1t[16 * 3 * 128];
__device__ float g_w2t[16 * 128 * 128];
__device__ float g_w3t[9 * 128 * 64];
__device__ float g_w3dt[128 * 9 * 3];
__device__ __align__(16) __nv_bfloat16 g_bw1[4 * 2 * 128 * 256];  // [cl][h][co][K]
__device__ __align__(16) __nv_bfloat16 g_bw2[4 * 2 * 128 * 512];  // [cl][h][co][K]

__global__ void wprep_k(const float* __restrict__ w1, const float* __restrict__ w2,
                        const float* __restrict__ w3, const float* __restrict__ dw1,
                        const float* __restrict__ dw2, const float* __restrict__ dw3)
{
    int st = gridDim.x * blockDim.x, g = blockIdx.x * blockDim.x + threadIdx.x;
    for (int t = g; t < 16 * 3 * 128; t += st) {
        int co = t & 127, r = t >> 7, ci = r % 3, kk = r / 3;
        g_w1t[(kk * 3 + ci) * 128 + co] = w1[((size_t)co * 3 + ci) * 16 + kk];
    }
    for (int t = g; t < 16 * 128 * 128; t += st) {
        int co = t & 127, r = t >> 7, ci = r & 127, kk = r >> 7;
        g_w2t[(kk * 128 + ci) * 128 + co] = w2[((size_t)co * 128 + ci) * 16 + kk];
    }
    for (int t = g; t < 9 * 128 * 64; t += st) {
        int co = t & 63, r = t >> 6, ci = r & 127, kk = r >> 7;
        g_w3t[(kk * 128 + ci) * 64 + co] = w3[((size_t)co * 128 + ci) * 9 + kk];
    }
    for (int t = g; t < 128 * 9 * 3; t += st) {
        int co = t % 3, r = t / 3, kk = r % 9, ci = r / 9;
        g_w3dt[t] = dw3[((size_t)co * 128 + ci) * 9 + kk];
    }
    for (int t = g; t < 4 * 2 * 128 * 256; t += st) {
        int k = t & 255, r2 = t >> 8, co = r2 & 127, h = (r2 >> 7) & 1, cl = r2 >> 8;
        int ci = k >> 2, rr = (k >> 1) & 1, cc = k & 1;
        int dh = cl >> 1, dw = cl & 1;
        float w = dw1[((size_t)ci * 128 + co) * 16 + (1 - dh + 2 * rr) * 4 + (1 - dw + 2 * cc)];
        g_bw1[t] = __float2bfloat16(h ? bfres(w) : w);
    }
    for (int t = g; t < 4 * 2 * 128 * 512; t += st) {
        int k = t & 511, r2 = t >> 9, co = r2 & 127, h = (r2 >> 7) & 1, cl = r2 >> 8;
        int ci = k >> 2, rr = (k >> 1) & 1, cc = k & 1;
        int dh = cl >> 1, dw = cl & 1;
        float w = dw2[((size_t)ci * 128 + co) * 16 + (1 - dh + 2 * rr) * 4 + (1 - dw + 2 * cc)];
        g_bw2[t] = __float2bfloat16(h ? bfres(w) : w);
    }
}

// enc1: bit-exact scalar chain; all weights resident, single sync (R13).
template <int K, int S, int CIN, int COUT, int H, bool RELU>
__global__ void __launch_bounds__(512) conv_seq(const float* __restrict__ in,
                                                const float* __restrict__ wt,
                                                const float* __restrict__ bias,
                                                float* __restrict__ out)
{
    constexpr int W = H, OH = (H + 2 - K) / S + 1, OW = OH;
    constexpr int IHS = 7 * S + K, IWS = 7 * S + K, IWP = IWS + 1;
    constexpr int SW_OFF = ((CIN * IHS * IWP + 3) / 4) * 4;
    constexpr int WN = K * K * CIN * 64;
    extern __shared__ float sm[];
    float* s_in = sm;
    float* s_w  = sm + SW_OFF;
    const int n = blockIdx.z, co0 = blockIdx.y * 64;
    constexpr int TWn = OW / 8;
    const int oh0 = (blockIdx.x / TWn) * 8, ow0 = (blockIdx.x % TWn) * 8;
    const int tid = threadIdx.x, px = tid & 63, cog = tid >> 6;
    const int ohr = px >> 3, owr = px & 7;
    const int ihb = oh0 * S - 1, iwb = ow0 * S - 1;

    for (int t = tid; t < CIN * IHS * IWS; t += 512) {
        int ci = t / (IHS * IWS), r = t % (IHS * IWS), rr = r / IWS, cc = r % IWS;
        int ih = ihb + rr, iw = iwb + cc;
        float v = 0.f;
        if (ih >= 0 && ih < H && iw >= 0 && iw < W)
            v = in[(((size_t)n * CIN + ci) * H + ih) * W + iw];
        s_in[(ci * IHS + rr) * IWP + cc] = v;
    }
    for (int t = tid; t < WN; t += 512)
        s_w[t] = wt[(size_t)(t >> 6) * COUT + co0 + (t & 63)];
    __syncthreads();

    const int cob = co0 + cog * 8;
    float a[8];
    #pragma unroll
    for (int i = 0; i < 8; i++) a[i] = 0.f;
    #pragma unroll
    for (int kh = 0; kh < K; kh++)
    #pragma unroll
    for (int kw = 0; kw < K; kw++) {
        const float* ip = &s_in[(ohr * S + kh) * IWP + owr * S + kw];
        const float* wp = &s_w[((kh * K + kw) * CIN) * 64 + cog * 8];
        #pragma unroll 3
        for (int ci = 0; ci < CIN; ci++) {
            float iv = ip[ci * IHS * IWP];
            float4 w0 = *(const float4*)&wp[ci * 64];
            float4 w1 = *(const float4*)&wp[ci * 64 + 4];
            a[0] = __fmaf_rn(iv, w0.x, a[0]);
            a[1] = __fmaf_rn(iv, w0.y, a[1]);
            a[2] = __fmaf_rn(iv, w0.z, a[2]);
            a[3] = __fmaf_rn(iv, w0.w, a[3]);
            a[4] = __fmaf_rn(iv, w1.x, a[4]);
            a[5] = __fmaf_rn(iv, w1.y, a[5]);
            a[6] = __fmaf_rn(iv, w1.z, a[6]);
            a[7] = __fmaf_rn(iv, w1.w, a[7]);
        }
    }
    const int oh = oh0 + ohr, ow = ow0 + owr;
    #pragma unroll
    for (int c = 0; c < 8; c++) {
        float v = __fadd_rn(a[c], bias[cob + c]);
        if (RELU) v = fmaxf(v, 0.f);
        out[(((size_t)n * COUT + cob + c) * OH + oh) * OW + ow] = v;
    }
}

// enc2 (R14 + ci unroll 4).
__global__ void __launch_bounds__(512) enc2_k(const float* __restrict__ in,
                                              const float* __restrict__ wt,
                                              const float* __restrict__ bias,
                                              float* __restrict__ out)
{
    extern __shared__ float sm[];
    float* s_in = sm;
    float* s_w  = sm + 128 * 18 * 19;
    const int n = blockIdx.z;
    const int oh0 = (blockIdx.x >> 2) * 8, ow0 = (blockIdx.x & 3) * 8;
    const int tid = threadIdx.x, px = tid & 31, cog = tid >> 5;
    const int ohr = px >> 2, owp = px & 3;
    const int ihb = oh0 * 2 - 1, iwb = ow0 * 2 - 1;

    for (int t = tid; t < 128 * 18 * 18; t += 512) {
        int ci = t / 324, r = t % 324, rr = r / 18, cc = r % 18;
        int ih = ihb + rr, iw = iwb + cc;
        float v = 0.f;
        if (ih >= 0 && ih < 64 && iw >= 0 && iw < 64)
            v = in[(((size_t)n * 128 + ci) * 64 + ih) * 64 + iw];
        s_in[(ci * 18 + rr) * 19 + cc] = v;
    }

    ull a[2][4];
    #pragma unroll
    for (int p = 0; p < 2; p++)
    #pragma unroll
    for (int j = 0; j < 4; j++) a[p][j] = 0ull;

    float4* sw4 = (float4*)s_w;
    #pragma unroll
    for (int kh = 0; kh < 4; kh++)
    #pragma unroll
    for (int kw = 0; kw < 4; kw++) {
        for (int ci0 = 0; ci0 < 128; ci0 += 64) {
            __syncthreads();
            const float4* wp4 =
                (const float4*)(wt + (size_t)((kh * 4 + kw) * 128 + ci0) * 128);
            for (int t = tid; t < 2048; t += 512) sw4[t] = wp4[t];
            __syncthreads();
            const float* ip = &s_in[((ci0 * 18) + ohr * 2 + kh) * 19 + owp * 4 + kw];
            const float* wp = &s_w[cog * 8];
            #pragma unroll 4
            for (int ci = 0; ci < 64; ci++) {
                float i0 = ip[ci * 342];
                float i1 = ip[ci * 342 + 2];
                ull p0 = pack2(i0), p1 = pack2(i1);
                ulonglong2 wA = *(const ulonglong2*)&wp[ci * 128];
                ulonglong2 wB = *(const ulonglong2*)&wp[ci * 128 + 4];
                a[0][0] = fma2(p0, wA.x, a[0][0]);
                a[0][1] = fma2(p0, wA.y, a[0][1]);
                a[0][2] = fma2(p0, wB.x, a[0][2]);
                a[0][3] = fma2(p0, wB.y, a[0][3]);
                a[1][0] = fma2(p1, wA.x, a[1][0]);
                a[1][1] = fma2(p1, wA.y, a[1][1]);
                a[1][2] = fma2(p1, wB.x, a[1][2]);
                a[1][3] = fma2(p1, wB.y, a[1][3]);
            }
        }
    }
    const int oh = oh0 + ohr;
    #pragma unroll
    for (int p = 0; p < 2; p++) {
        int ow = ow0 + owp * 2 + p;
        #pragma unroll
        for (int j = 0; j < 4; j++) {
            int co = cog * 8 + 2 * j;
            float lo, hi;
            unpack2(a[p][j], lo, hi);
            out[(((size_t)n * 128 + co) * 32 + oh) * 32 + ow] =
                fmaxf(__fadd_rn(lo, bias[co]), 0.f);
            out[(((size_t)n * 128 + co + 1) * 32 + oh) * 32 + ow] =
                fmaxf(__fadd_rn(hi, bias[co + 1]), 0.f);
        }
    }
}

// enc3 (R14 + ci unroll 4).
__global__ void __launch_bounds__(256) enc3_k(const float* __restrict__ in,
                                              const float* __restrict__ wt,
                                              const float* __restrict__ bias,
                                              float* __restrict__ out)
{
    extern __shared__ float sm[];
    float* s_in = sm;
    float* s_w  = sm + 128 * 10 * 11;
    const int n = blockIdx.z;
    const int oh0 = (blockIdx.x >> 2) * 8, ow0 = (blockIdx.x & 3) * 8;
    const int tid = threadIdx.x, px = tid & 31, cog = tid >> 5;
    const int ohr = px >> 2, owp = px & 3;
    const int ihb = oh0 - 1, iwb = ow0 - 1;

    for (int t = tid; t < 128 * 10 * 10; t += 256) {
        int ci = t / 100, r = t % 100, rr = r / 10, cc = r % 10;
        int ih = ihb + rr, iw = iwb + cc;
        float v = 0.f;
        if (ih >= 0 && ih < 32 && iw >= 0 && iw < 32)
            v = in[(((size_t)n * 128 + ci) * 32 + ih) * 32 + iw];
        s_in[(ci * 10 + rr) * 11 + cc] = v;
    }

    ull a[2][4];
    #pragma unroll
    for (int p = 0; p < 2; p++)
    #pragma unroll
    for (int j = 0; j < 4; j++) a[p][j] = 0ull;

    float4* sw4 = (float4*)s_w;
    #pragma unroll
    for (int kh = 0; kh < 3; kh++)
    #pragma unroll
    for (int kw = 0; kw < 3; kw++) {
        __syncthreads();
        const float4* wp4 = (const float4*)(wt + (size_t)(kh * 3 + kw) * 8192);
        for (int t = tid; t < 2048; t += 256) sw4[t] = wp4[t];
        __syncthreads();
        const float* ip = &s_in[(ohr + kh) * 11 + owp * 2 + kw];
        const float* wp = &s_w[cog * 8];
        #pragma unroll 4
        for (int ci = 0; ci < 128; ci++) {
            float i0 = ip[ci * 110];
            float i1 = ip[ci * 110 + 1];
            ull p0 = pack2(i0), p1 = pack2(i1);
            ulonglong2 wA = *(const ulonglong2*)&wp[ci * 64];
            ulonglong2 wB = *(const ulonglong2*)&wp[ci * 64 + 4];
            a[0][0] = fma2(p0, wA.x, a[0][0]);
            a[0][1] = fma2(p0, wA.y, a[0][1]);
            a[0][2] = fma2(p0, wB.x, a[0][2]);
            a[0][3] = fma2(p0, wB.y, a[0][3]);
            a[1][0] = fma2(p1, wA.x, a[1][0]);
            a[1][1] = fma2(p1, wA.y, a[1][1]);
            a[1][2] = fma2(p1, wB.x, a[1][2]);
            a[1][3] = fma2(p1, wB.y, a[1][3]);
        }
    }
    const int oh = oh0 + ohr;
    #pragma unroll
    for (int p = 0; p < 2; p++) {
        int ow = ow0 + owp * 2 + p;
        #pragma unroll
        for (int j = 0; j < 4; j++) {
            int co = cog * 8 + 2 * j;
            float lo, hi;
            unpack2(a[p][j], lo, hi);
            out[(((size_t)n * 64 + co) * 32 + oh) * 32 + ow] = __fadd_rn(lo, bias[co]);
            out[(((size_t)n * 64 + co + 1) * 32 + oh) * 32 + ow] = __fadd_rn(hi, bias[co + 1]);
        }
    }
}

// VQ (R14: f32x2 dual-codeword chains, bit-exact).
__global__ void __launch_bounds__(256) vq_k(const float* __restrict__ ze,
                                            const float* __restrict__ cb,
                                            float* __restrict__ zq,
                                            float* __restrict__ part)
{
    extern __shared__ float sm[];
    float* s_cbp = sm;            // [256][64][2]
    float* s_cb2 = sm + 32768;    // [512]
    __shared__ float red[256];
    const int tid = threadIdx.x;
    for (int t = tid; t < 32768; t += 256) {
        int j = t & 1, d = (t >> 1) & 63, kp = t >> 7;
        s_cbp[t] = cb[(size_t)(2 * kp + j) * 64 + d];
    }
    __syncthreads();
    for (int k = tid; k < 512; k += 256) {
        const float* cp = &s_cbp[((k >> 1) * 64) * 2 + (k & 1)];
        float s = 0.f;
        for (int d = 0; d < 64; d++) {
            float c = cp[2 * d];
            s = __fadd_rn(s, __fmul_rn(c, c));
        }
        s_cb2[k] = s;
    }
    __syncthreads();

    const int v = blockIdx.x * 256 + tid;
    const int n = v >> 10, hw = v & 1023;
    const float* zp = ze + (size_t)n * 64 * 1024 + hw;
    float z[64];
    #pragma unroll
    for (int d = 0; d < 64; d++) z[d] = zp[(size_t)d * 1024];

    float z2 = 0.f;
    #pragma unroll
    for (int d = 0; d < 64; d++) z2 = __fadd_rn(z2, __fmul_rn(z[d], z[d]));

    float best = 3.4e38f;
    int bi = 0;
    for (int kp0 = 0; kp0 < 256; kp0 += 2) {
        ull dt01 = 0ull, dt23 = 0ull;
        const ull* p0 = (const ull*)&s_cbp[kp0 * 128];
        const ull* p1 = (const ull*)&s_cbp[(kp0 + 1) * 128];
        #pragma unroll
        for (int d = 0; d < 64; d += 2) {
            ulonglong2 ua = *(const ulonglong2*)&p0[d];
            ulonglong2 ub = *(const ulonglong2*)&p1[d];
            ull zd0 = pack2(z[d]), zd1 = pack2(z[d + 1]);
            dt01 = fma2(zd0, ua.x, dt01);
            dt01 = fma2(zd1, ua.y, dt01);
            dt23 = fma2(zd0, ub.x, dt23);
            dt23 = fma2(zd1, ub.y, dt23);
        }
        float dt0, dt1, dt2, dt3;
        unpack2(dt01, dt0, dt1);
        unpack2(dt23, dt2, dt3);
        const int k0 = 2 * kp0;
        float s0 = __fsub_rn(__fadd_rn(z2, s_cb2[k0 + 0]), __fmul_rn(2.f, dt0));
        float s1 = __fsub_rn(__fadd_rn(z2, s_cb2[k0 + 1]), __fmul_rn(2.f, dt1));
        float s2 = __fsub_rn(__fadd_rn(z2, s_cb2[k0 + 2]), __fmul_rn(2.f, dt2));
        float s3 = __fsub_rn(__fadd_rn(z2, s_cb2[k0 + 3]), __fmul_rn(2.f, dt3));
        if (s0 < best) { best = s0; bi = k0; }
        if (s1 < best) { best = s1; bi = k0 + 1; }
        if (s2 < best) { best = s2; bi = k0 + 2; }
        if (s3 < best) { best = s3; bi = k0 + 3; }
    }

    float* zqp = zq + (size_t)n * 64 * 1024 + hw;
    const float* cbi = &s_cbp[((bi >> 1) * 64) * 2 + (bi & 1)];
    float lsum = 0.f;
    #pragma unroll
    for (int d = 0; d < 64; d++) {
        float c = cbi[2 * d];
        float df = z[d] - c;
        lsum = fmaf(df, df, lsum);
        zqp[(size_t)d * 1024] = __fadd_rn(z[d], __fsub_rn(c, z[d]));
    }
    red[tid] = lsum;
    __syncthreads();
    for (int s = 128; s > 0; s >>= 1) {
        if (tid < s) red[tid] += red[tid + s];
        __syncthreads();
    }
    if (tid == 0) part[blockIdx.x] = red[0];
}

// Deconv via mma.sync bf16 (R15: class-folded, patch staged once).
template <int CIN, int IHW>
__global__ void __launch_bounds__(256) deconv_mma_k(
    const float* __restrict__ in, const __nv_bfloat16* __restrict__ gB,
    const float* __restrict__ bias, float* __restrict__ out)
{
    constexpr int K = CIN * 4;
    constexpr int NCH = K / 64;
    constexpr int OH = IHW * 2, OW = IHW * 2;
    constexpr int TX = IHW / 16;
    constexpr int PATCH_B = CIN * 180 * 4;
    constexpr int AH_B = PATCH_B, AL_B = AH_B + 18432;
    constexpr int BH_B = AL_B + 18432, BL_B = BH_B + 18432;

    extern __shared__ char smc[];
    float* s_patch = (float*)smc;
    const uint32 sb = smem_u32(smc);

    const int tid = threadIdx.x;
    const int lane = tid & 31, wrp = tid >> 5;
    const int mg = wrp & 3, ng = wrp >> 2;
    const int n = blockIdx.z;
    const int y0 = (blockIdx.x / TX) * 8, x0 = (blockIdx.x % TX) * 16;

    for (int t = tid; t < CIN * 180; t += 256) {
        int ci = t / 180, r = t % 180, rr = r / 18, cc = r % 18;
        int yy = y0 - 1 + rr, xx = x0 - 1 + cc;
        float v = 0.f;
        if (yy >= 0 && yy < IHW && xx >= 0 && xx < IHW)
            v = in[(((size_t)n * CIN + ci) * IHW + yy) * IHW + xx];
        s_patch[t] = v;
    }

    const int am = tid >> 1, aks = (tid & 1) * 32;
    const int a_yl = am >> 4, a_xl = am & 15;

    for (int cl = 0; cl < 4; cl++) {
        const int dh = cl >> 1, dw = cl & 1;
        const int a_pr0 = a_yl + dh + 1, a_pc0 = a_xl + dw + 1;

        float c[2][8][4];
        #pragma unroll
        for (int i = 0; i < 2; i++)
        #pragma unroll
        for (int j = 0; j < 8; j++)
        #pragma unroll
        for (int q = 0; q < 4; q++) c[i][j][q] = 0.f;

        for (int kc = 0; kc < NCH; kc++) {
            __syncthreads();
            {
                uint32* ah = (uint32*)(smc + AH_B);
                uint32* al = (uint32*)(smc + AL_B);
                const int kc16 = kc * 16;
                #pragma unroll 4
                for (int j2 = 0; j2 < 16; j2++) {
                    int k = aks + 2 * j2;
                    int ci = kc16 + (k >> 2);
                    int r = (k >> 1) & 1;
                    const float* pp = &s_patch[(ci * 10 + (a_pr0 - r)) * 18];
                    float v0 = pp[a_pc0];
                    float v1 = pp[a_pc0 - 1];
                    int idx = (am * 72 + k) >> 1;
                    ah[idx] = pkbf2(v0, v1);
                    al[idx] = pkbf2(bfres(v0), bfres(v1));
                }
            }
            {
                const __nv_bfloat16* bh = gB + ((size_t)(cl * 2 + 0) * 128) * K + kc * 64;
                const __nv_bfloat16* bl = gB + ((size_t)(cl * 2 + 1) * 128) * K + kc * 64;
                for (int e = tid; e < 1024; e += 256) {
                    int co = e >> 3, k8 = (e & 7) * 8;
                    uint4 vh = *(const uint4*)(bh + (size_t)co * K + k8);
                    uint4 vl = *(const uint4*)(bl + (size_t)co * K + k8);
                    *(uint4*)(smc + BH_B + (co * 72 + k8) * 2) = vh;
                    *(uint4*)(smc + BL_B + (co * 72 + k8) * 2) = vl;
                }
            }
            __syncthreads();

            #pragma unroll
            for (int k16i = 0; k16i < 4; k16i++) {
                const int k16 = k16i * 16;
                uint32 a_h[2][4], a_l[2][4];
                #pragma unroll
                for (int i = 0; i < 2; i++) {
                    int row = mg * 32 + i * 16 + (lane & 15);
                    uint32 off = (uint32)((row * 72 + k16 + ((lane >> 4) << 3)) * 2);
                    ldm_x4(a_h[i][0], a_h[i][1], a_h[i][2], a_h[i][3], sb + AH_B + off);
                    ldm_x4(a_l[i][0], a_l[i][1], a_l[i][2], a_l[i][3], sb + AL_B + off);
                }
                uint32 b_h[8][2], b_l[8][2];
                #pragma unroll
                for (int j = 0; j < 8; j++) {
                    int nrow = ng * 64 + j * 8 + (lane & 7);
                    uint32 off = (uint32)((nrow * 72 + k16 + (((lane >> 3) & 1) << 3)) * 2);
                    ldm_x2(b_h[j][0], b_h[j][1], sb + BH_B + off);
                    ldm_x2(b_l[j][0], b_l[j][1], sb + BL_B + off);
                }
                #pragma unroll
                for (int i = 0; i < 2; i++)
                #pragma unroll
                for (int j = 0; j < 8; j++) {
                    mma16816(c[i][j], a_h[i], b_h[j]);
                    mma16816(c[i][j], a_h[i], b_l[j]);
                    mma16816(c[i][j], a_l[i], b_h[j]);
                }
            }
        }

        #pragma unroll
        for (int i = 0; i < 2; i++) {
            int row0 = mg * 32 + i * 16 + (lane >> 2);
            #pragma unroll
            for (int rr = 0; rr < 2; rr++) {
                int row = row0 + rr * 8;
                int y_l = row >> 4, x_l = row & 15;
                int oh = 2 * (y0 + y_l) + dh, ow = 2 * (x0 + x_l) + dw;
                size_t ob = ((size_t)n * 128) * OH * OW + (size_t)oh * OW + ow;
                #pragma unroll
                for (int j = 0; j < 8; j++) {
                    int col = ng * 64 + j * 8 + (lane & 3) * 2;
                    float v0 = c[i][j][rr * 2 + 0] + bias[col];
                    float v1 = c[i][j][rr * 2 + 1] + bias[col + 1];
                    out[ob + (size_t)col * OH * OW] = fmaxf(v0, 0.f);
                    out[ob + (size_t)(col + 1) * OH * OW] = fmaxf(v1, 0.f);
                }
            }
        }
    }
}

// dec3: 8-row tiles, 512 threads, 2 rows/thread; chain order identical.
__global__ void __launch_bounds__(512) dec3_k(const float* __restrict__ in,
                                              const float* __restrict__ wtt,
                                              const float* __restrict__ bias,
                                              const float* __restrict__ x,
                                              float* __restrict__ out,
                                              float* __restrict__ rec_part)
{
    extern __shared__ float sm[];
    float* s_in = sm;                    // [16][10][130]
    float* s_w  = sm + 16 * 10 * 130;    // [128*9][4]
    __shared__ float red[512];
    const int n = blockIdx.y, oh0 = blockIdx.x * 8;
    const int tid = threadIdx.x, rg = tid >> 7, col = tid & 127;

    for (int t = tid; t < 128 * 9 * 3; t += 512)
        s_w[(t / 3) * 4 + t % 3] = wtt[t];

    float a[2][3];
    #pragma unroll
    for (int p = 0; p < 2; p++)
    #pragma unroll
    for (int co = 0; co < 3; co++) a[p][co] = 0.f;

    for (int ci0 = 0; ci0 < 128; ci0 += 16) {
        for (int t = tid; t < 16 * 10 * 130; t += 512) {
            int cil = t / 1300, r2 = t % 1300, rr = r2 / 130, cc = r2 % 130;
            int ih = oh0 - 1 + rr, iw = cc - 1;
            float v = 0.f;
            if (ih >= 0 && ih < 128 && iw >= 0 && iw < 128)
                v = in[(((size_t)n * 128 + ci0 + cil) * 128 + ih) * 128 + iw];
            s_in[t] = v;
        }
        __syncthreads();
        for (int cil = 0; cil < 16; cil++) {
            float riv[4][3];
            const float* bp = &s_in[(cil * 10 + 2 * rg) * 130 + col];
            #pragma unroll
            for (int dr = 0; dr < 4; dr++)
            #pragma unroll
            for (int kw = 0; kw < 3; kw++) riv[dr][kw] = bp[dr * 130 + kw];
            #pragma unroll
            for (int kh = 0; kh < 3; kh++) {
                #pragma unroll
                for (int kw = 0; kw < 3; kw++) {
                    float4 wv = *(const float4*)&s_w[((ci0 + cil) * 9 + kh * 3 + kw) * 4];
                    float iv0 = riv[kh][kw];
                    float iv1 = riv[kh + 1][kw];
                    a[0][0] = fmaf(wv.x, iv0, a[0][0]);
                    a[0][1] = fmaf(wv.y, iv0, a[0][1]);
                    a[0][2] = fmaf(wv.z, iv0, a[0][2]);
                    a[1][0] = fmaf(wv.x, iv1, a[1][0]);
                    a[1][1] = fmaf(wv.y, iv1, a[1][1]);
                    a[1][2] = fmaf(wv.z, iv1, a[1][2]);
                }
            }
        }
        __syncthreads();
    }
    float lsum = 0.f;
    #pragma unroll
    for (int p = 0; p < 2; p++) {
        int oh = oh0 + 2 * rg + p;
        #pragma unroll
        for (int co = 0; co < 3; co++) {
            float v = a[p][co] + bias[co];
            size_t idx = (((size_t)n * 3 + co) * 128 + oh) * 128 + col;
            out[idx] = v;
            float d = v - x[idx];
            lsum = fmaf(d, d, lsum);
        }
    }
    red[tid] = lsum;
    __syncthreads();
    for (int s = 256; s > 0; s >>= 1) {
        if (tid < s) red[tid] += red[tid + s];
        __syncthreads();
    }
    if (tid == 0) rec_part[(size_t)n * 16 + blockIdx.x] = red[0];
}

__global__ void __launch_bounds__(256) finalize_k(const float* __restrict__ rec_part,
                                                  const float* __restrict__ vq_part,
                                                  float* __restrict__ out)
{
    __shared__ double rA[256], rB[256];
    const int tid = threadIdx.x;
    double s = 0.0;
    for (int t = tid; t < 1024; t += 256) s += (double)rec_part[t];
    rA[tid] = s;
    rB[tid] = (double)vq_part[tid];
    __syncthreads();
    for (int st = 128; st > 0; st >>= 1) {
        if (tid < st) { rA[tid] += rA[tid + st]; rB[tid] += rB[tid + st]; }
        __syncthreads();
    }
    if (tid == 0) {
        double recon = rA[0] / 3145728.0;
        double vq    = 1.25 * rB[0] / 4194304.0;
        out[3145728] = (float)(recon + vq);
        out[3145729] = (float)recon;
        out[3145730] = (float)vq;
    }
}

extern "C" void kernel_launch(void* const* d_in, const int* in_sizes, int n_in,
                              void* d_out, int out_size)
{
    (void)in_sizes; (void)n_in; (void)out_size;
    const float* x   = (const float*)d_in[0];
    const float* ew1 = (const float*)d_in[1];
    const float* eb1 = (const float*)d_in[2];
    const float* ew2 = (const float*)d_in[3];
    const float* eb2 = (const float*)d_in[4];
    const float* ew3 = (const float*)d_in[5];
    const float* eb3 = (const float*)d_in[6];
    const float* cb  = (const float*)d_in[7];
    const float* dw1 = (const float*)d_in[8];
    const float* db1 = (const float*)d_in[9];
    const float* dw2 = (const float*)d_in[10];
    const float* db2 = (const float*)d_in[11];
    const float* dw3 = (const float*)d_in[12];
    const float* db3 = (const float*)d_in[13];
    float* out = (float*)d_out;

    void *h1, *h2, *ze, *zq, *dd1, *dd2, *vqp, *recp;
    void *w1t, *w2t, *w3t, *w3dt, *bw1, *bw2;
    cudaGetSymbolAddress(&h1,  g_h1);
    cudaGetSymbolAddress(&h2,  g_h2);
    cudaGetSymbolAddress(&ze,  g_ze);
    cudaGetSymbolAddress(&zq,  g_zq);
    cudaGetSymbolAddress(&dd1, g_d1);
    cudaGetSymbolAddress(&dd2, g_d2);
    cudaGetSymbolAddress(&vqp,  g_vq_part);
    cudaGetSymbolAddress(&recp, g_rec_part);
    cudaGetSymbolAddress(&w1t,  g_w1t);
    cudaGetSymbolAddress(&w2t,  g_w2t);
    cudaGetSymbolAddress(&w3t,  g_w3t);
    cudaGetSymbolAddress(&w3dt, g_w3dt);
    cudaGetSymbolAddress(&bw1,  g_bw1);
    cudaGetSymbolAddress(&bw2,  g_bw2);

    const int SM_E1 = (1028 + 16 * 3 * 64) * 4;
    const int SM_E2 = (128 * 18 * 19 + 64 * 128) * 4;
    const int SM_E3 = (128 * 10 * 11 + 128 * 64) * 4;
    const int SM_M1 = 64 * 180 * 4 + 4 * 18432;
    const int SM_M2 = 128 * 180 * 4 + 4 * 18432;
    const int SM_D3 = (16 * 10 * 130 + 128 * 9 * 4) * 4;   // 101632
    const int SM_VQ = (32768 + 512) * 4;

    cudaFuncSetAttribute((const void*)enc2_k,
                         cudaFuncAttributeMaxDynamicSharedMemorySize, SM_E2);
    cudaFuncSetAttribute((const void*)enc3_k,
                         cudaFuncAttributeMaxDynamicSharedMemorySize, SM_E3);
    cudaFuncSetAttribute((const void*)deconv_mma_k<64,32>,
                         cudaFuncAttributeMaxDynamicSharedMemorySize, SM_M1);
    cudaFuncSetAttribute((const void*)deconv_mma_k<128,64>,
                         cudaFuncAttributeMaxDynamicSharedMemorySize, SM_M2);
    cudaFuncSetAttribute((const void*)vq_k,
                         cudaFuncAttributeMaxDynamicSharedMemorySize, SM_VQ);
    cudaFuncSetAttribute((const void*)dec3_k,
                         cudaFuncAttributeMaxDynamicSharedMemorySize, SM_D3);

    wprep_k<<<256, 256>>>(ew1, ew2, ew3, dw1, dw2, dw3);
    conv_seq<4,2,3,128,128,true><<<dim3(64, 2, NB), 512, SM_E1>>>(
        x, (const float*)w1t, eb1, (float*)h1);
    enc2_k<<<dim3(16, 1, NB), 512, SM_E2>>>(
        (const float*)h1, (const float*)w2t, eb2, (float*)h2);
    enc3_k<<<dim3(16, 1, NB), 256, SM_E3>>>(
        (const float*)h2, (const float*)w3t, eb3, (float*)ze);
    vq_k<<<256, 256, SM_VQ>>>(
        (const float*)ze, cb, (float*)zq, (float*)vqp);
    deconv_mma_k<64,32><<<dim3(8, 1, NB), 256, SM_M1>>>(
        (const float*)zq, (const __nv_bfloat16*)bw1, db1, (float*)dd1);
    deconv_mma_k<128,64><<<dim3(32, 1, NB), 256, SM_M2>>>(
        (const float*)dd1, (const __nv_bfloat16*)bw2, db2, (float*)dd2);
    dec3_k<<<dim3(16, NB), 512, SM_D3>>>(
        (const float*)dd2, (const float*)w3dt, db3, x, out, (float*)recp);
    finalize_k<<<1, 256>>>(
        (const float*)recp, (const float*)vqp, out);
}

// round 17
// speedup vs baseline: 1.1320x; 1.0009x over previous
#include <cuda_runtime.h>
#include <cuda_bf16.h>
#include <cstdint>
#include <cstddef>

#define NB 64
typedef unsigned long long ull;
typedef unsigned int uint32;

__device__ __forceinline__ ull pack2(float x) {
    ull d; unsigned u = __float_as_uint(x);
    asm("mov.b64 %0, {%1, %1};" : "=l"(d) : "r"(u));
    return d;
}
__device__ __forceinline__ ull fma2(ull a, ull b, ull c) {
    ull d;
    asm("fma.rn.f32x2 %0, %1, %2, %3;" : "=l"(d) : "l"(a), "l"(b), "l"(c));
    return d;
}
__device__ __forceinline__ void unpack2(ull a, float& lo, float& hi) {
    unsigned l, h;
    asm("mov.b64 {%0, %1}, %2;" : "=r"(l), "=r"(h) : "l"(a));
    lo = __uint_as_float(l); hi = __uint_as_float(h);
}
__device__ __forceinline__ uint32 smem_u32(const void* p) {
    uint32 a;
    asm("{ .reg .u64 t; cvta.to.shared.u64 t, %1; cvt.u32.u64 %0, t; }" : "=r"(a) : "l"(p));
    return a;
}
__device__ __forceinline__ void ldm_x4(uint32& r0, uint32& r1, uint32& r2, uint32& r3, uint32 a) {
    asm volatile("ldmatrix.sync.aligned.m8n8.x4.shared.b16 {%0,%1,%2,%3}, [%4];"
                 : "=r"(r0), "=r"(r1), "=r"(r2), "=r"(r3) : "r"(a));
}
__device__ __forceinline__ void mma16816(float* c, const uint32* a, const uint32* b) {
    asm volatile(
        "mma.sync.aligned.m16n8k16.row.col.f32.bf16.bf16.f32 "
        "{%0,%1,%2,%3}, {%4,%5,%6,%7}, {%8,%9}, {%0,%1,%2,%3};"
        : "+f"(c[0]), "+f"(c[1]), "+f"(c[2]), "+f"(c[3])
        : "r"(a[0]), "r"(a[1]), "r"(a[2]), "r"(a[3]), "r"(b[0]), "r"(b[1]));
}
__device__ __forceinline__ uint32 pkbf2(float a, float b) {
    return (uint32)__bfloat16_as_ushort(__float2bfloat16(a))
         | ((uint32)__bfloat16_as_ushort(__float2bfloat16(b)) << 16);
}
__device__ __forceinline__ float bfres(float v) {
    return v - __bfloat162float(__float2bfloat16(v));
}

__device__ float g_h1[(size_t)NB * 128 * 64 * 64];
__device__ float g_h2[(size_t)NB * 128 * 32 * 32];
__device__ float g_ze[(size_t)NB * 64 * 32 * 32];
__device__ float g_zq[(size_t)NB * 64 * 32 * 32];
__device__ float g_d1[(size_t)NB * 128 * 64 * 64];
__device__ float g_d2[(size_t)NB * 128 * 128 * 128];
__device__ float g_vq_part[256];
__device__ float g_rec_part[4096];
__device__ float g_w1t[16 * 3 * 128];
__device__ float g_w2t[16 * 128 * 128];
__device__ float g_w3t[9 * 128 * 64];
__device__ float g_w3dt[128 * 9 * 3];
__device__ __align__(16) __nv_bfloat16 g_bw1[4 * 2 * 128 * 256];  // [cl][h][co][K]
__device__ __align__(16) __nv_bfloat16 g_bw2[4 * 2 * 128 * 512];  // [cl][h][co][K]

__global__ void wprep_k(const float* __restrict__ w1, const float* __restrict__ w2,
                        const float* __restrict__ w3, const float* __restrict__ dw1,
                        const float* __restrict__ dw2, const float* __restrict__ dw3)
{
    int st = gridDim.x * blockDim.x, g = blockIdx.x * blockDim.x + threadIdx.x;
    for (int t = g; t < 16 * 3 * 128; t += st) {
        int co = t & 127, r = t >> 7, ci = r % 3, kk = r / 3;
        g_w1t[(kk * 3 + ci) * 128 + co] = w1[((size_t)co * 3 + ci) * 16 + kk];
    }
    for (int t = g; t < 16 * 128 * 128; t += st) {
        int co = t & 127, r = t >> 7, ci = r & 127, kk = r >> 7;
        g_w2t[(kk * 128 + ci) * 128 + co] = w2[((size_t)co * 128 + ci) * 16 + kk];
    }
    for (int t = g; t < 9 * 128 * 64; t += st) {
        int co = t & 63, r = t >> 6, ci = r & 127, kk = r >> 7;
        g_w3t[(kk * 128 + ci) * 64 + co] = w3[((size_t)co * 128 + ci) * 9 + kk];
    }
    for (int t = g; t < 128 * 9 * 3; t += st) {
        int co = t % 3, r = t / 3, kk = r % 9, ci = r / 9;
        g_w3dt[t] = dw3[((size_t)co * 128 + ci) * 9 + kk];
    }
    for (int t = g; t < 4 * 2 * 128 * 256; t += st) {
        int k = t & 255, r2 = t >> 8, co = r2 & 127, h = (r2 >> 7) & 1, cl = r2 >> 8;
        int ci = k >> 2, rr = (k >> 1) & 1, cc = k & 1;
        int dh = cl >> 1, dw = cl & 1;
        float w = dw1[((size_t)ci * 128 + co) * 16 + (1 - dh + 2 * rr) * 4 + (1 - dw + 2 * cc)];
        g_bw1[t] = __float2bfloat16(h ? bfres(w) : w);
    }
    for (int t = g; t < 4 * 2 * 128 * 512; t += st) {
        int k = t & 511, r2 = t >> 9, co = r2 & 127, h = (r2 >> 7) & 1, cl = r2 >> 8;
        int ci = k >> 2, rr = (k >> 1) & 1, cc = k & 1;
        int dh = cl >> 1, dw = cl & 1;
        float w = dw2[((size_t)ci * 128 + co) * 16 + (1 - dh + 2 * rr) * 4 + (1 - dw + 2 * cc)];
        g_bw2[t] = __float2bfloat16(h ? bfres(w) : w);
    }
}

// enc1: bit-exact scalar chain; all weights resident, single sync (R13).
template <int K, int S, int CIN, int COUT, int H, bool RELU>
__global__ void __launch_bounds__(512) conv_seq(const float* __restrict__ in,
                                                const float* __restrict__ wt,
                                                const float* __restrict__ bias,
                                                float* __restrict__ out)
{
    constexpr int W = H, OH = (H + 2 - K) / S + 1, OW = OH;
    constexpr int IHS = 7 * S + K, IWS = 7 * S + K, IWP = IWS + 1;
    constexpr int SW_OFF = ((CIN * IHS * IWP + 3) / 4) * 4;
    constexpr int WN = K * K * CIN * 64;
    extern __shared__ float sm[];
    float* s_in = sm;
    float* s_w  = sm + SW_OFF;
    const int n = blockIdx.z, co0 = blockIdx.y * 64;
    constexpr int TWn = OW / 8;
    const int oh0 = (blockIdx.x / TWn) * 8, ow0 = (blockIdx.x % TWn) * 8;
    const int tid = threadIdx.x, px = tid & 63, cog = tid >> 6;
    const int ohr = px >> 3, owr = px & 7;
    const int ihb = oh0 * S - 1, iwb = ow0 * S - 1;

    for (int t = tid; t < CIN * IHS * IWS; t += 512) {
        int ci = t / (IHS * IWS), r = t % (IHS * IWS), rr = r / IWS, cc = r % IWS;
        int ih = ihb + rr, iw = iwb + cc;
        float v = 0.f;
        if (ih >= 0 && ih < H && iw >= 0 && iw < W)
            v = in[(((size_t)n * CIN + ci) * H + ih) * W + iw];
        s_in[(ci * IHS + rr) * IWP + cc] = v;
    }
    for (int t = tid; t < WN; t += 512)
        s_w[t] = wt[(size_t)(t >> 6) * COUT + co0 + (t & 63)];
    __syncthreads();

    const int cob = co0 + cog * 8;
    float a[8];
    #pragma unroll
    for (int i = 0; i < 8; i++) a[i] = 0.f;
    #pragma unroll
    for (int kh = 0; kh < K; kh++)
    #pragma unroll
    for (int kw = 0; kw < K; kw++) {
        const float* ip = &s_in[(ohr * S + kh) * IWP + owr * S + kw];
        const float* wp = &s_w[((kh * K + kw) * CIN) * 64 + cog * 8];
        #pragma unroll 3
        for (int ci = 0; ci < CIN; ci++) {
            float iv = ip[ci * IHS * IWP];
            float4 w0 = *(const float4*)&wp[ci * 64];
            float4 w1 = *(const float4*)&wp[ci * 64 + 4];
            a[0] = __fmaf_rn(iv, w0.x, a[0]);
            a[1] = __fmaf_rn(iv, w0.y, a[1]);
            a[2] = __fmaf_rn(iv, w0.z, a[2]);
            a[3] = __fmaf_rn(iv, w0.w, a[3]);
            a[4] = __fmaf_rn(iv, w1.x, a[4]);
            a[5] = __fmaf_rn(iv, w1.y, a[5]);
            a[6] = __fmaf_rn(iv, w1.z, a[6]);
            a[7] = __fmaf_rn(iv, w1.w, a[7]);
        }
    }
    const int oh = oh0 + ohr, ow = ow0 + owr;
    #pragma unroll
    for (int c = 0; c < 8; c++) {
        float v = __fadd_rn(a[c], bias[cob + c]);
        if (RELU) v = fmaxf(v, 0.f);
        out[(((size_t)n * COUT + cob + c) * OH + oh) * OW + ow] = v;
    }
}

// enc2 (R16).
__global__ void __launch_bounds__(512) enc2_k(const float* __restrict__ in,
                                              const float* __restrict__ wt,
                                              const float* __restrict__ bias,
                                              float* __restrict__ out)
{
    extern __shared__ float sm[];
    float* s_in = sm;
    float* s_w  = sm + 128 * 18 * 19;
    const int n = blockIdx.z;
    const int oh0 = (blockIdx.x >> 2) * 8, ow0 = (blockIdx.x & 3) * 8;
    const int tid = threadIdx.x, px = tid & 31, cog = tid >> 5;
    const int ohr = px >> 2, owp = px & 3;
    const int ihb = oh0 * 2 - 1, iwb = ow0 * 2 - 1;

    for (int t = tid; t < 128 * 18 * 18; t += 512) {
        int ci = t / 324, r = t % 324, rr = r / 18, cc = r % 18;
        int ih = ihb + rr, iw = iwb + cc;
        float v = 0.f;
        if (ih >= 0 && ih < 64 && iw >= 0 && iw < 64)
            v = in[(((size_t)n * 128 + ci) * 64 + ih) * 64 + iw];
        s_in[(ci * 18 + rr) * 19 + cc] = v;
    }

    ull a[2][4];
    #pragma unroll
    for (int p = 0; p < 2; p++)
    #pragma unroll
    for (int j = 0; j < 4; j++) a[p][j] = 0ull;

    float4* sw4 = (float4*)s_w;
    #pragma unroll
    for (int kh = 0; kh < 4; kh++)
    #pragma unroll
    for (int kw = 0; kw < 4; kw++) {
        for (int ci0 = 0; ci0 < 128; ci0 += 64) {
            __syncthreads();
            const float4* wp4 =
                (const float4*)(wt + (size_t)((kh * 4 + kw) * 128 + ci0) * 128);
            for (int t = tid; t < 2048; t += 512) sw4[t] = wp4[t];
            __syncthreads();
            const float* ip = &s_in[((ci0 * 18) + ohr * 2 + kh) * 19 + owp * 4 + kw];
            const float* wp = &s_w[cog * 8];
            #pragma unroll 4
            for (int ci = 0; ci < 64; ci++) {
                float i0 = ip[ci * 342];
                float i1 = ip[ci * 342 + 2];
                ull p0 = pack2(i0), p1 = pack2(i1);
                ulonglong2 wA = *(const ulonglong2*)&wp[ci * 128];
                ulonglong2 wB = *(const ulonglong2*)&wp[ci * 128 + 4];
                a[0][0] = fma2(p0, wA.x, a[0][0]);
                a[0][1] = fma2(p0, wA.y, a[0][1]);
                a[0][2] = fma2(p0, wB.x, a[0][2]);
                a[0][3] = fma2(p0, wB.y, a[0][3]);
                a[1][0] = fma2(p1, wA.x, a[1][0]);
                a[1][1] = fma2(p1, wA.y, a[1][1]);
                a[1][2] = fma2(p1, wB.x, a[1][2]);
                a[1][3] = fma2(p1, wB.y, a[1][3]);
            }
        }
    }
    const int oh = oh0 + ohr;
    #pragma unroll
    for (int p = 0; p < 2; p++) {
        int ow = ow0 + owp * 2 + p;
        #pragma unroll
        for (int j = 0; j < 4; j++) {
            int co = cog * 8 + 2 * j;
            float lo, hi;
            unpack2(a[p][j], lo, hi);
            out[(((size_t)n * 128 + co) * 32 + oh) * 32 + ow] =
                fmaxf(__fadd_rn(lo, bias[co]), 0.f);
            out[(((size_t)n * 128 + co + 1) * 32 + oh) * 32 + ow] =
                fmaxf(__fadd_rn(hi, bias[co + 1]), 0.f);
        }
    }
}

// enc3 (R16).
__global__ void __launch_bounds__(256) enc3_k(const float* __restrict__ in,
                                              const float* __restrict__ wt,
                                              const float* __restrict__ bias,
                                              float* __restrict__ out)
{
    extern __shared__ float sm[];
    float* s_in = sm;
    float* s_w  = sm + 128 * 10 * 11;
    const int n = blockIdx.z;
    const int oh0 = (blockIdx.x >> 2) * 8, ow0 = (blockIdx.x & 3) * 8;
    const int tid = threadIdx.x, px = tid & 31, cog = tid >> 5;
    const int ohr = px >> 2, owp = px & 3;
    const int ihb = oh0 - 1, iwb = ow0 - 1;

    for (int t = tid; t < 128 * 10 * 10; t += 256) {
        int ci = t / 100, r = t % 100, rr = r / 10, cc = r % 10;
        int ih = ihb + rr, iw = iwb + cc;
        float v = 0.f;
        if (ih >= 0 && ih < 32 && iw >= 0 && iw < 32)
            v = in[(((size_t)n * 128 + ci) * 32 + ih) * 32 + iw];
        s_in[(ci * 10 + rr) * 11 + cc] = v;
    }

    ull a[2][4];
    #pragma unroll
    for (int p = 0; p < 2; p++)
    #pragma unroll
    for (int j = 0; j < 4; j++) a[p][j] = 0ull;

    float4* sw4 = (float4*)s_w;
    #pragma unroll
    for (int kh = 0; kh < 3; kh++)
    #pragma unroll
    for (int kw = 0; kw < 3; kw++) {
        __syncthreads();
        const float4* wp4 = (const float4*)(wt + (size_t)(kh * 3 + kw) * 8192);
        for (int t = tid; t < 2048; t += 256) sw4[t] = wp4[t];
        __syncthreads();
        const float* ip = &s_in[(ohr + kh) * 11 + owp * 2 + kw];
        const float* wp = &s_w[cog * 8];
        #pragma unroll 4
        for (int ci = 0; ci < 128; ci++) {
            float i0 = ip[ci * 110];
            float i1 = ip[ci * 110 + 1];
            ull p0 = pack2(i0), p1 = pack2(i1);
            ulonglong2 wA = *(const ulonglong2*)&wp[ci * 64];
            ulonglong2 wB = *(const ulonglong2*)&wp[ci * 64 + 4];
            a[0][0] = fma2(p0, wA.x, a[0][0]);
            a[0][1] = fma2(p0, wA.y, a[0][1]);
            a[0][2] = fma2(p0, wB.x, a[0][2]);
            a[0][3] = fma2(p0, wB.y, a[0][3]);
            a[1][0] = fma2(p1, wA.x, a[1][0]);
            a[1][1] = fma2(p1, wA.y, a[1][1]);
            a[1][2] = fma2(p1, wB.x, a[1][2]);
            a[1][3] = fma2(p1, wB.y, a[1][3]);
        }
    }
    const int oh = oh0 + ohr;
    #pragma unroll
    for (int p = 0; p < 2; p++) {
        int ow = ow0 + owp * 2 + p;
        #pragma unroll
        for (int j = 0; j < 4; j++) {
            int co = cog * 8 + 2 * j;
            float lo, hi;
            unpack2(a[p][j], lo, hi);
            out[(((size_t)n * 64 + co) * 32 + oh) * 32 + ow] = __fadd_rn(lo, bias[co]);
            out[(((size_t)n * 64 + co + 1) * 32 + oh) * 32 + ow] = __fadd_rn(hi, bias[co + 1]);
        }
    }
}

// VQ (R14: f32x2 dual-codeword chains, bit-exact).
__global__ void __launch_bounds__(256) vq_k(const float* __restrict__ ze,
                                            const float* __restrict__ cb,
                                            float* __restrict__ zq,
                                            float* __restrict__ part)
{
    extern __shared__ float sm[];
    float* s_cbp = sm;            // [256][64][2]
    float* s_cb2 = sm + 32768;    // [512]
    __shared__ float red[256];
    const int tid = threadIdx.x;
    for (int t = tid; t < 32768; t += 256) {
        int j = t & 1, d = (t >> 1) & 63, kp = t >> 7;
        s_cbp[t] = cb[(size_t)(2 * kp + j) * 64 + d];
    }
    __syncthreads();
    for (int k = tid; k < 512; k += 256) {
        const float* cp = &s_cbp[((k >> 1) * 64) * 2 + (k & 1)];
        float s = 0.f;
        for (int d = 0; d < 64; d++) {
            float c = cp[2 * d];
            s = __fadd_rn(s, __fmul_rn(c, c));
        }
        s_cb2[k] = s;
    }
    __syncthreads();

    const int v = blockIdx.x * 256 + tid;
    const int n = v >> 10, hw = v & 1023;
    const float* zp = ze + (size_t)n * 64 * 1024 + hw;
    float z[64];
    #pragma unroll
    for (int d = 0; d < 64; d++) z[d] = zp[(size_t)d * 1024];

    float z2 = 0.f;
    #pragma unroll
    for (int d = 0; d < 64; d++) z2 = __fadd_rn(z2, __fmul_rn(z[d], z[d]));

    float best = 3.4e38f;
    int bi = 0;
    for (int kp0 = 0; kp0 < 256; kp0 += 2) {
        ull dt01 = 0ull, dt23 = 0ull;
        const ull* p0 = (const ull*)&s_cbp[kp0 * 128];
        const ull* p1 = (const ull*)&s_cbp[(kp0 + 1) * 128];
        #pragma unroll
        for (int d = 0; d < 64; d += 2) {
            ulonglong2 ua = *(const ulonglong2*)&p0[d];
            ulonglong2 ub = *(const ulonglong2*)&p1[d];
            ull zd0 = pack2(z[d]), zd1 = pack2(z[d + 1]);
            dt01 = fma2(zd0, ua.x, dt01);
            dt01 = fma2(zd1, ua.y, dt01);
            dt23 = fma2(zd0, ub.x, dt23);
            dt23 = fma2(zd1, ub.y, dt23);
        }
        float dt0, dt1, dt2, dt3;
        unpack2(dt01, dt0, dt1);
        unpack2(dt23, dt2, dt3);
        const int k0 = 2 * kp0;
        float s0 = __fsub_rn(__fadd_rn(z2, s_cb2[k0 + 0]), __fmul_rn(2.f, dt0));
        float s1 = __fsub_rn(__fadd_rn(z2, s_cb2[k0 + 1]), __fmul_rn(2.f, dt1));
        float s2 = __fsub_rn(__fadd_rn(z2, s_cb2[k0 + 2]), __fmul_rn(2.f, dt2));
        float s3 = __fsub_rn(__fadd_rn(z2, s_cb2[k0 + 3]), __fmul_rn(2.f, dt3));
        if (s0 < best) { best = s0; bi = k0; }
        if (s1 < best) { best = s1; bi = k0 + 1; }
        if (s2 < best) { best = s2; bi = k0 + 2; }
        if (s3 < best) { best = s3; bi = k0 + 3; }
    }

    float* zqp = zq + (size_t)n * 64 * 1024 + hw;
    const float* cbi = &s_cbp[((bi >> 1) * 64) * 2 + (bi & 1)];
    float lsum = 0.f;
    #pragma unroll
    for (int d = 0; d < 64; d++) {
        float c = cbi[2 * d];
        float df = z[d] - c;
        lsum = fmaf(df, df, lsum);
        zqp[(size_t)d * 1024] = __fadd_rn(z[d], __fsub_rn(c, z[d]));
    }
    red[tid] = lsum;
    __syncthreads();
    for (int s = 128; s > 0; s >>= 1) {
        if (tid < s) red[tid] += red[tid + s];
        __syncthreads();
    }
    if (tid == 0) part[blockIdx.x] = red[0];
}

// Deconv via mma.sync bf16 (R15 class-folded) + paired x4 B loads.
template <int CIN, int IHW>
__global__ void __launch_bounds__(256) deconv_mma_k(
    const float* __restrict__ in, const __nv_bfloat16* __restrict__ gB,
    const float* __restrict__ bias, float* __restrict__ out)
{
    constexpr int K = CIN * 4;
    constexpr int NCH = K / 64;
    constexpr int OH = IHW * 2, OW = IHW * 2;
    constexpr int TX = IHW / 16;
    constexpr int PATCH_B = CIN * 180 * 4;
    constexpr int AH_B = PATCH_B, AL_B = AH_B + 18432;
    constexpr int BH_B = AL_B + 18432, BL_B = BH_B + 18432;

    extern __shared__ char smc[];
    float* s_patch = (float*)smc;
    const uint32 sb = smem_u32(smc);

    const int tid = threadIdx.x;
    const int lane = tid & 31, wrp = tid >> 5;
    const int mg = wrp & 3, ng = wrp >> 2;
    const int n = blockIdx.z;
    const int y0 = (blockIdx.x / TX) * 8, x0 = (blockIdx.x % TX) * 16;

    for (int t = tid; t < CIN * 180; t += 256) {
        int ci = t / 180, r = t % 180, rr = r / 18, cc = r % 18;
        int yy = y0 - 1 + rr, xx = x0 - 1 + cc;
        float v = 0.f;
        if (yy >= 0 && yy < IHW && xx >= 0 && xx < IHW)
            v = in[(((size_t)n * CIN + ci) * IHW + yy) * IHW + xx];
        s_patch[t] = v;
    }

    const int am = tid >> 1, aks = (tid & 1) * 32;
    const int a_yl = am >> 4, a_xl = am & 15;

    for (int cl = 0; cl < 4; cl++) {
        const int dh = cl >> 1, dw = cl & 1;
        const int a_pr0 = a_yl + dh + 1, a_pc0 = a_xl + dw + 1;

        float c[2][8][4];
        #pragma unroll
        for (int i = 0; i < 2; i++)
        #pragma unroll
        for (int j = 0; j < 8; j++)
        #pragma unroll
        for (int q = 0; q < 4; q++) c[i][j][q] = 0.f;

        for (int kc = 0; kc < NCH; kc++) {
            __syncthreads();
            {
                uint32* ah = (uint32*)(smc + AH_B);
                uint32* al = (uint32*)(smc + AL_B);
                const int kc16 = kc * 16;
                #pragma unroll
                for (int j2 = 0; j2 < 16; j2++) {
                    int k = aks + 2 * j2;
                    int ci = kc16 + (k >> 2);
                    int r = (k >> 1) & 1;
                    const float* pp = &s_patch[(ci * 10 + (a_pr0 - r)) * 18];
                    float v0 = pp[a_pc0];
                    float v1 = pp[a_pc0 - 1];
                    int idx = (am * 72 + k) >> 1;
                    ah[idx] = pkbf2(v0, v1);
                    al[idx] = pkbf2(bfres(v0), bfres(v1));
                }
            }
            {
                const __nv_bfloat16* bh = gB + ((size_t)(cl * 2 + 0) * 128) * K + kc * 64;
                const __nv_bfloat16* bl = gB + ((size_t)(cl * 2 + 1) * 128) * K + kc * 64;
                for (int e = tid; e < 1024; e += 256) {
                    int co = e >> 3, k8 = (e & 7) * 8;
                    uint4 vh = *(const uint4*)(bh + (size_t)co * K + k8);
                    uint4 vl = *(const uint4*)(bl + (size_t)co * K + k8);
                    *(uint4*)(smc + BH_B + (co * 72 + k8) * 2) = vh;
                    *(uint4*)(smc + BL_B + (co * 72 + k8) * 2) = vl;
                }
            }
            __syncthreads();

            #pragma unroll
            for (int k16i = 0; k16i < 4; k16i++) {
                const int k16 = k16i * 16;
                uint32 a_h[2][4], a_l[2][4];
                #pragma unroll
                for (int i = 0; i < 2; i++) {
                    int row = mg * 32 + i * 16 + (lane & 15);
                    uint32 off = (uint32)((row * 72 + k16 + ((lane >> 4) << 3)) * 2);
                    ldm_x4(a_h[i][0], a_h[i][1], a_h[i][2], a_h[i][3], sb + AH_B + off);
                    ldm_x4(a_l[i][0], a_l[i][1], a_l[i][2], a_l[i][3], sb + AL_B + off);
                }
                uint32 b_h[8][2], b_l[8][2];
                #pragma unroll
                for (int j = 0; j < 8; j += 2) {
                    int nrow = ng * 64 + j * 8 + ((lane >> 4) & 1) * 8 + (lane & 7);
                    uint32 off = (uint32)((nrow * 72 + k16 + (((lane >> 3) & 1) << 3)) * 2);
                    ldm_x4(b_h[j][0], b_h[j][1], b_h[j + 1][0], b_h[j + 1][1],
                           sb + BH_B + off);
                    ldm_x4(b_l[j][0], b_l[j][1], b_l[j + 1][0], b_l[j + 1][1],
                           sb + BL_B + off);
                }
                #pragma unroll
                for (int i = 0; i < 2; i++)
                #pragma unroll
                for (int j = 0; j < 8; j++) {
                    mma16816(c[i][j], a_h[i], b_h[j]);
                    mma16816(c[i][j], a_h[i], b_l[j]);
                    mma16816(c[i][j], a_l[i], b_h[j]);
                }
            }
        }

        #pragma unroll
        for (int i = 0; i < 2; i++) {
            int row0 = mg * 32 + i * 16 + (lane >> 2);
            #pragma unroll
            for (int rr = 0; rr < 2; rr++) {
                int row = row0 + rr * 8;
                int y_l = row >> 4, x_l = row & 15;
                int oh = 2 * (y0 + y_l) + dh, ow = 2 * (x0 + x_l) + dw;
                size_t ob = ((size_t)n * 128) * OH * OW + (size_t)oh * OW + ow;
                #pragma unroll
                for (int j = 0; j < 8; j++) {
                    int col = ng * 64 + j * 8 + (lane & 3) * 2;
                    float v0 = c[i][j][rr * 2 + 0] + bias[col];
                    float v1 = c[i][j][rr * 2 + 1] + bias[col + 1];
                    out[ob + (size_t)col * OH * OW] = fmaxf(v0, 0.f);
                    out[ob + (size_t)(col + 1) * OH * OW] = fmaxf(v1, 0.f);
                }
            }
        }
    }
}

// dec3: 8-row tiles, 512 threads, 2 rows/thread (R16).
__global__ void __launch_bounds__(512) dec3_k(const float* __restrict__ in,
                                              const float* __restrict__ wtt,
                                              const float* __restrict__ bias,
                                              const float* __restrict__ x,
                                              float* __restrict__ out,
                                              float* __restrict__ rec_part)
{
    extern __shared__ float sm[];
    float* s_in = sm;
    float* s_w  = sm + 16 * 10 * 130;
    __shared__ float red[512];
    const int n = blockIdx.y, oh0 = blockIdx.x * 8;
    const int tid = threadIdx.x, rg = tid >> 7, col = tid & 127;

    for (int t = tid; t < 128 * 9 * 3; t += 512)
        s_w[(t / 3) * 4 + t % 3] = wtt[t];

    float a[2][3];
    #pragma unroll
    for (int p = 0; p < 2; p++)
    #pragma unroll
    for (int co = 0; co < 3; co++) a[p][co] = 0.f;

    for (int ci0 = 0; ci0 < 128; ci0 += 16) {
        for (int t = tid; t < 16 * 10 * 130; t += 512) {
            int cil = t / 1300, r2 = t % 1300, rr = r2 / 130, cc = r2 % 130;
            int ih = oh0 - 1 + rr, iw = cc - 1;
            float v = 0.f;
            if (ih >= 0 && ih < 128 && iw >= 0 && iw < 128)
                v = in[(((size_t)n * 128 + ci0 + cil) * 128 + ih) * 128 + iw];
            s_in[t] = v;
        }
        __syncthreads();
        for (int cil = 0; cil < 16; cil++) {
            float riv[4][3];
            const float* bp = &s_in[(cil * 10 + 2 * rg) * 130 + col];
            #pragma unroll
            for (int dr = 0; dr < 4; dr++)
            #pragma unroll
            for (int kw = 0; kw < 3; kw++) riv[dr][kw] = bp[dr * 130 + kw];
            #pragma unroll
            for (int kh = 0; kh < 3; kh++) {
                #pragma unroll
                for (int kw = 0; kw < 3; kw++) {
                    float4 wv = *(const float4*)&s_w[((ci0 + cil) * 9 + kh * 3 + kw) * 4];
                    float iv0 = riv[kh][kw];
                    float iv1 = riv[kh + 1][kw];
                    a[0][0] = fmaf(wv.x, iv0, a[0][0]);
                    a[0][1] = fmaf(wv.y, iv0, a[0][1]);
                    a[0][2] = fmaf(wv.z, iv0, a[0][2]);
                    a[1][0] = fmaf(wv.x, iv1, a[1][0]);
                    a[1][1] = fmaf(wv.y, iv1, a[1][1]);
                    a[1][2] = fmaf(wv.z, iv1, a[1][2]);
                }
            }
        }
        __syncthreads();
    }
    float lsum = 0.f;
    #pragma unroll
    for (int p = 0; p < 2; p++) {
        int oh = oh0 + 2 * rg + p;
        #pragma unroll
        for (int co = 0; co < 3; co++) {
            float v = a[p][co] + bias[co];
            size_t idx = (((size_t)n * 3 + co) * 128 + oh) * 128 + col;
            out[idx] = v;
            float d = v - x[idx];
            lsum = fmaf(d, d, lsum);
        }
    }
    red[tid] = lsum;
    __syncthreads();
    for (int s = 256; s > 0; s >>= 1) {
        if (tid < s) red[tid] += red[tid + s];
        __syncthreads();
    }
    if (tid == 0) rec_part[(size_t)n * 16 + blockIdx.x] = red[0];
}

__global__ void __launch_bounds__(256) finalize_k(const float* __restrict__ rec_part,
                                                  const float* __restrict__ vq_part,
                                                  float* __restrict__ out)
{
    __shared__ double rA[256], rB[256];
    const int tid = threadIdx.x;
    double s = 0.0;
    for (int t = tid; t < 1024; t += 256) s += (double)rec_part[t];
    rA[tid] = s;
    rB[tid] = (double)vq_part[tid];
    __syncthreads();
    for (int st = 128; st > 0; st >>= 1) {
        if (tid < st) { rA[tid] += rA[tid + st]; rB[tid] += rB[tid + st]; }
        __syncthreads();
    }
    if (tid == 0) {
        double recon = rA[0] / 3145728.0;
        double vq    = 1.25 * rB[0] / 4194304.0;
        out[3145728] = (float)(recon + vq);
        out[3145729] = (float)recon;
        out[3145730] = (float)vq;
    }
}

extern "C" void kernel_launch(void* const* d_in, const int* in_sizes, int n_in,
                              void* d_out, int out_size)
{
    (void)in_sizes; (void)n_in; (void)out_size;
    const float* x   = (const float*)d_in[0];
    const float* ew1 = (const float*)d_in[1];
    const float* eb1 = (const float*)d_in[2];
    const float* ew2 = (const float*)d_in[3];
    const float* eb2 = (const float*)d_in[4];
    const float* ew3 = (const float*)d_in[5];
    const float* eb3 = (const float*)d_in[6];
    const float* cb  = (const float*)d_in[7];
    const float* dw1 = (const float*)d_in[8];
    const float* db1 = (const float*)d_in[9];
    const float* dw2 = (const float*)d_in[10];
    const float* db2 = (const float*)d_in[11];
    const float* dw3 = (const float*)d_in[12];
    const float* db3 = (const float*)d_in[13];
    float* out = (float*)d_out;

    void *h1, *h2, *ze, *zq, *dd1, *dd2, *vqp, *recp;
    void *w1t, *w2t, *w3t, *w3dt, *bw1, *bw2;
    cudaGetSymbolAddress(&h1,  g_h1);
    cudaGetSymbolAddress(&h2,  g_h2);
    cudaGetSymbolAddress(&ze,  g_ze);
    cudaGetSymbolAddress(&zq,  g_zq);
    cudaGetSymbolAddress(&dd1, g_d1);
    cudaGetSymbolAddress(&dd2, g_d2);
    cudaGetSymbolAddress(&vqp,  g_vq_part);
    cudaGetSymbolAddress(&recp, g_rec_part);
    cudaGetSymbolAddress(&w1t,  g_w1t);
    cudaGetSymbolAddress(&w2t,  g_w2t);
    cudaGetSymbolAddress(&w3t,  g_w3t);
    cudaGetSymbolAddress(&w3dt, g_w3dt);
    cudaGetSymbolAddress(&bw1,  g_bw1);
    cudaGetSymbolAddress(&bw2,  g_bw2);

    const int SM_E1 = (1028 + 16 * 3 * 64) * 4;
    const int SM_E2 = (128 * 18 * 19 + 64 * 128) * 4;
    const int SM_E3 = (128 * 10 * 11 + 128 * 64) * 4;
    const int SM_M1 = 64 * 180 * 4 + 4 * 18432;
    const int SM_M2 = 128 * 180 * 4 + 4 * 18432;
    const int SM_D3 = (16 * 10 * 130 + 128 * 9 * 4) * 4;
    const int SM_VQ = (32768 + 512) * 4;

    cudaFuncSetAttribute((const void*)enc2_k,
                         cudaFuncAttributeMaxDynamicSharedMemorySize, SM_E2);
    cudaFuncSetAttribute((const void*)enc3_k,
                         cudaFuncAttributeMaxDynamicSharedMemorySize, SM_E3);
    cudaFuncSetAttribute((const void*)deconv_mma_k<64,32>,
                         cudaFuncAttributeMaxDynamicSharedMemorySize, SM_M1);
    cudaFuncSetAttribute((const void*)deconv_mma_k<128,64>,
                         cudaFuncAttributeMaxDynamicSharedMemorySize, SM_M2);
    cudaFuncSetAttribute((const void*)vq_k,
                         cudaFuncAttributeMaxDynamicSharedMemorySize, SM_VQ);
    cudaFuncSetAttribute((const void*)dec3_k,
                         cudaFuncAttributeMaxDynamicSharedMemorySize, SM_D3);

    wprep_k<<<256, 256>>>(ew1, ew2, ew3, dw1, dw2, dw3);
    conv_seq<4,2,3,128,128,true><<<dim3(64, 2, NB), 512, SM_E1>>>(
        x, (const float*)w1t, eb1, (float*)h1);
    enc2_k<<<dim3(16, 1, NB), 512, SM_E2>>>(
        (const float*)h1, (const float*)w2t, eb2, (float*)h2);
    enc3_k<<<dim3(16, 1, NB), 256, SM_E3>>>(
        (const float*)h2, (const float*)w3t, eb3, (float*)ze);
    vq_k<<<256, 256, SM_VQ>>>(
        (const float*)ze, cb, (float*)zq, (float*)vqp);
    deconv_mma_k<64,32><<<dim3(8, 1, NB), 256, SM_M1>>>(
        (const float*)zq, (const __nv_bfloat16*)bw1, db1, (float*)dd1);
    deconv_mma_k<128,64><<<dim3(32, 1, NB), 256, SM_M2>>>(
        (const float*)dd1, (const __nv_bfloat16*)bw2, db2, (float*)dd2);
    dec3_k<<<dim3(16, NB), 512, SM_D3>>>(
        (const float*)dd2, (const float*)w3dt, db3, x, out, (float*)recp);
    finalize_k<<<1, 256>>>(
        (const float*)recp, (const float*)vqp, out);
}